// round 2
// baseline (speedup 1.0000x reference)
#include <cuda_runtime.h>
#include <math.h>

// ---------------- problem constants ----------------
#define TT 1024     // tokens
#define EE 1024     // embed dim
#define VV 32000    // vocab
#define NH 16       // query heads
#define NKV 4       // kv heads
#define DHD 64      // head dim
#define KVD (NKV*DHD)   // 256
#define LNUM 2
#define RNUM 2
#define FF 4096
#define EPSV 1e-5f

// ---------------- device scratch (no allocations allowed) ----------------
__device__ float g_x[TT*EE];
__device__ float g_h[TT*EE];
__device__ float g_q[TT*EE];
__device__ float g_k[TT*KVD];
__device__ float g_v[TT*KVD];
__device__ float g_att[(size_t)NH*TT*TT];
__device__ float g_y[TT*EE];
__device__ float g_ff[TT*FF];
__device__ float g_logits[(size_t)TT*VV];
__device__ float g_loss;

// ---------------- helpers ----------------
__device__ __forceinline__ float blk_sum256(float v, float* sh) {
    int tid = threadIdx.x;
    sh[tid] = v; __syncthreads();
    #pragma unroll
    for (int s = 128; s > 0; s >>= 1) {
        if (tid < s) sh[tid] += sh[tid + s];
        __syncthreads();
    }
    float r = sh[0]; __syncthreads();
    return r;
}
__device__ __forceinline__ float blk_max256(float v, float* sh) {
    int tid = threadIdx.x;
    sh[tid] = v; __syncthreads();
    #pragma unroll
    for (int s = 128; s > 0; s >>= 1) {
        if (tid < s) sh[tid] = fmaxf(sh[tid], sh[tid + s]);
        __syncthreads();
    }
    float r = sh[0]; __syncthreads();
    return r;
}
__device__ __forceinline__ float gelu_exact(float x) {
    return 0.5f * x * (1.0f + erff(x * 0.7071067811865476f));
}

// ---------------- embedding gather ----------------
__global__ void gather_embed_k(const float* __restrict__ embed, const int* __restrict__ idx) {
    int i = blockIdx.x * blockDim.x + threadIdx.x;   // grid covers TT*EE
    int t = i >> 10;
    int e = i & 1023;
    g_x[i] = embed[(size_t)idx[t] * EE + e];
}

// ---------------- layernorm: one block per row ----------------
__global__ void layernorm_k(const float* __restrict__ in, float* __restrict__ out,
                            const float* __restrict__ g, const float* __restrict__ b) {
    __shared__ float sh[256];
    int row = blockIdx.x;
    const float* x = in + (size_t)row * EE;
    float s = 0.f;
    for (int i = threadIdx.x; i < EE; i += 256) s += x[i];
    float mu = blk_sum256(s, sh) * (1.0f / EE);
    float vs = 0.f;
    for (int i = threadIdx.x; i < EE; i += 256) { float d = x[i] - mu; vs += d * d; }
    float var = blk_sum256(vs, sh) * (1.0f / EE);
    float inv = rsqrtf(var + EPSV);
    float* o = out + (size_t)row * EE;
    for (int i = threadIdx.x; i < EE; i += 256)
        o[i] = (x[i] - mu) * inv * g[i] + b[i];
}

// ---------------- 128x128x8 SGEMM (fp32), MODE: 0=store 1=+resid 2=gelu ----------------
// TRANSB=false: B is [K,N] row-major. TRANSB=true: B is [N,K] row-major (C = A * B^T).
// All M,N divisible by 128, K by 8 in this problem.
template<int MODE, bool TRANSB>
__global__ __launch_bounds__(256) void sgemm_k(const float* __restrict__ A,
                                               const float* __restrict__ Bm,
                                               float* __restrict__ C,
                                               const float* __restrict__ Rs,
                                               int M, int N, int K) {
    __shared__ __align__(16) float As[8][132];
    __shared__ __align__(16) float Bs[8][132];
    const int tid = threadIdx.x;
    const int tx = tid & 15;
    const int ty = tid >> 4;
    const int bx = blockIdx.x, by = blockIdx.y;
    const int row0 = by * 128, col0 = bx * 128;

    float acc[8][8];
    #pragma unroll
    for (int i = 0; i < 8; i++)
        #pragma unroll
        for (int j = 0; j < 8; j++) acc[i][j] = 0.f;

    const int ar = tid >> 1;          // 0..127
    const int ak = (tid & 1) * 4;     // 0 or 4
    const int br = tid >> 5;          // 0..7
    const int bc = (tid & 31) * 4;    // 0..124

    for (int k0 = 0; k0 < K; k0 += 8) {
        float4 av = *(const float4*)(A + (size_t)(row0 + ar) * K + k0 + ak);
        As[ak + 0][ar] = av.x; As[ak + 1][ar] = av.y;
        As[ak + 2][ar] = av.z; As[ak + 3][ar] = av.w;
        if (!TRANSB) {
            float4 bv = *(const float4*)(Bm + (size_t)(k0 + br) * N + col0 + bc);
            *(float4*)&Bs[br][bc] = bv;
        } else {
            float4 bv = *(const float4*)(Bm + (size_t)(col0 + ar) * K + k0 + ak);
            Bs[ak + 0][ar] = bv.x; Bs[ak + 1][ar] = bv.y;
            Bs[ak + 2][ar] = bv.z; Bs[ak + 3][ar] = bv.w;
        }
        __syncthreads();
        #pragma unroll
        for (int kk = 0; kk < 8; kk++) {
            float a[8], b[8];
            *(float4*)&a[0] = *(float4*)&As[kk][ty * 4];
            *(float4*)&a[4] = *(float4*)&As[kk][64 + ty * 4];
            *(float4*)&b[0] = *(float4*)&Bs[kk][tx * 4];
            *(float4*)&b[4] = *(float4*)&Bs[kk][64 + tx * 4];
            #pragma unroll
            for (int i = 0; i < 8; i++)
                #pragma unroll
                for (int j = 0; j < 8; j++)
                    acc[i][j] += a[i] * b[j];
        }
        __syncthreads();
    }

    #pragma unroll
    for (int ig = 0; ig < 2; ig++) {
        #pragma unroll
        for (int i = 0; i < 4; i++) {
            int r = row0 + ig * 64 + ty * 4 + i;
            #pragma unroll
            for (int jg = 0; jg < 2; jg++) {
                int c = col0 + jg * 64 + tx * 4;
                float4 o;
                o.x = acc[ig * 4 + i][jg * 4 + 0];
                o.y = acc[ig * 4 + i][jg * 4 + 1];
                o.z = acc[ig * 4 + i][jg * 4 + 2];
                o.w = acc[ig * 4 + i][jg * 4 + 3];
                if (MODE == 1) {
                    float4 rv = *(const float4*)(Rs + (size_t)r * N + c);
                    o.x += rv.x; o.y += rv.y; o.z += rv.z; o.w += rv.w;
                } else if (MODE == 2) {
                    o.x = gelu_exact(o.x); o.y = gelu_exact(o.y);
                    o.z = gelu_exact(o.z); o.w = gelu_exact(o.w);
                }
                *(float4*)(C + (size_t)r * N + c) = o;
            }
        }
    }
}

// ---------------- RoPE (in-place, first 32 dims of each head) ----------------
__global__ void rope_k(float* __restrict__ buf, int nheads) {
    int i = blockIdx.x * blockDim.x + threadIdx.x;   // TT * nheads * 16
    int total = TT * nheads * 16;
    if (i >= total) return;
    int j = i & 15;
    int head = (i >> 4) % nheads;
    int t = i / (16 * nheads);
    float theta = powf(10000.0f, -(float)(2 * j) / 32.0f);
    float ang = (float)t * theta;
    float c = cosf(ang), s = sinf(ang);
    float* base = buf + (size_t)t * nheads * DHD + head * DHD;
    float x1 = base[j], x2 = base[j + 16];
    base[j]      = x1 * c - x2 * s;
    base[j + 16] = x2 * c + x1 * s;
}

// ---------------- attention scores: 64x64 tile per block, causal block-skip ----------------
__global__ __launch_bounds__(256) void attn_scores_k() {
    int st = blockIdx.x, tt = blockIdx.y, h = blockIdx.z;
    if (st > tt) return;   // entire tile above diagonal
    int kh = h >> 2;
    __shared__ float Qs[64][65];
    __shared__ float Ks[64][65];
    int tid = threadIdx.x;
    #pragma unroll
    for (int i = 0; i < 16; i++) {
        int idx = tid + i * 256;
        int r = idx >> 6, c = idx & 63;
        Qs[r][c] = g_q[(size_t)(tt * 64 + r) * EE + h * 64 + c];
        Ks[r][c] = g_k[(size_t)(st * 64 + r) * KVD + kh * 64 + c];
    }
    __syncthreads();
    int tx = tid & 15, ty = tid >> 4;
    float acc[4][4] = {};
    #pragma unroll 8
    for (int d = 0; d < 64; d++) {
        float a[4], b[4];
        #pragma unroll
        for (int i = 0; i < 4; i++) a[i] = Qs[ty * 4 + i][d];
        #pragma unroll
        for (int j = 0; j < 4; j++) b[j] = Ks[tx * 4 + j][d];
        #pragma unroll
        for (int i = 0; i < 4; i++)
            #pragma unroll
            for (int j = 0; j < 4; j++)
                acc[i][j] += a[i] * b[j];
    }
    #pragma unroll
    for (int i = 0; i < 4; i++)
        #pragma unroll
        for (int j = 0; j < 4; j++)
            g_att[(size_t)h * TT * TT + (size_t)(tt * 64 + ty * 4 + i) * TT + st * 64 + tx * 4 + j]
                = acc[i][j] * 0.125f;
}

// ---------------- row softmax + sigmoid-threshold gate, zero-fill s>t ----------------
__global__ void softmax_thresh_k(const float* __restrict__ gate_all, int l) {
    __shared__ float sh[256];
    int h = blockIdx.x >> 10;
    int t = blockIdx.x & 1023;
    float* p = g_att + (size_t)h * TT * TT + (size_t)t * TT;
    float thr = 1.0f / (1.0f + expf(-gate_all[l * NH + h]));
    float m = -1e30f;
    for (int i = threadIdx.x; i <= t; i += 256) m = fmaxf(m, p[i]);
    m = blk_max256(m, sh);
    float s = 0.f;
    for (int i = threadIdx.x; i <= t; i += 256) s += expf(p[i] - m);
    s = blk_sum256(s, sh);
    float inv = 1.0f / s;
    for (int i = threadIdx.x; i < TT; i += 256) {
        float o = 0.f;
        if (i <= t) {
            float pv = expf(p[i] - m) * inv;
            o = (pv >= thr) ? pv : 0.f;
        }
        p[i] = o;
    }
}

// ---------------- y = att @ v (per head), K clipped at causal boundary ----------------
__global__ __launch_bounds__(256) void attn_av_k() {
    int tt = blockIdx.x, h = blockIdx.y;
    int kh = h >> 2;
    __shared__ float As[16][65];
    __shared__ float Vs[16][64];
    int tid = threadIdx.x;
    int tx = tid & 15, ty = tid >> 4;
    float acc[4][4] = {};
    int kmax = (tt + 1) * 64;
    const float* abase = g_att + (size_t)h * TT * TT;
    for (int k0 = 0; k0 < kmax; k0 += 16) {
        #pragma unroll
        for (int i = 0; i < 4; i++) {
            int idx = tid + i * 256;
            int r = idx >> 4, c = idx & 15;
            As[c][r] = abase[(size_t)(tt * 64 + r) * TT + k0 + c];
        }
        #pragma unroll
        for (int i = 0; i < 4; i++) {
            int idx = tid + i * 256;
            int r = idx >> 6, c = idx & 63;
            Vs[r][c] = g_v[(size_t)(k0 + r) * KVD + kh * 64 + c];
        }
        __syncthreads();
        #pragma unroll
        for (int kk = 0; kk < 16; kk++) {
            float a[4], b[4];
            #pragma unroll
            for (int i = 0; i < 4; i++) a[i] = As[kk][ty * 4 + i];
            #pragma unroll
            for (int j = 0; j < 4; j++) b[j] = Vs[kk][tx * 4 + j];
            #pragma unroll
            for (int i = 0; i < 4; i++)
                #pragma unroll
                for (int j = 0; j < 4; j++)
                    acc[i][j] += a[i] * b[j];
        }
        __syncthreads();
    }
    #pragma unroll
    for (int i = 0; i < 4; i++)
        #pragma unroll
        for (int j = 0; j < 4; j++)
            g_y[(size_t)(tt * 64 + ty * 4 + i) * EE + h * 64 + tx * 4 + j] = acc[i][j];
}

// ---------------- loss ----------------
__global__ void zero_loss_k() { g_loss = 0.f; }

__global__ void loss_rows_k(const float* __restrict__ logits, const int* __restrict__ targets) {
    __shared__ float sh[256];
    int t = blockIdx.x;
    const float* row = logits + (size_t)t * VV;
    float m = -1e30f;
    for (int i = threadIdx.x; i < VV; i += 256) m = fmaxf(m, row[i]);
    m = blk_max256(m, sh);
    float s = 0.f;
    for (int i = threadIdx.x; i < VV; i += 256) s += expf(row[i] - m);
    s = blk_sum256(s, sh);
    if (threadIdx.x == 0) {
        float lp = row[targets[t]] - m - logf(s);
        atomicAdd(&g_loss, -lp);
    }
}

__global__ void loss_fin_k(float* dst) { *dst = g_loss * (1.0f / (float)TT); }

// ---------------- host orchestration ----------------
extern "C" void kernel_launch(void* const* d_in, const int* in_sizes, int n_in,
                              void* d_out, int out_size) {
    const float* embed = (const float*)d_in[0];
    const float* ln1_g = (const float*)d_in[1];
    const float* ln1_b = (const float*)d_in[2];
    const float* Wq    = (const float*)d_in[3];
    const float* Wk    = (const float*)d_in[4];
    const float* Wv    = (const float*)d_in[5];
    const float* Wo    = (const float*)d_in[6];
    const float* gate  = (const float*)d_in[7];
    const float* ln2_g = (const float*)d_in[8];
    const float* ln2_b = (const float*)d_in[9];
    const float* W1    = (const float*)d_in[10];
    const float* W2    = (const float*)d_in[11];
    const float* lnf_g = (const float*)d_in[12];
    const float* lnf_b = (const float*)d_in[13];
    const int*   idx   = (const int*)d_in[14];
    const int*   tgt   = (const int*)d_in[15];

    float *xp, *hp, *qp, *kp, *vp, *yp, *ffp, *logp, *lossp;
    cudaGetSymbolAddress((void**)&xp,   g_x);
    cudaGetSymbolAddress((void**)&hp,   g_h);
    cudaGetSymbolAddress((void**)&qp,   g_q);
    cudaGetSymbolAddress((void**)&kp,   g_k);
    cudaGetSymbolAddress((void**)&vp,   g_v);
    cudaGetSymbolAddress((void**)&yp,   g_y);
    cudaGetSymbolAddress((void**)&ffp,  g_ff);
    cudaGetSymbolAddress((void**)&logp, g_logits);
    cudaGetSymbolAddress((void**)&lossp, g_loss);

    const size_t BTV = (size_t)TT * VV;
    float* logits_dst = (out_size >= (int)BTV || (size_t)out_size >= BTV) ? (float*)d_out : logp;
    float* loss_dst = nullptr;
    if ((size_t)out_size > BTV)      loss_dst = (float*)d_out + BTV;
    else if ((size_t)out_size < BTV) loss_dst = (float*)d_out;   // loss-only output

    // embedding gather
    gather_embed_k<<<(TT * EE) / 256, 256>>>(embed, idx);

    for (int r = 0; r < RNUM; r++) {
        for (int l = 0; l < LNUM; l++) {
            const float* wq = Wq + (size_t)l * EE * EE;
            const float* wk = Wk + (size_t)l * EE * KVD;
            const float* wv = Wv + (size_t)l * EE * KVD;
            const float* wo = Wo + (size_t)l * EE * EE;
            const float* w1 = W1 + (size_t)l * EE * FF;
            const float* w2 = W2 + (size_t)l * FF * EE;

            // h = LN1(x)
            layernorm_k<<<TT, 256>>>(xp, hp, ln1_g + l * EE, ln1_b + l * EE);
            // q/k/v projections
            sgemm_k<0, false><<<dim3(EE / 128, TT / 128), 256>>>(hp, wq, qp, nullptr, TT, EE, EE);
            sgemm_k<0, false><<<dim3(KVD / 128, TT / 128), 256>>>(hp, wk, kp, nullptr, TT, KVD, EE);
            sgemm_k<0, false><<<dim3(KVD / 128, TT / 128), 256>>>(hp, wv, vp, nullptr, TT, KVD, EE);
            // RoPE
            rope_k<<<(TT * NH * 16) / 256, 256>>>(qp, NH);
            rope_k<<<(TT * NKV * 16) / 256, 256>>>(kp, NKV);
            // attention
            attn_scores_k<<<dim3(TT / 64, TT / 64, NH), 256>>>();
            softmax_thresh_k<<<NH * TT, 256>>>(gate, l);
            attn_av_k<<<dim3(TT / 64, NH), 256>>>();
            // x += y @ Wo
            sgemm_k<1, false><<<dim3(EE / 128, TT / 128), 256>>>(yp, wo, xp, xp, TT, EE, EE);
            // FFN
            layernorm_k<<<TT, 256>>>(xp, hp, ln2_g + l * EE, ln2_b + l * EE);
            sgemm_k<2, false><<<dim3(FF / 128, TT / 128), 256>>>(hp, w1, ffp, nullptr, TT, FF, EE);
            sgemm_k<1, false><<<dim3(EE / 128, TT / 128), 256>>>(ffp, w2, xp, xp, TT, EE, FF);
        }
    }

    // final LN + logits = h @ embed^T
    layernorm_k<<<TT, 256>>>(xp, hp, lnf_g, lnf_b);
    sgemm_k<0, true><<<dim3(VV / 128, TT / 128), 256>>>(hp, embed, logits_dst, nullptr, TT, VV, EE);

    // loss
    zero_loss_k<<<1, 1>>>();
    loss_rows_k<<<TT, 256>>>(logits_dst, tgt);
    if (loss_dst) loss_fin_k<<<1, 1>>>(loss_dst);
}

// round 3
// speedup vs baseline: 2.4554x; 2.4554x over previous
#include <cuda_runtime.h>
#include <cuda_bf16.h>
#include <math.h>
#include <stdint.h>

// ---------------- problem constants ----------------
#define TT 1024
#define EE 1024
#define VV 32000
#define NH 16
#define NKV 4
#define DHD 64
#define KVD (NKV*DHD)     // 256
#define QKVN 1536         // E + 2*KVD
#define LNUM 2
#define RNUM 2
#define FF 4096
#define EPSV 1e-5f

typedef __nv_bfloat16 bf16;

// ---------------- device scratch ----------------
__device__ float g_x[TT*EE];
__device__ bf16  g_hh[TT*EE], g_hl[TT*EE];
__device__ float g_qkv[TT*QKVN];
__device__ float g_att[(size_t)NH*TT*TT];
__device__ bf16  g_yh[TT*EE], g_yl[TT*EE];
__device__ bf16  g_ffh[TT*FF], g_ffl[TT*FF];
__device__ bf16  g_wqkv_h[LNUM*QKVN*EE], g_wqkv_l[LNUM*QKVN*EE];   // [N=1536][K=1024]
__device__ bf16  g_wo_h[LNUM*EE*EE],     g_wo_l[LNUM*EE*EE];       // [1024][1024]
__device__ bf16  g_w1_h[LNUM*FF*EE],     g_w1_l[LNUM*FF*EE];       // [4096][1024]
__device__ bf16  g_w2_h[LNUM*EE*FF],     g_w2_l[LNUM*EE*FF];       // [1024][4096]
__device__ bf16  g_eh[(size_t)VV*EE],    g_el[(size_t)VV*EE];      // [32000][1024]
__device__ float g_logits[(size_t)TT*VV];
__device__ float g_loss;

// ---------------- helpers ----------------
__device__ __forceinline__ float blk_sum256(float v, float* sh) {
    int tid = threadIdx.x;
    sh[tid] = v; __syncthreads();
    #pragma unroll
    for (int s = 128; s > 0; s >>= 1) { if (tid < s) sh[tid] += sh[tid + s]; __syncthreads(); }
    float r = sh[0]; __syncthreads();
    return r;
}
__device__ __forceinline__ float blk_max256(float v, float* sh) {
    int tid = threadIdx.x;
    sh[tid] = v; __syncthreads();
    #pragma unroll
    for (int s = 128; s > 0; s >>= 1) { if (tid < s) sh[tid] = fmaxf(sh[tid], sh[tid + s]); __syncthreads(); }
    float r = sh[0]; __syncthreads();
    return r;
}
__device__ __forceinline__ float gelu_exact(float x) {
    return 0.5f * x * (1.0f + erff(x * 0.7071067811865476f));
}
__device__ __forceinline__ void split_bf16(float v, bf16& h, bf16& l) {
    h = __float2bfloat16(v);
    l = __float2bfloat16(v - __bfloat162float(h));
}

// ---------------- PTX wrappers ----------------
__device__ __forceinline__ void mma_bf16(float* d, const uint32_t* a, const uint32_t* b) {
    asm volatile("mma.sync.aligned.m16n8k16.row.col.f32.bf16.bf16.f32 "
        "{%0,%1,%2,%3}, {%4,%5,%6,%7}, {%8,%9}, {%0,%1,%2,%3};"
        : "+f"(d[0]), "+f"(d[1]), "+f"(d[2]), "+f"(d[3])
        : "r"(a[0]), "r"(a[1]), "r"(a[2]), "r"(a[3]), "r"(b[0]), "r"(b[1]));
}
__device__ __forceinline__ void ldsm4(uint32_t* r, uint32_t addr) {
    asm volatile("ldmatrix.sync.aligned.m8n8.x4.shared.b16 {%0,%1,%2,%3}, [%4];"
        : "=r"(r[0]), "=r"(r[1]), "=r"(r[2]), "=r"(r[3]) : "r"(addr));
}
__device__ __forceinline__ void cp16(uint32_t s, const void* g) {
    asm volatile("cp.async.cg.shared.global [%0], [%1], 16;" :: "r"(s), "l"(g));
}

// ---------------- split-bf16 tensor-core GEMM ----------------
// C[M=grid.y*128][N] = Ah/Al [M][K] * (Bh/Bl [N][K])^T with fp32 accumulate.
// MODE 0: store fp32 C.  MODE 1: C = acc + Rs (residual).  MODE 2: gelu(acc) -> split bf16 Oh/Ol.
#define GSMEM (2*4*128*40*2)   // 81920 bytes
template<int MODE>
__global__ __launch_bounds__(256, 1) void gemm3_k(
    const bf16* __restrict__ Ah, const bf16* __restrict__ Al,
    const bf16* __restrict__ Bh, const bf16* __restrict__ Bl,
    float* C, const float* Rs,
    bf16* Oh, bf16* Ol,
    int N, int K)
{
    extern __shared__ __align__(16) bf16 sm[];
    const int tid = threadIdx.x;
    const int lane = tid & 31, warp = tid >> 5;
    const int wm = warp & 1, wn = warp >> 1;          // 2 x 4 warp grid
    const int row0 = blockIdx.y * 128, col0 = blockIdx.x * 128;
    const uint32_t sbase = (uint32_t)__cvta_generic_to_shared(sm);
    const int TSB = 128 * 40 * 2;   // bytes per array (padded stride 40 bf16)

    float acc[4][4][4];
    #pragma unroll
    for (int i = 0; i < 4; i++)
        #pragma unroll
        for (int j = 0; j < 4; j++)
            #pragma unroll
            for (int r = 0; r < 4; r++) acc[i][j][r] = 0.f;

    auto issue = [&](int buf, int kt) {
        int k0 = kt * 32;
        uint32_t b0 = sbase + buf * (4 * TSB);
        #pragma unroll
        for (int i = 0; i < 2; i++) {
            int id = tid + i * 256;
            int r = id >> 2, c8 = (id & 3) << 3;
            uint32_t so = (uint32_t)(r * 40 + c8) * 2;
            cp16(b0 + so,           Ah + (size_t)(row0 + r) * K + k0 + c8);
            cp16(b0 + TSB + so,     Al + (size_t)(row0 + r) * K + k0 + c8);
            cp16(b0 + 2*TSB + so,   Bh + (size_t)(col0 + r) * K + k0 + c8);
            cp16(b0 + 3*TSB + so,   Bl + (size_t)(col0 + r) * K + k0 + c8);
        }
        asm volatile("cp.async.commit_group;");
    };

    const int KT = K >> 5;
    issue(0, 0);
    const int lr = lane & 15, lc8 = (lane >> 4) << 3;

    for (int kt = 0; kt < KT; kt++) {
        int cur = kt & 1;
        if (kt + 1 < KT) { issue(cur ^ 1, kt + 1); asm volatile("cp.async.wait_group 1;"); }
        else             { asm volatile("cp.async.wait_group 0;"); }
        __syncthreads();
        uint32_t ab = sbase + cur * (4 * TSB);
        #pragma unroll
        for (int k16 = 0; k16 < 2; k16++) {
            uint32_t ah[4][4], al[4][4], bh[4][2], bl[4][2];
            #pragma unroll
            for (int mf = 0; mf < 4; mf++) {
                uint32_t off = (uint32_t)((wm * 64 + mf * 16 + lr) * 40 + k16 * 16 + lc8) * 2;
                ldsm4(ah[mf], ab + off);
                ldsm4(al[mf], ab + TSB + off);
            }
            #pragma unroll
            for (int g = 0; g < 2; g++) {
                uint32_t off = (uint32_t)((wn * 32 + g * 16 + lr) * 40 + k16 * 16 + lc8) * 2;
                uint32_t r[4];
                ldsm4(r, ab + 2 * TSB + off);
                bh[g*2][0] = r[0]; bh[g*2][1] = r[2]; bh[g*2+1][0] = r[1]; bh[g*2+1][1] = r[3];
                ldsm4(r, ab + 3 * TSB + off);
                bl[g*2][0] = r[0]; bl[g*2][1] = r[2]; bl[g*2+1][0] = r[1]; bl[g*2+1][1] = r[3];
            }
            #pragma unroll
            for (int mf = 0; mf < 4; mf++)
                #pragma unroll
                for (int nf = 0; nf < 4; nf++) {
                    mma_bf16(acc[mf][nf], ah[mf], bh[nf]);
                    mma_bf16(acc[mf][nf], ah[mf], bl[nf]);
                    mma_bf16(acc[mf][nf], al[mf], bh[nf]);
                }
        }
        __syncthreads();
    }

    // epilogue
    #pragma unroll
    for (int mf = 0; mf < 4; mf++)
        #pragma unroll
        for (int nf = 0; nf < 4; nf++) {
            int r = row0 + wm * 64 + mf * 16 + (lane >> 2);
            int c = col0 + wn * 32 + nf * 8 + (lane & 3) * 2;
            float* d = acc[mf][nf];
            if (MODE == 0) {
                *(float2*)(C + (size_t)r * N + c)       = make_float2(d[0], d[1]);
                *(float2*)(C + (size_t)(r + 8) * N + c) = make_float2(d[2], d[3]);
            } else if (MODE == 1) {
                float2 r1 = *(const float2*)(Rs + (size_t)r * N + c);
                float2 r2 = *(const float2*)(Rs + (size_t)(r + 8) * N + c);
                *(float2*)(C + (size_t)r * N + c)       = make_float2(d[0] + r1.x, d[1] + r1.y);
                *(float2*)(C + (size_t)(r + 8) * N + c) = make_float2(d[2] + r2.x, d[3] + r2.y);
            } else {
                float v0 = gelu_exact(d[0]), v1 = gelu_exact(d[1]);
                float v2 = gelu_exact(d[2]), v3 = gelu_exact(d[3]);
                bf16 h0, l0, h1, l1, h2, l2, h3, l3;
                split_bf16(v0, h0, l0); split_bf16(v1, h1, l1);
                split_bf16(v2, h2, l2); split_bf16(v3, h3, l3);
                *(__nv_bfloat162*)(Oh + (size_t)r * N + c)       = __halves2bfloat162(h0, h1);
                *(__nv_bfloat162*)(Ol + (size_t)r * N + c)       = __halves2bfloat162(l0, l1);
                *(__nv_bfloat162*)(Oh + (size_t)(r + 8) * N + c) = __halves2bfloat162(h2, h3);
                *(__nv_bfloat162*)(Ol + (size_t)(r + 8) * N + c) = __halves2bfloat162(l2, l3);
            }
        }
}

// ---------------- weight transpose + split: W[K][N] -> Th/Tl[N][ldt] ----------------
__global__ void wtsplit_k(const float* __restrict__ W, bf16* __restrict__ Th,
                          bf16* __restrict__ Tl, int K, int N, int ldt) {
    __shared__ float t[32][33];
    int n0 = blockIdx.x * 32, k0 = blockIdx.y * 32;
    int tx = threadIdx.x, ty = threadIdx.y;
    #pragma unroll
    for (int r = ty; r < 32; r += 8)
        t[r][tx] = W[(size_t)(k0 + r) * N + n0 + tx];
    __syncthreads();
    #pragma unroll
    for (int r = ty; r < 32; r += 8) {
        float v = t[tx][r];
        bf16 h, l; split_bf16(v, h, l);
        Th[(size_t)(n0 + r) * ldt + k0 + tx] = h;
        Tl[(size_t)(n0 + r) * ldt + k0 + tx] = l;
    }
}

// ---------------- embed split (already [N][K]) ----------------
__global__ void esplit_k(const float* __restrict__ E, bf16* __restrict__ Eh, bf16* __restrict__ El) {
    size_t i = (size_t)blockIdx.x * 256 + threadIdx.x;
    float v = E[i];
    bf16 h, l; split_bf16(v, h, l);
    Eh[i] = h; El[i] = l;
}

// ---------------- embedding gather ----------------
__global__ void gather_embed_k(const float* __restrict__ embed, const int* __restrict__ idx) {
    int i = blockIdx.x * blockDim.x + threadIdx.x;
    int t = i >> 10, e = i & 1023;
    g_x[i] = embed[(size_t)idx[t] * EE + e];
}

// ---------------- layernorm with split-bf16 output ----------------
__global__ void layernorm_split_k(const float* __restrict__ in, bf16* __restrict__ oh,
                                  bf16* __restrict__ ol,
                                  const float* __restrict__ g, const float* __restrict__ b) {
    __shared__ float sh[256];
    int row = blockIdx.x;
    const float* x = in + (size_t)row * EE;
    float s = 0.f;
    for (int i = threadIdx.x; i < EE; i += 256) s += x[i];
    float mu = blk_sum256(s, sh) * (1.0f / EE);
    float vs = 0.f;
    for (int i = threadIdx.x; i < EE; i += 256) { float d = x[i] - mu; vs += d * d; }
    float var = blk_sum256(vs, sh) * (1.0f / EE);
    float inv = rsqrtf(var + EPSV);
    for (int i = threadIdx.x; i < EE; i += 256) {
        float v = (x[i] - mu) * inv * g[i] + b[i];
        bf16 h, l; split_bf16(v, h, l);
        oh[(size_t)row * EE + i] = h;
        ol[(size_t)row * EE + i] = l;
    }
}

// ---------------- RoPE on g_qkv (q: 16 heads, k: 4 heads) ----------------
__global__ void rope_k() {
    int i = blockIdx.x * blockDim.x + threadIdx.x;   // TT*20*16
    int j = i & 15;
    int head = (i >> 4) % 20;
    int t = i / (16 * 20);
    int col = (head < NH) ? head * DHD : EE + (head - NH) * DHD;
    float theta = powf(10000.0f, -(float)(2 * j) / 32.0f);
    float ang = (float)t * theta;
    float c = cosf(ang), s = sinf(ang);
    float* base = g_qkv + (size_t)t * QKVN + col;
    float x1 = base[j], x2 = base[j + 16];
    base[j]      = x1 * c - x2 * s;
    base[j + 16] = x2 * c + x1 * s;
}

// ---------------- attention scores (64x64 tile, causal block-skip) ----------------
__global__ __launch_bounds__(256) void attn_scores_k() {
    int st = blockIdx.x, tt = blockIdx.y, h = blockIdx.z;
    if (st > tt) return;
    int kh = h >> 2;
    __shared__ float Qs[64][65];
    __shared__ float Ks[64][65];
    int tid = threadIdx.x;
    #pragma unroll
    for (int i = 0; i < 16; i++) {
        int idx = tid + i * 256;
        int r = idx >> 6, c = idx & 63;
        Qs[r][c] = g_qkv[(size_t)(tt * 64 + r) * QKVN + h * DHD + c];
        Ks[r][c] = g_qkv[(size_t)(st * 64 + r) * QKVN + EE + kh * DHD + c];
    }
    __syncthreads();
    int tx = tid & 15, ty = tid >> 4;
    float acc[4][4] = {};
    #pragma unroll 8
    for (int d = 0; d < 64; d++) {
        float a[4], b[4];
        #pragma unroll
        for (int i = 0; i < 4; i++) a[i] = Qs[ty * 4 + i][d];
        #pragma unroll
        for (int j = 0; j < 4; j++) b[j] = Ks[tx * 4 + j][d];
        #pragma unroll
        for (int i = 0; i < 4; i++)
            #pragma unroll
            for (int j = 0; j < 4; j++)
                acc[i][j] += a[i] * b[j];
    }
    #pragma unroll
    for (int i = 0; i < 4; i++)
        #pragma unroll
        for (int j = 0; j < 4; j++)
            g_att[(size_t)h * TT * TT + (size_t)(tt * 64 + ty * 4 + i) * TT + st * 64 + tx * 4 + j]
                = acc[i][j] * 0.125f;
}

// ---------------- softmax + sigmoid-threshold gate ----------------
__global__ void softmax_thresh_k(const float* __restrict__ gate_all, int l) {
    __shared__ float sh[256];
    int h = blockIdx.x >> 10;
    int t = blockIdx.x & 1023;
    float* p = g_att + (size_t)h * TT * TT + (size_t)t * TT;
    float thr = 1.0f / (1.0f + expf(-gate_all[l * NH + h]));
    float m = -1e30f;
    for (int i = threadIdx.x; i <= t; i += 256) m = fmaxf(m, p[i]);
    m = blk_max256(m, sh);
    float s = 0.f;
    for (int i = threadIdx.x; i <= t; i += 256) s += expf(p[i] - m);
    s = blk_sum256(s, sh);
    float inv = 1.0f / s;
    for (int i = threadIdx.x; i < TT; i += 256) {
        float o = 0.f;
        if (i <= t) {
            float pv = expf(p[i] - m) * inv;
            o = (pv >= thr) ? pv : 0.f;
        }
        p[i] = o;
    }
}

// ---------------- y = att @ v, writes y split bf16 ----------------
__global__ __launch_bounds__(256) void attn_av_k() {
    int tt = blockIdx.x, h = blockIdx.y;
    int kh = h >> 2;
    __shared__ float As[16][65];
    __shared__ float Vs[16][64];
    int tid = threadIdx.x;
    int tx = tid & 15, ty = tid >> 4;
    float acc[4][4] = {};
    int kmax = (tt + 1) * 64;
    const float* abase = g_att + (size_t)h * TT * TT;
    for (int k0 = 0; k0 < kmax; k0 += 16) {
        #pragma unroll
        for (int i = 0; i < 4; i++) {
            int idx = tid + i * 256;
            int r = idx >> 4, c = idx & 15;
            As[c][r] = abase[(size_t)(tt * 64 + r) * TT + k0 + c];
        }
        #pragma unroll
        for (int i = 0; i < 4; i++) {
            int idx = tid + i * 256;
            int r = idx >> 6, c = idx & 63;
            Vs[r][c] = g_qkv[(size_t)(k0 + r) * QKVN + EE + KVD + kh * DHD + c];
        }
        __syncthreads();
        #pragma unroll
        for (int kk = 0; kk < 16; kk++) {
            float a[4], b[4];
            #pragma unroll
            for (int i = 0; i < 4; i++) a[i] = As[kk][ty * 4 + i];
            #pragma unroll
            for (int j = 0; j < 4; j++) b[j] = Vs[kk][tx * 4 + j];
            #pragma unroll
            for (int i = 0; i < 4; i++)
                #pragma unroll
                for (int j = 0; j < 4; j++)
                    acc[i][j] += a[i] * b[j];
        }
        __syncthreads();
    }
    #pragma unroll
    for (int i = 0; i < 4; i++)
        #pragma unroll
        for (int j = 0; j < 4; j++) {
            size_t idx = (size_t)(tt * 64 + ty * 4 + i) * EE + h * DHD + tx * 4 + j;
            bf16 hh, ll; split_bf16(acc[i][j], hh, ll);
            g_yh[idx] = hh; g_yl[idx] = ll;
        }
}

// ---------------- loss ----------------
__global__ void zero_loss_k() { g_loss = 0.f; }

__global__ void loss_rows_k(const float* __restrict__ logits, const int* __restrict__ targets) {
    __shared__ float sh[256];
    int t = blockIdx.x;
    const float* row = logits + (size_t)t * VV;
    float m = -1e30f;
    for (int i = threadIdx.x; i < VV; i += 256) m = fmaxf(m, row[i]);
    m = blk_max256(m, sh);
    float s = 0.f;
    for (int i = threadIdx.x; i < VV; i += 256) s += expf(row[i] - m);
    s = blk_sum256(s, sh);
    if (threadIdx.x == 0) {
        float lp = row[targets[t]] - m - logf(s);
        atomicAdd(&g_loss, -lp);
    }
}

__global__ void loss_fin_k(float* dst) { *dst = g_loss * (1.0f / (float)TT); }

// ---------------- host orchestration ----------------
extern "C" void kernel_launch(void* const* d_in, const int* in_sizes, int n_in,
                              void* d_out, int out_size) {
    const float* embed = (const float*)d_in[0];
    const float* ln1_g = (const float*)d_in[1];
    const float* ln1_b = (const float*)d_in[2];
    const float* Wq    = (const float*)d_in[3];
    const float* Wk    = (const float*)d_in[4];
    const float* Wv    = (const float*)d_in[5];
    const float* Wo    = (const float*)d_in[6];
    const float* gate  = (const float*)d_in[7];
    const float* ln2_g = (const float*)d_in[8];
    const float* ln2_b = (const float*)d_in[9];
    const float* W1    = (const float*)d_in[10];
    const float* W2    = (const float*)d_in[11];
    const float* lnf_g = (const float*)d_in[12];
    const float* lnf_b = (const float*)d_in[13];
    const int*   idx   = (const int*)d_in[14];
    const int*   tgt   = (const int*)d_in[15];

    float *xp, *qkvp, *logp;
    bf16 *hh, *hl, *yh, *yl, *ffh, *ffl;
    bf16 *wqkvh, *wqkvl, *woh, *wol, *w1h, *w1l, *w2h, *w2l, *eh, *el;
    cudaGetSymbolAddress((void**)&xp,    g_x);
    cudaGetSymbolAddress((void**)&qkvp,  g_qkv);
    cudaGetSymbolAddress((void**)&logp,  g_logits);
    cudaGetSymbolAddress((void**)&hh,    g_hh);
    cudaGetSymbolAddress((void**)&hl,    g_hl);
    cudaGetSymbolAddress((void**)&yh,    g_yh);
    cudaGetSymbolAddress((void**)&yl,    g_yl);
    cudaGetSymbolAddress((void**)&ffh,   g_ffh);
    cudaGetSymbolAddress((void**)&ffl,   g_ffl);
    cudaGetSymbolAddress((void**)&wqkvh, g_wqkv_h);
    cudaGetSymbolAddress((void**)&wqkvl, g_wqkv_l);
    cudaGetSymbolAddress((void**)&woh,   g_wo_h);
    cudaGetSymbolAddress((void**)&wol,   g_wo_l);
    cudaGetSymbolAddress((void**)&w1h,   g_w1_h);
    cudaGetSymbolAddress((void**)&w1l,   g_w1_l);
    cudaGetSymbolAddress((void**)&w2h,   g_w2_h);
    cudaGetSymbolAddress((void**)&w2l,   g_w2_l);
    cudaGetSymbolAddress((void**)&eh,    g_eh);
    cudaGetSymbolAddress((void**)&el,    g_el);

    cudaFuncSetAttribute(gemm3_k<0>, cudaFuncAttributeMaxDynamicSharedMemorySize, GSMEM);
    cudaFuncSetAttribute(gemm3_k<1>, cudaFuncAttributeMaxDynamicSharedMemorySize, GSMEM);
    cudaFuncSetAttribute(gemm3_k<2>, cudaFuncAttributeMaxDynamicSharedMemorySize, GSMEM);

    const size_t BTV = (size_t)TT * VV;
    float* logits_dst = ((size_t)out_size >= BTV) ? (float*)d_out : logp;
    float* loss_dst = nullptr;
    if ((size_t)out_size > BTV)      loss_dst = (float*)d_out + BTV;
    else if ((size_t)out_size < BTV) loss_dst = (float*)d_out;

    dim3 tb(32, 8);
    // weight split + transpose (deterministic, redone each call)
    for (int l = 0; l < LNUM; l++) {
        wtsplit_k<<<dim3(EE/32, EE/32), tb>>>(Wq + (size_t)l*EE*EE,
            wqkvh + (size_t)l*QKVN*EE, wqkvl + (size_t)l*QKVN*EE, EE, EE, EE);
        wtsplit_k<<<dim3(KVD/32, EE/32), tb>>>(Wk + (size_t)l*EE*KVD,
            wqkvh + (size_t)l*QKVN*EE + (size_t)EE*EE, wqkvl + (size_t)l*QKVN*EE + (size_t)EE*EE, EE, KVD, EE);
        wtsplit_k<<<dim3(KVD/32, EE/32), tb>>>(Wv + (size_t)l*EE*KVD,
            wqkvh + (size_t)l*QKVN*EE + (size_t)(EE+KVD)*EE, wqkvl + (size_t)l*QKVN*EE + (size_t)(EE+KVD)*EE, EE, KVD, EE);
        wtsplit_k<<<dim3(EE/32, EE/32), tb>>>(Wo + (size_t)l*EE*EE,
            woh + (size_t)l*EE*EE, wol + (size_t)l*EE*EE, EE, EE, EE);
        wtsplit_k<<<dim3(FF/32, EE/32), tb>>>(W1 + (size_t)l*EE*FF,
            w1h + (size_t)l*FF*EE, w1l + (size_t)l*FF*EE, EE, FF, EE);
        wtsplit_k<<<dim3(EE/32, FF/32), tb>>>(W2 + (size_t)l*FF*EE,
            w2h + (size_t)l*EE*FF, w2l + (size_t)l*EE*FF, FF, EE, FF);
    }
    esplit_k<<<(int)(((size_t)VV*EE)/256), 256>>>(embed, eh, el);

    // embedding gather
    gather_embed_k<<<(TT * EE) / 256, 256>>>(embed, idx);

    for (int r = 0; r < RNUM; r++) {
        for (int l = 0; l < LNUM; l++) {
            // h = LN1(x) -> split bf16
            layernorm_split_k<<<TT, 256>>>(xp, hh, hl, ln1_g + l * EE, ln1_b + l * EE);
            // fused QKV projection -> g_qkv fp32
            gemm3_k<0><<<dim3(QKVN/128, TT/128), 256, GSMEM>>>(hh, hl,
                wqkvh + (size_t)l*QKVN*EE, wqkvl + (size_t)l*QKVN*EE,
                qkvp, nullptr, nullptr, nullptr, QKVN, EE);
            // RoPE (q and k)
            rope_k<<<(TT * 20 * 16) / 256, 256>>>();
            // attention
            attn_scores_k<<<dim3(TT/64, TT/64, NH), 256>>>();
            softmax_thresh_k<<<NH * TT, 256>>>(gate, l);
            attn_av_k<<<dim3(TT/64, NH), 256>>>();
            // x += y @ Wo
            gemm3_k<1><<<dim3(EE/128, TT/128), 256, GSMEM>>>(yh, yl,
                woh + (size_t)l*EE*EE, wol + (size_t)l*EE*EE,
                xp, xp, nullptr, nullptr, EE, EE);
            // FFN
            layernorm_split_k<<<TT, 256>>>(xp, hh, hl, ln2_g + l * EE, ln2_b + l * EE);
            gemm3_k<2><<<dim3(FF/128, TT/128), 256, GSMEM>>>(hh, hl,
                w1h + (size_t)l*FF*EE, w1l + (size_t)l*FF*EE,
                nullptr, nullptr, ffh, ffl, FF, EE);
            gemm3_k<1><<<dim3(EE/128, TT/128), 256, GSMEM>>>(ffh, ffl,
                w2h + (size_t)l*EE*FF, w2l + (size_t)l*EE*FF,
                xp, xp, nullptr, nullptr, EE, FF);
        }
    }

    // final LN + logits
    layernorm_split_k<<<TT, 256>>>(xp, hh, hl, lnf_g, lnf_b);
    gemm3_k<0><<<dim3(VV/128, TT/128), 256, GSMEM>>>(hh, hl, eh, el,
        logits_dst, nullptr, nullptr, nullptr, VV, EE);

    // loss
    zero_loss_k<<<1, 1>>>();
    loss_rows_k<<<TT, 256>>>(logits_dst, tgt);
    if (loss_dst) loss_fin_k<<<1, 1>>>(loss_dst);
}

// round 5
// speedup vs baseline: 2.8493x; 1.1604x over previous
#include <cuda_runtime.h>
#include <cuda_bf16.h>
#include <math.h>
#include <stdint.h>

// ---------------- problem constants ----------------
#define TT 1024
#define EE 1024
#define VV 32000
#define NH 16
#define NKV 4
#define DHD 64
#define KVD (NKV*DHD)     // 256
#define QKVN 1536
#define LNUM 2
#define RNUM 2
#define FF 4096
#define EPSV 1e-5f

typedef __nv_bfloat16 bf16;

// ---------------- device scratch ----------------
__device__ float g_x[TT*EE];
__device__ bf16  g_hh[TT*EE], g_hl[TT*EE];
__device__ float g_qkv[TT*QKVN];
__device__ float g_att[(size_t)NH*TT*TT];
__device__ bf16  g_yh[TT*EE], g_yl[TT*EE];
__device__ bf16  g_ffh[TT*FF], g_ffl[TT*FF];
__device__ bf16  g_wqkv_h[LNUM*QKVN*EE], g_wqkv_l[LNUM*QKVN*EE];
__device__ bf16  g_wo_h[LNUM*EE*EE],     g_wo_l[LNUM*EE*EE];
__device__ bf16  g_w1_h[LNUM*FF*EE],     g_w1_l[LNUM*FF*EE];
__device__ bf16  g_w2_h[LNUM*EE*FF],     g_w2_l[LNUM*EE*FF];
__device__ bf16  g_eh[(size_t)VV*EE],    g_el[(size_t)VV*EE];
__device__ float g_logits[(size_t)TT*VV];
__device__ float g_loss;

// ---------------- generic helpers ----------------
__device__ __forceinline__ float blk_sum256(float v, float* sh) {
    int tid = threadIdx.x;
    sh[tid] = v; __syncthreads();
    #pragma unroll
    for (int s = 128; s > 0; s >>= 1) { if (tid < s) sh[tid] += sh[tid + s]; __syncthreads(); }
    float r = sh[0]; __syncthreads();
    return r;
}
__device__ __forceinline__ float blk_max256(float v, float* sh) {
    int tid = threadIdx.x;
    sh[tid] = v; __syncthreads();
    #pragma unroll
    for (int s = 128; s > 0; s >>= 1) { if (tid < s) sh[tid] = fmaxf(sh[tid], sh[tid + s]); __syncthreads(); }
    float r = sh[0]; __syncthreads();
    return r;
}
__device__ __forceinline__ float gelu_exact(float x) {
    return 0.5f * x * (1.0f + erff(x * 0.7071067811865476f));
}
__device__ __forceinline__ void split_bf16(float v, bf16& h, bf16& l) {
    h = __float2bfloat16(v);
    l = __float2bfloat16(v - __bfloat162float(h));
}

// ---------------- PTX wrappers ----------------
__device__ __forceinline__ void mma_bf16(float* d, const uint32_t* a, const uint32_t* b) {
    asm volatile("mma.sync.aligned.m16n8k16.row.col.f32.bf16.bf16.f32 "
        "{%0,%1,%2,%3}, {%4,%5,%6,%7}, {%8,%9}, {%0,%1,%2,%3};"
        : "+f"(d[0]), "+f"(d[1]), "+f"(d[2]), "+f"(d[3])
        : "r"(a[0]), "r"(a[1]), "r"(a[2]), "r"(a[3]), "r"(b[0]), "r"(b[1]));
}
__device__ __forceinline__ void ldsm4(uint32_t* r, uint32_t addr) {
    asm volatile("ldmatrix.sync.aligned.m8n8.x4.shared.b16 {%0,%1,%2,%3}, [%4];"
        : "=r"(r[0]), "=r"(r[1]), "=r"(r[2]), "=r"(r[3]) : "r"(addr));
}
__device__ __forceinline__ void cp16(uint32_t s, const void* g) {
    asm volatile("cp.async.cg.shared.global [%0], [%1], 16;" :: "r"(s), "l"(g));
}
#define CP_COMMIT()  asm volatile("cp.async.commit_group;")
#define CP_WAIT(n)   asm volatile("cp.async.wait_group %0;" :: "n"(n))

// SW128 swizzle: 128B rows, 16B chunks, chunk ^= row&7  (conflict-free ldmatrix)
__device__ __forceinline__ uint32_t sw_off(int row, int chunk) {
    return (uint32_t)(row * 128 + ((chunk ^ (row & 7)) << 4));
}

// ---------------- split-bf16 HMMA GEMM ----------------
// C[128 x TN] tiles. blockIdx.x = M tile (fast), blockIdx.y = N tile.
// A(h,l)[M][K], B(h,l)[N][K] bf16; D = A*B^T fp32 via 3 MMA combos (ah*bh + ah*bl + al*bh).
// MODE 0: store fp32. MODE 1: +Rs residual fp32. MODE 2: gelu -> split bf16 Oh/Ol.
// BK = 64 (128B rows), double-buffered cp.async, SW128 swizzle.
template<int MODE, int TN>
__global__ __launch_bounds__(256, 1) void gemm_mma(
    const bf16* __restrict__ Ah, const bf16* __restrict__ Al,
    const bf16* __restrict__ Bh, const bf16* __restrict__ Bl,
    float* C, const float* Rs, bf16* Oh, bf16* Ol,
    int N, int K)
{
    constexpr int TSA = 128 * 128;      // bytes per A tile (128 rows x 128B)
    constexpr int TSB = TN * 128;       // bytes per B tile
    constexpr int SB  = 2 * TSA + 2 * TSB;   // stage bytes
    constexpr int BCH = TN * 8;         // chunks per B tile
    constexpr int TC  = 2048 + 2 * BCH; // total 16B chunks per stage
    constexpr int NG  = TN / 64;        // 16-row B groups per warp (2 or 4)
    constexpr int NF  = 2 * NG;         // n8 fragments per warp

    extern __shared__ char dsm[];
    const int tid = threadIdx.x;
    const int lane = tid & 31, warp = tid >> 5;
    const int wm = warp & 1, wn = warp >> 1;       // 2 x 4 warp grid
    const int row0 = blockIdx.x * 128, col0 = blockIdx.y * TN;
    const uint32_t sb = (uint32_t)__cvta_generic_to_shared(dsm);

    float acc[4][NF][4];
    #pragma unroll
    for (int i = 0; i < 4; i++)
        #pragma unroll
        for (int j = 0; j < NF; j++)
            #pragma unroll
            for (int r = 0; r < 4; r++) acc[i][j][r] = 0.f;

    auto load_stage = [&](int s) {
        int k0 = s * 64;
        uint32_t base = sb + (s & 1) * SB;
        #pragma unroll
        for (int ii = 0; ii < TC / 256; ii++) {
            int i = tid + ii * 256;
            const bf16* src;
            uint32_t toff;
            if (i < 2048) {
                int t = i >> 10, w = i & 1023;
                int r = w >> 3, c = w & 7;
                src = (t ? Al : Ah) + (size_t)(row0 + r) * K + k0 + c * 8;
                toff = t * TSA + sw_off(r, c);
            } else {
                int j = i - 2048;
                int t = j / BCH, w = j & (BCH - 1);
                int r = w >> 3, c = w & 7;
                src = (t ? Bl : Bh) + (size_t)(col0 + r) * K + k0 + c * 8;
                toff = 2 * TSA + t * TSB + sw_off(r, c);
            }
            cp16(base + toff, src);
        }
        CP_COMMIT();
    };

    const int S = K >> 6;
    load_stage(0);
    load_stage(1);

    const int lr = lane & 15, lcs = lane >> 4;   // ldsm row-within-16, 16B col select

    for (int s = 0; s < S; s++) {
        if (s + 1 < S) { CP_WAIT(1); } else { CP_WAIT(0); }
        __syncthreads();
        uint32_t ab = sb + (s & 1) * SB;
        #pragma unroll
        for (int k16 = 0; k16 < 4; k16++) {
            const int cch = k16 * 2 + lcs;
            uint32_t ah[4][4], al[4][4];
            #pragma unroll
            for (int mf = 0; mf < 4; mf++) {
                int row = wm * 64 + mf * 16 + lr;
                uint32_t off = sw_off(row, cch);
                ldsm4(ah[mf], ab + off);
                ldsm4(al[mf], ab + TSA + off);
            }
            #pragma unroll
            for (int g = 0; g < NG; g++) {
                int row = wn * (TN / 4) + g * 16 + lr;
                uint32_t off = sw_off(row, cch);
                uint32_t rh[4], rl[4];
                ldsm4(rh, ab + 2 * TSA + off);
                ldsm4(rl, ab + 2 * TSA + TSB + off);
                uint32_t b0h[2] = {rh[0], rh[2]}, b1h[2] = {rh[1], rh[3]};
                uint32_t b0l[2] = {rl[0], rl[2]}, b1l[2] = {rl[1], rl[3]};
                #pragma unroll
                for (int mf = 0; mf < 4; mf++) {
                    mma_bf16(acc[mf][g*2], ah[mf], b0h);
                    mma_bf16(acc[mf][g*2], ah[mf], b0l);
                    mma_bf16(acc[mf][g*2], al[mf], b0h);
                    mma_bf16(acc[mf][g*2+1], ah[mf], b1h);
                    mma_bf16(acc[mf][g*2+1], ah[mf], b1l);
                    mma_bf16(acc[mf][g*2+1], al[mf], b1h);
                }
            }
        }
        __syncthreads();
        if (s + 2 < S) load_stage(s + 2);
    }

    // epilogue
    #pragma unroll
    for (int mf = 0; mf < 4; mf++)
        #pragma unroll
        for (int nf = 0; nf < NF; nf++) {
            int r = row0 + wm * 64 + mf * 16 + (lane >> 2);
            int c = col0 + wn * (TN / 4) + nf * 8 + (lane & 3) * 2;
            float* d = acc[mf][nf];
            if (MODE == 0) {
                *(float2*)(C + (size_t)r * N + c)       = make_float2(d[0], d[1]);
                *(float2*)(C + (size_t)(r + 8) * N + c) = make_float2(d[2], d[3]);
            } else if (MODE == 1) {
                float2 r1 = *(const float2*)(Rs + (size_t)r * N + c);
                float2 r2 = *(const float2*)(Rs + (size_t)(r + 8) * N + c);
                *(float2*)(C + (size_t)r * N + c)       = make_float2(d[0] + r1.x, d[1] + r1.y);
                *(float2*)(C + (size_t)(r + 8) * N + c) = make_float2(d[2] + r2.x, d[3] + r2.y);
            } else {
                float v0 = gelu_exact(d[0]), v1 = gelu_exact(d[1]);
                float v2 = gelu_exact(d[2]), v3 = gelu_exact(d[3]);
                bf16 h0, l0, h1, l1, h2, l2, h3, l3;
                split_bf16(v0, h0, l0); split_bf16(v1, h1, l1);
                split_bf16(v2, h2, l2); split_bf16(v3, h3, l3);
                *(__nv_bfloat162*)(Oh + (size_t)r * N + c)       = __halves2bfloat162(h0, h1);
                *(__nv_bfloat162*)(Ol + (size_t)r * N + c)       = __halves2bfloat162(l0, l1);
                *(__nv_bfloat162*)(Oh + (size_t)(r + 8) * N + c) = __halves2bfloat162(h2, h3);
                *(__nv_bfloat162*)(Ol + (size_t)(r + 8) * N + c) = __halves2bfloat162(l2, l3);
            }
        }
}

#define GSM128 (2 * (2*128*128 + 2*128*128))
#define GSM256 (2 * (2*128*128 + 2*256*128))

// ---------------- weight transpose + split ----------------
__global__ void wtsplit_k(const float* __restrict__ W, bf16* __restrict__ Th,
                          bf16* __restrict__ Tl, int K, int N, int ldt) {
    __shared__ float t[32][33];
    int n0 = blockIdx.x * 32, k0 = blockIdx.y * 32;
    int tx = threadIdx.x, ty = threadIdx.y;
    #pragma unroll
    for (int r = ty; r < 32; r += 8)
        t[r][tx] = W[(size_t)(k0 + r) * N + n0 + tx];
    __syncthreads();
    #pragma unroll
    for (int r = ty; r < 32; r += 8) {
        float v = t[tx][r];
        bf16 h, l; split_bf16(v, h, l);
        Th[(size_t)(n0 + r) * ldt + k0 + tx] = h;
        Tl[(size_t)(n0 + r) * ldt + k0 + tx] = l;
    }
}

// ---------------- embed split ----------------
__global__ void esplit_k(const float* __restrict__ E, bf16* __restrict__ Eh, bf16* __restrict__ El) {
    size_t i = ((size_t)blockIdx.x * 256 + threadIdx.x) * 4;
    float4 v = *(const float4*)(E + i);
    bf16 h0,l0,h1,l1,h2,l2,h3,l3;
    split_bf16(v.x,h0,l0); split_bf16(v.y,h1,l1); split_bf16(v.z,h2,l2); split_bf16(v.w,h3,l3);
    *(__nv_bfloat162*)(Eh + i)     = __halves2bfloat162(h0, h1);
    *(__nv_bfloat162*)(Eh + i + 2) = __halves2bfloat162(h2, h3);
    *(__nv_bfloat162*)(El + i)     = __halves2bfloat162(l0, l1);
    *(__nv_bfloat162*)(El + i + 2) = __halves2bfloat162(l2, l3);
}

// ---------------- embedding gather ----------------
__global__ void gather_embed_k(const float* __restrict__ embed, const int* __restrict__ idx) {
    int i = blockIdx.x * blockDim.x + threadIdx.x;
    int t = i >> 10, e = i & 1023;
    g_x[i] = embed[(size_t)idx[t] * EE + e];
}

// ---------------- layernorm with split-bf16 output ----------------
__global__ void layernorm_split_k(const float* __restrict__ in, bf16* __restrict__ oh,
                                  bf16* __restrict__ ol,
                                  const float* __restrict__ g, const float* __restrict__ b) {
    __shared__ float sh[256];
    int row = blockIdx.x;
    const float* x = in + (size_t)row * EE;
    float s = 0.f;
    for (int i = threadIdx.x; i < EE; i += 256) s += x[i];
    float mu = blk_sum256(s, sh) * (1.0f / EE);
    float vs = 0.f;
    for (int i = threadIdx.x; i < EE; i += 256) { float d = x[i] - mu; vs += d * d; }
    float var = blk_sum256(vs, sh) * (1.0f / EE);
    float inv = rsqrtf(var + EPSV);
    for (int i = threadIdx.x; i < EE; i += 256) {
        float v = (x[i] - mu) * inv * g[i] + b[i];
        bf16 h, l; split_bf16(v, h, l);
        oh[(size_t)row * EE + i] = h;
        ol[(size_t)row * EE + i] = l;
    }
}

// ---------------- RoPE on g_qkv ----------------
__global__ void rope_k() {
    int i = blockIdx.x * blockDim.x + threadIdx.x;   // TT*20*16
    int j = i & 15;
    int head = (i >> 4) % 20;
    int t = i / (16 * 20);
    int col = (head < NH) ? head * DHD : EE + (head - NH) * DHD;
    float theta = powf(10000.0f, -(float)(2 * j) / 32.0f);
    float ang = (float)t * theta;
    float c = cosf(ang), s = sinf(ang);
    float* base = g_qkv + (size_t)t * QKVN + col;
    float x1 = base[j], x2 = base[j + 16];
    base[j]      = x1 * c - x2 * s;
    base[j + 16] = x2 * c + x1 * s;
}

// ---------------- attention scores ----------------
__global__ __launch_bounds__(256) void attn_scores_k() {
    int st = blockIdx.x, tt = blockIdx.y, h = blockIdx.z;
    if (st > tt) return;
    int kh = h >> 2;
    __shared__ float Qs[64][65];
    __shared__ float Ks[64][65];
    int tid = threadIdx.x;
    #pragma unroll
    for (int i = 0; i < 16; i++) {
        int idx = tid + i * 256;
        int r = idx >> 6, c = idx & 63;
        Qs[r][c] = g_qkv[(size_t)(tt * 64 + r) * QKVN + h * DHD + c];
        Ks[r][c] = g_qkv[(size_t)(st * 64 + r) * QKVN + EE + kh * DHD + c];
    }
    __syncthreads();
    int tx = tid & 15, ty = tid >> 4;
    float acc[4][4] = {};
    #pragma unroll 8
    for (int d = 0; d < 64; d++) {
        float a[4], b[4];
        #pragma unroll
        for (int i = 0; i < 4; i++) a[i] = Qs[ty * 4 + i][d];
        #pragma unroll
        for (int j = 0; j < 4; j++) b[j] = Ks[tx * 4 + j][d];
        #pragma unroll
        for (int i = 0; i < 4; i++)
            #pragma unroll
            for (int j = 0; j < 4; j++)
                acc[i][j] += a[i] * b[j];
    }
    #pragma unroll
    for (int i = 0; i < 4; i++)
        #pragma unroll
        for (int j = 0; j < 4; j++)
            g_att[(size_t)h * TT * TT + (size_t)(tt * 64 + ty * 4 + i) * TT + st * 64 + tx * 4 + j]
                = acc[i][j] * 0.125f;
}

// ---------------- softmax + sigmoid-threshold gate ----------------
__global__ void softmax_thresh_k(const float* __restrict__ gate_all, int l) {
    __shared__ float sh[256];
    int h = blockIdx.x >> 10;
    int t = blockIdx.x & 1023;
    float* p = g_att + (size_t)h * TT * TT + (size_t)t * TT;
    float thr = 1.0f / (1.0f + expf(-gate_all[l * NH + h]));
    float m = -1e30f;
    for (int i = threadIdx.x; i <= t; i += 256) m = fmaxf(m, p[i]);
    m = blk_max256(m, sh);
    float s = 0.f;
    for (int i = threadIdx.x; i <= t; i += 256) s += expf(p[i] - m);
    s = blk_sum256(s, sh);
    float inv = 1.0f / s;
    for (int i = threadIdx.x; i < TT; i += 256) {
        float o = 0.f;
        if (i <= t) {
            float pv = expf(p[i] - m) * inv;
            o = (pv >= thr) ? pv : 0.f;
        }
        p[i] = o;
    }
}

// ---------------- y = att @ v, split-bf16 output ----------------
__global__ __launch_bounds__(256) void attn_av_k() {
    int tt = blockIdx.x, h = blockIdx.y;
    int kh = h >> 2;
    __shared__ float As[16][65];
    __shared__ float Vs[16][64];
    int tid = threadIdx.x;
    int tx = tid & 15, ty = tid >> 4;
    float acc[4][4] = {};
    int kmax = (tt + 1) * 64;
    const float* abase = g_att + (size_t)h * TT * TT;
    for (int k0 = 0; k0 < kmax; k0 += 16) {
        #pragma unroll
        for (int i = 0; i < 4; i++) {
            int idx = tid + i * 256;
            int r = idx >> 4, c = idx & 15;
            As[c][r] = abase[(size_t)(tt * 64 + r) * TT + k0 + c];
        }
        #pragma unroll
        for (int i = 0; i < 4; i++) {
            int idx = tid + i * 256;
            int r = idx >> 6, c = idx & 63;
            Vs[r][c] = g_qkv[(size_t)(k0 + r) * QKVN + EE + KVD + kh * DHD + c];
        }
        __syncthreads();
        #pragma unroll
        for (int kk = 0; kk < 16; kk++) {
            float a[4], b[4];
            #pragma unroll
            for (int i = 0; i < 4; i++) a[i] = As[kk][ty * 4 + i];
            #pragma unroll
            for (int j = 0; j < 4; j++) b[j] = Vs[kk][tx * 4 + j];
            #pragma unroll
            for (int i = 0; i < 4; i++)
                #pragma unroll
                for (int j = 0; j < 4; j++)
                    acc[i][j] += a[i] * b[j];
        }
        __syncthreads();
    }
    #pragma unroll
    for (int i = 0; i < 4; i++)
        #pragma unroll
        for (int j = 0; j < 4; j++) {
            size_t idx = (size_t)(tt * 64 + ty * 4 + i) * EE + h * DHD + tx * 4 + j;
            bf16 hh, ll; split_bf16(acc[i][j], hh, ll);
            g_yh[idx] = hh; g_yl[idx] = ll;
        }
}

// ---------------- loss ----------------
__global__ void zero_loss_k() { g_loss = 0.f; }

__global__ void loss_rows_k(const float* __restrict__ logits, const int* __restrict__ targets) {
    __shared__ float sh[256];
    int t = blockIdx.x;
    const float* row = logits + (size_t)t * VV;
    float m = -1e30f;
    for (int i = threadIdx.x; i < VV; i += 256) m = fmaxf(m, row[i]);
    m = blk_max256(m, sh);
    float s = 0.f;
    for (int i = threadIdx.x; i < VV; i += 256) s += expf(row[i] - m);
    s = blk_sum256(s, sh);
    if (threadIdx.x == 0) {
        float lp = row[targets[t]] - m - logf(s);
        atomicAdd(&g_loss, -lp);
    }
}

__global__ void loss_fin_k(float* dst) { *dst = g_loss * (1.0f / (float)TT); }

// ---------------- host orchestration ----------------
extern "C" void kernel_launch(void* const* d_in, const int* in_sizes, int n_in,
                              void* d_out, int out_size) {
    const float* embed = (const float*)d_in[0];
    const float* ln1_g = (const float*)d_in[1];
    const float* ln1_b = (const float*)d_in[2];
    const float* Wq    = (const float*)d_in[3];
    const float* Wk    = (const float*)d_in[4];
    const float* Wv    = (const float*)d_in[5];
    const float* Wo    = (const float*)d_in[6];
    const float* gate  = (const float*)d_in[7];
    const float* ln2_g = (const float*)d_in[8];
    const float* ln2_b = (const float*)d_in[9];
    const float* W1    = (const float*)d_in[10];
    const float* W2    = (const float*)d_in[11];
    const float* lnf_g = (const float*)d_in[12];
    const float* lnf_b = (const float*)d_in[13];
    const int*   idx   = (const int*)d_in[14];
    const int*   tgt   = (const int*)d_in[15];

    float *xp, *qkvp, *logp;
    bf16 *hh, *hl, *yh, *yl, *ffh, *ffl;
    bf16 *wqkvh, *wqkvl, *woh, *wol, *w1h, *w1l, *w2h, *w2l, *eh, *el;
    cudaGetSymbolAddress((void**)&xp,    g_x);
    cudaGetSymbolAddress((void**)&qkvp,  g_qkv);
    cudaGetSymbolAddress((void**)&logp,  g_logits);
    cudaGetSymbolAddress((void**)&hh,    g_hh);
    cudaGetSymbolAddress((void**)&hl,    g_hl);
    cudaGetSymbolAddress((void**)&yh,    g_yh);
    cudaGetSymbolAddress((void**)&yl,    g_yl);
    cudaGetSymbolAddress((void**)&ffh,   g_ffh);
    cudaGetSymbolAddress((void**)&ffl,   g_ffl);
    cudaGetSymbolAddress((void**)&wqkvh, g_wqkv_h);
    cudaGetSymbolAddress((void**)&wqkvl, g_wqkv_l);
    cudaGetSymbolAddress((void**)&woh,   g_wo_h);
    cudaGetSymbolAddress((void**)&wol,   g_wo_l);
    cudaGetSymbolAddress((void**)&w1h,   g_w1_h);
    cudaGetSymbolAddress((void**)&w1l,   g_w1_l);
    cudaGetSymbolAddress((void**)&w2h,   g_w2_h);
    cudaGetSymbolAddress((void**)&w2l,   g_w2_l);
    cudaGetSymbolAddress((void**)&eh,    g_eh);
    cudaGetSymbolAddress((void**)&el,    g_el);

    cudaFuncSetAttribute(gemm_mma<0,128>, cudaFuncAttributeMaxDynamicSharedMemorySize, GSM128);
    cudaFuncSetAttribute(gemm_mma<1,128>, cudaFuncAttributeMaxDynamicSharedMemorySize, GSM128);
    cudaFuncSetAttribute(gemm_mma<0,256>, cudaFuncAttributeMaxDynamicSharedMemorySize, GSM256);
    cudaFuncSetAttribute(gemm_mma<2,256>, cudaFuncAttributeMaxDynamicSharedMemorySize, GSM256);

    const size_t BTV = (size_t)TT * VV;
    float* logits_dst = ((size_t)out_size >= BTV) ? (float*)d_out : logp;
    float* loss_dst = nullptr;
    if ((size_t)out_size > BTV)      loss_dst = (float*)d_out + BTV;
    else if ((size_t)out_size < BTV) loss_dst = (float*)d_out;

    dim3 tb(32, 8);
    for (int l = 0; l < LNUM; l++) {
        wtsplit_k<<<dim3(EE/32, EE/32), tb>>>(Wq + (size_t)l*EE*EE,
            wqkvh + (size_t)l*QKVN*EE, wqkvl + (size_t)l*QKVN*EE, EE, EE, EE);
        wtsplit_k<<<dim3(KVD/32, EE/32), tb>>>(Wk + (size_t)l*EE*KVD,
            wqkvh + (size_t)l*QKVN*EE + (size_t)EE*EE, wqkvl + (size_t)l*QKVN*EE + (size_t)EE*EE, EE, KVD, EE);
        wtsplit_k<<<dim3(KVD/32, EE/32), tb>>>(Wv + (size_t)l*EE*KVD,
            wqkvh + (size_t)l*QKVN*EE + (size_t)(EE+KVD)*EE, wqkvl + (size_t)l*QKVN*EE + (size_t)(EE+KVD)*EE, EE, KVD, EE);
        wtsplit_k<<<dim3(EE/32, EE/32), tb>>>(Wo + (size_t)l*EE*EE,
            woh + (size_t)l*EE*EE, wol + (size_t)l*EE*EE, EE, EE, EE);
        wtsplit_k<<<dim3(FF/32, EE/32), tb>>>(W1 + (size_t)l*EE*FF,
            w1h + (size_t)l*FF*EE, w1l + (size_t)l*FF*EE, EE, FF, EE);
        wtsplit_k<<<dim3(EE/32, FF/32), tb>>>(W2 + (size_t)l*FF*EE,
            w2h + (size_t)l*EE*FF, w2l + (size_t)l*EE*FF, FF, EE, FF);
    }
    esplit_k<<<(int)(((size_t)VV*EE)/1024), 256>>>(embed, eh, el);

    gather_embed_k<<<(TT * EE) / 256, 256>>>(embed, idx);

    for (int r = 0; r < RNUM; r++) {
        for (int l = 0; l < LNUM; l++) {
            layernorm_split_k<<<TT, 256>>>(xp, hh, hl, ln1_g + l * EE, ln1_b + l * EE);
            gemm_mma<0,128><<<dim3(TT/128, QKVN/128), 256, GSM128>>>(hh, hl,
                wqkvh + (size_t)l*QKVN*EE, wqkvl + (size_t)l*QKVN*EE,
                qkvp, nullptr, nullptr, nullptr, QKVN, EE);
            rope_k<<<(TT * 20 * 16) / 256, 256>>>();
            attn_scores_k<<<dim3(TT/64, TT/64, NH), 256>>>();
            softmax_thresh_k<<<NH * TT, 256>>>(gate, l);
            attn_av_k<<<dim3(TT/64, NH), 256>>>();
            gemm_mma<1,128><<<dim3(TT/128, EE/128), 256, GSM128>>>(yh, yl,
                woh + (size_t)l*EE*EE, wol + (size_t)l*EE*EE,
                xp, xp, nullptr, nullptr, EE, EE);
            layernorm_split_k<<<TT, 256>>>(xp, hh, hl, ln2_g + l * EE, ln2_b + l * EE);
            gemm_mma<2,256><<<dim3(TT/128, FF/256), 256, GSM256>>>(hh, hl,
                w1h + (size_t)l*FF*EE, w1l + (size_t)l*FF*EE,
                nullptr, nullptr, ffh, ffl, FF, EE);
            gemm_mma<1,128><<<dim3(TT/128, EE/128), 256, GSM128>>>(ffh, ffl,
                w2h + (size_t)l*EE*FF, w2l + (size_t)l*EE*FF,
                xp, xp, nullptr, nullptr, EE, FF);
        }
    }

    layernorm_split_k<<<TT, 256>>>(xp, hh, hl, lnf_g, lnf_b);
    gemm_mma<0,256><<<dim3(TT/128, VV/256), 256, GSM256>>>(hh, hl, eh, el,
        logits_dst, nullptr, nullptr, nullptr, VV, EE);

    zero_loss_k<<<1, 1>>>();
    loss_rows_k<<<TT, 256>>>(logits_dst, tgt);
    if (loss_dst) loss_fin_k<<<1, 1>>>(loss_dst);
}

// round 6
// speedup vs baseline: 3.6682x; 1.2874x over previous
#include <cuda_runtime.h>
#include <cuda_bf16.h>
#include <math.h>
#include <stdint.h>

// ---------------- problem constants ----------------
#define TT 1024
#define EE 1024
#define VV 32000
#define NH 16
#define NKV 4
#define DHD 64
#define KVD (NKV*DHD)     // 256
#define QKVN 1536
#define LNUM 2
#define RNUM 2
#define FF 4096
#define EPSV 1e-5f

typedef __nv_bfloat16 bf16;

// ---------------- device scratch ----------------
__device__ float g_x[TT*EE];
__device__ bf16  g_hh[TT*EE], g_hl[TT*EE];
__device__ float g_qkv[TT*QKVN];
__device__ float g_att[(size_t)NH*TT*TT];
__device__ float g_part[3*TT*QKVN];          // split-K partials (18MB, reused)
__device__ float g_ypart[4*TT*EE];           // AV split-K partials (16MB)
__device__ bf16  g_yh[TT*EE], g_yl[TT*EE];
__device__ bf16  g_ffh[TT*FF], g_ffl[TT*FF];
__device__ bf16  g_wqkv_h[LNUM*QKVN*EE], g_wqkv_l[LNUM*QKVN*EE];
__device__ bf16  g_wo_h[LNUM*EE*EE],     g_wo_l[LNUM*EE*EE];
__device__ bf16  g_w1_h[LNUM*FF*EE],     g_w1_l[LNUM*FF*EE];
__device__ bf16  g_w2_h[LNUM*EE*FF],     g_w2_l[LNUM*EE*FF];
__device__ bf16  g_eh[(size_t)VV*EE],    g_el[(size_t)VV*EE];
__device__ float g_logits[(size_t)TT*VV];
__device__ float g_loss;

// ---------------- generic helpers ----------------
__device__ __forceinline__ float blk_sum256(float v, float* sh) {
    int tid = threadIdx.x;
    sh[tid] = v; __syncthreads();
    #pragma unroll
    for (int s = 128; s > 0; s >>= 1) { if (tid < s) sh[tid] += sh[tid + s]; __syncthreads(); }
    float r = sh[0]; __syncthreads();
    return r;
}
__device__ __forceinline__ float blk_max256(float v, float* sh) {
    int tid = threadIdx.x;
    sh[tid] = v; __syncthreads();
    #pragma unroll
    for (int s = 128; s > 0; s >>= 1) { if (tid < s) sh[tid] = fmaxf(sh[tid], sh[tid + s]); __syncthreads(); }
    float r = sh[0]; __syncthreads();
    return r;
}
__device__ __forceinline__ float gelu_exact(float x) {
    return 0.5f * x * (1.0f + erff(x * 0.7071067811865476f));
}
__device__ __forceinline__ void split_bf16(float v, bf16& h, bf16& l) {
    h = __float2bfloat16(v);
    l = __float2bfloat16(v - __bfloat162float(h));
}

// ---------------- PTX wrappers ----------------
__device__ __forceinline__ void mma_bf16(float* d, const uint32_t* a, const uint32_t* b) {
    asm volatile("mma.sync.aligned.m16n8k16.row.col.f32.bf16.bf16.f32 "
        "{%0,%1,%2,%3}, {%4,%5,%6,%7}, {%8,%9}, {%0,%1,%2,%3};"
        : "+f"(d[0]), "+f"(d[1]), "+f"(d[2]), "+f"(d[3])
        : "r"(a[0]), "r"(a[1]), "r"(a[2]), "r"(a[3]), "r"(b[0]), "r"(b[1]));
}
__device__ __forceinline__ void ldsm4(uint32_t* r, uint32_t addr) {
    asm volatile("ldmatrix.sync.aligned.m8n8.x4.shared.b16 {%0,%1,%2,%3}, [%4];"
        : "=r"(r[0]), "=r"(r[1]), "=r"(r[2]), "=r"(r[3]) : "r"(addr));
}
__device__ __forceinline__ void cp16(uint32_t s, const void* g) {
    asm volatile("cp.async.cg.shared.global [%0], [%1], 16;" :: "r"(s), "l"(g));
}
#define CP_COMMIT()  asm volatile("cp.async.commit_group;")
#define CP_WAIT(n)   asm volatile("cp.async.wait_group %0;" :: "n"(n))

// SW128 swizzle: 128B rows, 16B chunks, chunk ^= row&7  (conflict-free ldmatrix)
__device__ __forceinline__ uint32_t sw_off(int row, int chunk) {
    return (uint32_t)(row * 128 + ((chunk ^ (row & 7)) << 4));
}

// ---------------- split-bf16 HMMA GEMM ----------------
// C[128 x TN] tiles. blockIdx.x = M tile, blockIdx.y = N tile, blockIdx.z = K split.
// A(h,l)[M][K], B(h,l)[N][K] bf16; D = A*B^T fp32 via 3 MMA combos.
// gridDim.z==1: MODE 0 store fp32, MODE 1 acc+Rs, MODE 2 gelu->split bf16.
// gridDim.z>1:  plain fp32 store to C + z*(M*N) partial slab (reduced later).
template<int MODE, int TN, int NSTG>
__global__ __launch_bounds__(256, 1) void gemm_mma(
    const bf16* __restrict__ Ah, const bf16* __restrict__ Al,
    const bf16* __restrict__ Bh, const bf16* __restrict__ Bl,
    float* C, const float* Rs, bf16* Oh, bf16* Ol,
    int N, int K)
{
    constexpr int TSA = 128 * 128;
    constexpr int TSB = TN * 128;
    constexpr int SB  = 2 * TSA + 2 * TSB;
    constexpr int BCH = TN * 8;
    constexpr int TC  = 2048 + 2 * BCH;
    constexpr int NG  = TN / 64;
    constexpr int NF  = 2 * NG;

    extern __shared__ char dsm[];
    const int tid = threadIdx.x;
    const int lane = tid & 31, warp = tid >> 5;
    const int wm = warp & 1, wn = warp >> 1;
    const int row0 = blockIdx.x * 128, col0 = blockIdx.y * TN;
    const uint32_t sb = (uint32_t)__cvta_generic_to_shared(dsm);

    float acc[4][NF][4];
    #pragma unroll
    for (int i = 0; i < 4; i++)
        #pragma unroll
        for (int j = 0; j < NF; j++)
            #pragma unroll
            for (int r = 0; r < 4; r++) acc[i][j][r] = 0.f;

    auto load_stage = [&](int s) {
        int k0 = s * 64;
        uint32_t base = sb + (s % NSTG) * SB;
        #pragma unroll
        for (int ii = 0; ii < TC / 256; ii++) {
            int i = tid + ii * 256;
            const bf16* src;
            uint32_t toff;
            if (i < 2048) {
                int t = i >> 10, w = i & 1023;
                int r = w >> 3, c = w & 7;
                src = (t ? Al : Ah) + (size_t)(row0 + r) * K + k0 + c * 8;
                toff = t * TSA + sw_off(r, c);
            } else {
                int j = i - 2048;
                int t = j / BCH, w = j & (BCH - 1);
                int r = w >> 3, c = w & 7;
                src = (t ? Bl : Bh) + (size_t)(col0 + r) * K + k0 + c * 8;
                toff = 2 * TSA + t * TSB + sw_off(r, c);
            }
            cp16(base + toff, src);
        }
        CP_COMMIT();
    };

    const int Stot = K >> 6;
    const int SK = gridDim.z;
    const int Sc = (Stot + SK - 1) / SK;
    const int s0 = blockIdx.z * Sc;
    const int s1 = min(Stot, s0 + Sc);

    #pragma unroll
    for (int i = 0; i < NSTG; i++)
        if (s0 + i < s1) load_stage(s0 + i);

    const int lr = lane & 15, lcs = lane >> 4;

    for (int s = s0; s < s1; s++) {
        int ahead = s1 - 1 - s;
        int w = ahead < (NSTG - 1) ? ahead : (NSTG - 1);
        if (w == 2)      { CP_WAIT(2); }
        else if (w == 1) { CP_WAIT(1); }
        else             { CP_WAIT(0); }
        __syncthreads();
        uint32_t ab = sb + (s % NSTG) * SB;
        #pragma unroll
        for (int k16 = 0; k16 < 4; k16++) {
            const int cch = k16 * 2 + lcs;
            uint32_t ah[4][4], al[4][4];
            #pragma unroll
            for (int mf = 0; mf < 4; mf++) {
                int row = wm * 64 + mf * 16 + lr;
                uint32_t off = sw_off(row, cch);
                ldsm4(ah[mf], ab + off);
                ldsm4(al[mf], ab + TSA + off);
            }
            #pragma unroll
            for (int g = 0; g < NG; g++) {
                int row = wn * (TN / 4) + g * 16 + lr;
                uint32_t off = sw_off(row, cch);
                uint32_t rh[4], rl[4];
                ldsm4(rh, ab + 2 * TSA + off);
                ldsm4(rl, ab + 2 * TSA + TSB + off);
                uint32_t b0h[2] = {rh[0], rh[2]}, b1h[2] = {rh[1], rh[3]};
                uint32_t b0l[2] = {rl[0], rl[2]}, b1l[2] = {rl[1], rl[3]};
                #pragma unroll
                for (int mf = 0; mf < 4; mf++) {
                    mma_bf16(acc[mf][g*2], ah[mf], b0h);
                    mma_bf16(acc[mf][g*2], ah[mf], b0l);
                    mma_bf16(acc[mf][g*2], al[mf], b0h);
                    mma_bf16(acc[mf][g*2+1], ah[mf], b1h);
                    mma_bf16(acc[mf][g*2+1], ah[mf], b1l);
                    mma_bf16(acc[mf][g*2+1], al[mf], b1h);
                }
            }
        }
        __syncthreads();
        if (s + NSTG < s1) load_stage(s + NSTG);
    }

    // epilogue
    const size_t pstride = (size_t)gridDim.x * 128 * N;
    float* Cp = C + (size_t)blockIdx.z * pstride;
    #pragma unroll
    for (int mf = 0; mf < 4; mf++)
        #pragma unroll
        for (int nf = 0; nf < NF; nf++) {
            int r = row0 + wm * 64 + mf * 16 + (lane >> 2);
            int c = col0 + wn * (TN / 4) + nf * 8 + (lane & 3) * 2;
            float* d = acc[mf][nf];
            if (gridDim.z > 1) {
                *(float2*)(Cp + (size_t)r * N + c)       = make_float2(d[0], d[1]);
                *(float2*)(Cp + (size_t)(r + 8) * N + c) = make_float2(d[2], d[3]);
            } else if (MODE == 0) {
                *(float2*)(C + (size_t)r * N + c)       = make_float2(d[0], d[1]);
                *(float2*)(C + (size_t)(r + 8) * N + c) = make_float2(d[2], d[3]);
            } else if (MODE == 1) {
                float2 r1 = *(const float2*)(Rs + (size_t)r * N + c);
                float2 r2 = *(const float2*)(Rs + (size_t)(r + 8) * N + c);
                *(float2*)(C + (size_t)r * N + c)       = make_float2(d[0] + r1.x, d[1] + r1.y);
                *(float2*)(C + (size_t)(r + 8) * N + c) = make_float2(d[2] + r2.x, d[3] + r2.y);
            } else {
                float v0 = gelu_exact(d[0]), v1 = gelu_exact(d[1]);
                float v2 = gelu_exact(d[2]), v3 = gelu_exact(d[3]);
                bf16 h0, l0, h1, l1, h2, l2, h3, l3;
                split_bf16(v0, h0, l0); split_bf16(v1, h1, l1);
                split_bf16(v2, h2, l2); split_bf16(v3, h3, l3);
                *(__nv_bfloat162*)(Oh + (size_t)r * N + c)       = __halves2bfloat162(h0, h1);
                *(__nv_bfloat162*)(Ol + (size_t)r * N + c)       = __halves2bfloat162(l0, l1);
                *(__nv_bfloat162*)(Oh + (size_t)(r + 8) * N + c) = __halves2bfloat162(h2, h3);
                *(__nv_bfloat162*)(Ol + (size_t)(r + 8) * N + c) = __halves2bfloat162(l2, l3);
            }
        }
}

#define GSM128 (3 * (2*128*128 + 2*128*128))   // 196608
#define GSM256 (2 * (2*128*128 + 2*256*128))   // 196608

// ---------------- split-K reduce kernels ----------------
__global__ void red3_k(float* __restrict__ dst, const float* __restrict__ p, int n) {
    int i = blockIdx.x * 256 + threadIdx.x;
    dst[i] = p[i] + p[i + n] + p[i + 2 * n];
}
__global__ void redadd2_k(float* __restrict__ x, const float* __restrict__ p, int n) {
    int i = blockIdx.x * 256 + threadIdx.x;
    x[i] += p[i] + p[i + n];
}

// ---------------- AV split-K output reduce + split ----------------
__global__ void ysplit_k() {
    int i = blockIdx.x * 256 + threadIdx.x;   // TT*EE
    int t = i >> 10;
    int nk = (t >> 8) + 1;
    float s = 0.f;
    for (int kz = 0; kz < nk; kz++) s += g_ypart[(size_t)kz * TT * EE + i];
    bf16 h, l; split_bf16(s, h, l);
    g_yh[i] = h; g_yl[i] = l;
}

// ---------------- weight transpose + split ----------------
__global__ void wtsplit_k(const float* __restrict__ W, bf16* __restrict__ Th,
                          bf16* __restrict__ Tl, int K, int N, int ldt) {
    __shared__ float t[32][33];
    int n0 = blockIdx.x * 32, k0 = blockIdx.y * 32;
    int tx = threadIdx.x, ty = threadIdx.y;
    #pragma unroll
    for (int r = ty; r < 32; r += 8)
        t[r][tx] = W[(size_t)(k0 + r) * N + n0 + tx];
    __syncthreads();
    #pragma unroll
    for (int r = ty; r < 32; r += 8) {
        float v = t[tx][r];
        bf16 h, l; split_bf16(v, h, l);
        Th[(size_t)(n0 + r) * ldt + k0 + tx] = h;
        Tl[(size_t)(n0 + r) * ldt + k0 + tx] = l;
    }
}

// ---------------- embed split ----------------
__global__ void esplit_k(const float* __restrict__ E, bf16* __restrict__ Eh, bf16* __restrict__ El) {
    size_t i = ((size_t)blockIdx.x * 256 + threadIdx.x) * 4;
    float4 v = *(const float4*)(E + i);
    bf16 h0,l0,h1,l1,h2,l2,h3,l3;
    split_bf16(v.x,h0,l0); split_bf16(v.y,h1,l1); split_bf16(v.z,h2,l2); split_bf16(v.w,h3,l3);
    *(__nv_bfloat162*)(Eh + i)     = __halves2bfloat162(h0, h1);
    *(__nv_bfloat162*)(Eh + i + 2) = __halves2bfloat162(h2, h3);
    *(__nv_bfloat162*)(El + i)     = __halves2bfloat162(l0, l1);
    *(__nv_bfloat162*)(El + i + 2) = __halves2bfloat162(l2, l3);
}

// ---------------- embedding gather ----------------
__global__ void gather_embed_k(const float* __restrict__ embed, const int* __restrict__ idx) {
    int i = blockIdx.x * blockDim.x + threadIdx.x;
    int t = i >> 10, e = i & 1023;
    g_x[i] = embed[(size_t)idx[t] * EE + e];
}

// ---------------- layernorm with split-bf16 output ----------------
__global__ void layernorm_split_k(const float* __restrict__ in, bf16* __restrict__ oh,
                                  bf16* __restrict__ ol,
                                  const float* __restrict__ g, const float* __restrict__ b) {
    __shared__ float sh[256];
    int row = blockIdx.x;
    const float* x = in + (size_t)row * EE;
    float s = 0.f;
    for (int i = threadIdx.x; i < EE; i += 256) s += x[i];
    float mu = blk_sum256(s, sh) * (1.0f / EE);
    float vs = 0.f;
    for (int i = threadIdx.x; i < EE; i += 256) { float d = x[i] - mu; vs += d * d; }
    float var = blk_sum256(vs, sh) * (1.0f / EE);
    float inv = rsqrtf(var + EPSV);
    for (int i = threadIdx.x; i < EE; i += 256) {
        float v = (x[i] - mu) * inv * g[i] + b[i];
        bf16 h, l; split_bf16(v, h, l);
        oh[(size_t)row * EE + i] = h;
        ol[(size_t)row * EE + i] = l;
    }
}

// ---------------- RoPE on g_qkv ----------------
__global__ void rope_k() {
    int i = blockIdx.x * blockDim.x + threadIdx.x;   // TT*20*16
    int j = i & 15;
    int head = (i >> 4) % 20;
    int t = i / (16 * 20);
    int col = (head < NH) ? head * DHD : EE + (head - NH) * DHD;
    float theta = powf(10000.0f, -(float)(2 * j) / 32.0f);
    float ang = (float)t * theta;
    float c = cosf(ang), s = sinf(ang);
    float* base = g_qkv + (size_t)t * QKVN + col;
    float x1 = base[j], x2 = base[j + 16];
    base[j]      = x1 * c - x2 * s;
    base[j + 16] = x2 * c + x1 * s;
}

// ---------------- attention scores ----------------
__global__ __launch_bounds__(256) void attn_scores_k() {
    int st = blockIdx.x, tt = blockIdx.y, h = blockIdx.z;
    if (st > tt) return;
    int kh = h >> 2;
    __shared__ float Qs[64][65];
    __shared__ float Ks[64][65];
    int tid = threadIdx.x;
    #pragma unroll
    for (int i = 0; i < 16; i++) {
        int idx = tid + i * 256;
        int r = idx >> 6, c = idx & 63;
        Qs[r][c] = g_qkv[(size_t)(tt * 64 + r) * QKVN + h * DHD + c];
        Ks[r][c] = g_qkv[(size_t)(st * 64 + r) * QKVN + EE + kh * DHD + c];
    }
    __syncthreads();
    int tx = tid & 15, ty = tid >> 4;
    float acc[4][4] = {};
    #pragma unroll 8
    for (int d = 0; d < 64; d++) {
        float a[4], b[4];
        #pragma unroll
        for (int i = 0; i < 4; i++) a[i] = Qs[ty * 4 + i][d];
        #pragma unroll
        for (int j = 0; j < 4; j++) b[j] = Ks[tx * 4 + j][d];
        #pragma unroll
        for (int i = 0; i < 4; i++)
            #pragma unroll
            for (int j = 0; j < 4; j++)
                acc[i][j] += a[i] * b[j];
    }
    #pragma unroll
    for (int i = 0; i < 4; i++)
        #pragma unroll
        for (int j = 0; j < 4; j++)
            g_att[(size_t)h * TT * TT + (size_t)(tt * 64 + ty * 4 + i) * TT + st * 64 + tx * 4 + j]
                = acc[i][j] * 0.125f;
}

// ---------------- single-pass softmax + sigmoid-threshold gate ----------------
// Row kept in 4 registers/thread: 1 global read + 1 write, zero-fill to 64-boundary.
__global__ void softmax_thresh_k(const float* __restrict__ gate_all, int l) {
    __shared__ float sh[256];
    int t = blockIdx.x, h = blockIdx.y;
    int tid = threadIdx.x;
    float* p = g_att + (size_t)h * TT * TT + (size_t)t * TT;
    float thr = 1.0f / (1.0f + expf(-gate_all[l * NH + h]));
    float x[4];
    #pragma unroll
    for (int k = 0; k < 4; k++) {
        int i = k * 256 + tid;
        x[k] = (i <= t) ? p[i] : -1e30f;
    }
    float m = fmaxf(fmaxf(x[0], x[1]), fmaxf(x[2], x[3]));
    m = blk_max256(m, sh);
    float e[4], s = 0.f;
    #pragma unroll
    for (int k = 0; k < 4; k++) {
        int i = k * 256 + tid;
        e[k] = (i <= t) ? expf(x[k] - m) : 0.f;
        s += e[k];
    }
    s = blk_sum256(s, sh);
    float inv = 1.0f / s;
    int kend = ((t >> 6) + 1) << 6;
    #pragma unroll
    for (int k = 0; k < 4; k++) {
        int i = k * 256 + tid;
        if (i < kend) {
            float pv = e[k] * inv;
            p[i] = (pv >= thr) ? pv : 0.f;
        }
    }
}

// ---------------- y = att @ v, split-K partials ----------------
// grid (tt=16, h=16, kz=4); each active block covers K chunk [kz*256, min(kmax, +256)).
__global__ __launch_bounds__(256) void attn_av_k() {
    int tt = blockIdx.x, h = blockIdx.y, kz = blockIdx.z;
    int kmax = (tt + 1) * 64;
    int kstart = kz * 256;
    if (kstart >= kmax) return;
    int kstop = min(kmax, kstart + 256);
    int kh = h >> 2;
    __shared__ float As[16][65];
    __shared__ float Vs[16][64];
    int tid = threadIdx.x;
    int tx = tid & 15, ty = tid >> 4;
    float acc[4][4] = {};
    const float* abase = g_att + (size_t)h * TT * TT;
    for (int k0 = kstart; k0 < kstop; k0 += 16) {
        #pragma unroll
        for (int i = 0; i < 4; i++) {
            int idx = tid + i * 256;
            int r = idx >> 4, c = idx & 15;
            As[c][r] = abase[(size_t)(tt * 64 + r) * TT + k0 + c];
        }
        #pragma unroll
        for (int i = 0; i < 4; i++) {
            int idx = tid + i * 256;
            int r = idx >> 6, c = idx & 63;
            Vs[r][c] = g_qkv[(size_t)(k0 + r) * QKVN + EE + KVD + kh * DHD + c];
        }
        __syncthreads();
        #pragma unroll
        for (int kk = 0; kk < 16; kk++) {
            float a[4], b[4];
            #pragma unroll
            for (int i = 0; i < 4; i++) a[i] = As[kk][ty * 4 + i];
            #pragma unroll
            for (int j = 0; j < 4; j++) b[j] = Vs[kk][tx * 4 + j];
            #pragma unroll
            for (int i = 0; i < 4; i++)
                #pragma unroll
                for (int j = 0; j < 4; j++)
                    acc[i][j] += a[i] * b[j];
        }
        __syncthreads();
    }
    float* yp = g_ypart + (size_t)kz * TT * EE;
    #pragma unroll
    for (int i = 0; i < 4; i++)
        #pragma unroll
        for (int j = 0; j < 4; j++)
            yp[(size_t)(tt * 64 + ty * 4 + i) * EE + h * DHD + tx * 4 + j] = acc[i][j];
}

// ---------------- loss ----------------
__global__ void zero_loss_k() { g_loss = 0.f; }

__global__ void loss_rows_k(const float* __restrict__ logits, const int* __restrict__ targets) {
    __shared__ float sh[256];
    int t = blockIdx.x;
    const float* row = logits + (size_t)t * VV;
    float m = -1e30f;
    for (int i = threadIdx.x; i < VV; i += 256) m = fmaxf(m, row[i]);
    m = blk_max256(m, sh);
    float s = 0.f;
    for (int i = threadIdx.x; i < VV; i += 256) s += expf(row[i] - m);
    s = blk_sum256(s, sh);
    if (threadIdx.x == 0) {
        float lp = row[targets[t]] - m - logf(s);
        atomicAdd(&g_loss, -lp);
    }
}

__global__ void loss_fin_k(float* dst) { *dst = g_loss * (1.0f / (float)TT); }

// ---------------- host orchestration ----------------
extern "C" void kernel_launch(void* const* d_in, const int* in_sizes, int n_in,
                              void* d_out, int out_size) {
    const float* embed = (const float*)d_in[0];
    const float* ln1_g = (const float*)d_in[1];
    const float* ln1_b = (const float*)d_in[2];
    const float* Wq    = (const float*)d_in[3];
    const float* Wk    = (const float*)d_in[4];
    const float* Wv    = (const float*)d_in[5];
    const float* Wo    = (const float*)d_in[6];
    const float* gate  = (const float*)d_in[7];
    const float* ln2_g = (const float*)d_in[8];
    const float* ln2_b = (const float*)d_in[9];
    const float* W1    = (const float*)d_in[10];
    const float* W2    = (const float*)d_in[11];
    const float* lnf_g = (const float*)d_in[12];
    const float* lnf_b = (const float*)d_in[13];
    const int*   idx   = (const int*)d_in[14];
    const int*   tgt   = (const int*)d_in[15];

    float *xp, *qkvp, *logp, *partp;
    bf16 *hh, *hl, *yh, *yl, *ffh, *ffl;
    bf16 *wqkvh, *wqkvl, *woh, *wol, *w1h, *w1l, *w2h, *w2l, *eh, *el;
    cudaGetSymbolAddress((void**)&xp,    g_x);
    cudaGetSymbolAddress((void**)&qkvp,  g_qkv);
    cudaGetSymbolAddress((void**)&logp,  g_logits);
    cudaGetSymbolAddress((void**)&partp, g_part);
    cudaGetSymbolAddress((void**)&hh,    g_hh);
    cudaGetSymbolAddress((void**)&hl,    g_hl);
    cudaGetSymbolAddress((void**)&yh,    g_yh);
    cudaGetSymbolAddress((void**)&yl,    g_yl);
    cudaGetSymbolAddress((void**)&ffh,   g_ffh);
    cudaGetSymbolAddress((void**)&ffl,   g_ffl);
    cudaGetSymbolAddress((void**)&wqkvh, g_wqkv_h);
    cudaGetSymbolAddress((void**)&wqkvl, g_wqkv_l);
    cudaGetSymbolAddress((void**)&woh,   g_wo_h);
    cudaGetSymbolAddress((void**)&wol,   g_wo_l);
    cudaGetSymbolAddress((void**)&w1h,   g_w1_h);
    cudaGetSymbolAddress((void**)&w1l,   g_w1_l);
    cudaGetSymbolAddress((void**)&w2h,   g_w2_h);
    cudaGetSymbolAddress((void**)&w2l,   g_w2_l);
    cudaGetSymbolAddress((void**)&eh,    g_eh);
    cudaGetSymbolAddress((void**)&el,    g_el);

    cudaFuncSetAttribute(gemm_mma<0,128,3>, cudaFuncAttributeMaxDynamicSharedMemorySize, GSM128);
    cudaFuncSetAttribute(gemm_mma<1,128,3>, cudaFuncAttributeMaxDynamicSharedMemorySize, GSM128);
    cudaFuncSetAttribute(gemm_mma<0,256,2>, cudaFuncAttributeMaxDynamicSharedMemorySize, GSM256);
    cudaFuncSetAttribute(gemm_mma<2,256,2>, cudaFuncAttributeMaxDynamicSharedMemorySize, GSM256);

    const size_t BTV = (size_t)TT * VV;
    float* logits_dst = ((size_t)out_size >= BTV) ? (float*)d_out : logp;
    float* loss_dst = nullptr;
    if ((size_t)out_size > BTV)      loss_dst = (float*)d_out + BTV;
    else if ((size_t)out_size < BTV) loss_dst = (float*)d_out;

    dim3 tb(32, 8);
    for (int l = 0; l < LNUM; l++) {
        wtsplit_k<<<dim3(EE/32, EE/32), tb>>>(Wq + (size_t)l*EE*EE,
            wqkvh + (size_t)l*QKVN*EE, wqkvl + (size_t)l*QKVN*EE, EE, EE, EE);
        wtsplit_k<<<dim3(KVD/32, EE/32), tb>>>(Wk + (size_t)l*EE*KVD,
            wqkvh + (size_t)l*QKVN*EE + (size_t)EE*EE, wqkvl + (size_t)l*QKVN*EE + (size_t)EE*EE, EE, KVD, EE);
        wtsplit_k<<<dim3(KVD/32, EE/32), tb>>>(Wv + (size_t)l*EE*KVD,
            wqkvh + (size_t)l*QKVN*EE + (size_t)(EE+KVD)*EE, wqkvl + (size_t)l*QKVN*EE + (size_t)(EE+KVD)*EE, EE, KVD, EE);
        wtsplit_k<<<dim3(EE/32, EE/32), tb>>>(Wo + (size_t)l*EE*EE,
            woh + (size_t)l*EE*EE, wol + (size_t)l*EE*EE, EE, EE, EE);
        wtsplit_k<<<dim3(FF/32, EE/32), tb>>>(W1 + (size_t)l*EE*FF,
            w1h + (size_t)l*FF*EE, w1l + (size_t)l*FF*EE, EE, FF, EE);
        wtsplit_k<<<dim3(EE/32, FF/32), tb>>>(W2 + (size_t)l*FF*EE,
            w2h + (size_t)l*EE*FF, w2l + (size_t)l*EE*FF, FF, EE, FF);
    }
    esplit_k<<<(int)(((size_t)VV*EE)/1024), 256>>>(embed, eh, el);

    gather_embed_k<<<(TT * EE) / 256, 256>>>(embed, idx);

    for (int r = 0; r < RNUM; r++) {
        for (int l = 0; l < LNUM; l++) {
            layernorm_split_k<<<TT, 256>>>(xp, hh, hl, ln1_g + l * EE, ln1_b + l * EE);
            // QKV: split-K=3 -> partials -> reduce
            gemm_mma<0,128,3><<<dim3(TT/128, QKVN/128, 3), 256, GSM128>>>(hh, hl,
                wqkvh + (size_t)l*QKVN*EE, wqkvl + (size_t)l*QKVN*EE,
                partp, nullptr, nullptr, nullptr, QKVN, EE);
            red3_k<<<(TT*QKVN)/256, 256>>>(qkvp, partp, TT*QKVN);
            rope_k<<<(TT * 20 * 16) / 256, 256>>>();
            attn_scores_k<<<dim3(TT/64, TT/64, NH), 256>>>();
            softmax_thresh_k<<<dim3(TT, NH), 256>>>(gate, l);
            attn_av_k<<<dim3(TT/64, NH, 4), 256>>>();
            ysplit_k<<<(TT*EE)/256, 256>>>();
            // Wo: split-K=2 -> partials -> x += p0+p1
            gemm_mma<1,128,3><<<dim3(TT/128, EE/128, 2), 256, GSM128>>>(yh, yl,
                woh + (size_t)l*EE*EE, wol + (size_t)l*EE*EE,
                partp, nullptr, nullptr, nullptr, EE, EE);
            redadd2_k<<<(TT*EE)/256, 256>>>(xp, partp, TT*EE);
            layernorm_split_k<<<TT, 256>>>(xp, hh, hl, ln2_g + l * EE, ln2_b + l * EE);
            gemm_mma<2,256,2><<<dim3(TT/128, FF/256, 1), 256, GSM256>>>(hh, hl,
                w1h + (size_t)l*FF*EE, w1l + (size_t)l*FF*EE,
                nullptr, nullptr, ffh, ffl, FF, EE);
            // W2: split-K=2
            gemm_mma<1,128,3><<<dim3(TT/128, EE/128, 2), 256, GSM128>>>(ffh, ffl,
                w2h + (size_t)l*EE*FF, w2l + (size_t)l*EE*FF,
                partp, nullptr, nullptr, nullptr, EE, FF);
            redadd2_k<<<(TT*EE)/256, 256>>>(xp, partp, TT*EE);
        }
    }

    layernorm_split_k<<<TT, 256>>>(xp, hh, hl, lnf_g, lnf_b);
    gemm_mma<0,256,2><<<dim3(TT/128, VV/256, 1), 256, GSM256>>>(hh, hl, eh, el,
        logits_dst, nullptr, nullptr, nullptr, VV, EE);

    zero_loss_k<<<1, 1>>>();
    loss_rows_k<<<TT, 256>>>(logits_dst, tgt);
    if (loss_dst) loss_fin_k<<<1, 1>>>(loss_dst);
}

// round 7
// speedup vs baseline: 4.0914x; 1.1154x over previous
#include <cuda_runtime.h>
#include <cuda_bf16.h>
#include <math.h>
#include <stdint.h>

// ---------------- problem constants ----------------
#define TT 1024
#define EE 1024
#define VV 32000
#define NH 16
#define NKV 4
#define DHD 64
#define KVD (NKV*DHD)     // 256
#define QKVN 1536
#define LNUM 2
#define RNUM 2
#define FF 4096
#define EPSV 1e-5f

typedef __nv_bfloat16 bf16;

// ---------------- device scratch ----------------
__device__ float g_x[TT*EE];
__device__ bf16  g_hh[TT*EE], g_hl[TT*EE];
__device__ float g_att[(size_t)NH*TT*TT];
__device__ bf16  g_atth[(size_t)NH*TT*TT], g_attl[(size_t)NH*TT*TT];
__device__ float g_part[3*TT*QKVN];          // split-K partials (reused)
__device__ bf16  g_qh[NH*TT*DHD],  g_ql[NH*TT*DHD];
__device__ bf16  g_kh[NKV*TT*DHD], g_kl[NKV*TT*DHD];
__device__ bf16  g_vth[NKV*DHD*TT], g_vtl[NKV*DHD*TT];   // transposed V
__device__ bf16  g_yh[TT*EE], g_yl[TT*EE];
__device__ bf16  g_ffh[TT*FF], g_ffl[TT*FF];
__device__ bf16  g_wqkv_h[LNUM*QKVN*EE], g_wqkv_l[LNUM*QKVN*EE];
__device__ bf16  g_wo_h[LNUM*EE*EE],     g_wo_l[LNUM*EE*EE];
__device__ bf16  g_w1_h[LNUM*FF*EE],     g_w1_l[LNUM*FF*EE];
__device__ bf16  g_w2_h[LNUM*EE*FF],     g_w2_l[LNUM*EE*FF];
__device__ bf16  g_eh[(size_t)VV*EE],    g_el[(size_t)VV*EE];
__device__ float g_logits[(size_t)TT*VV];
__device__ float g_loss;

// ---------------- generic helpers ----------------
__device__ __forceinline__ float blk_sum256(float v, float* sh) {
    int tid = threadIdx.x;
    sh[tid] = v; __syncthreads();
    #pragma unroll
    for (int s = 128; s > 0; s >>= 1) { if (tid < s) sh[tid] += sh[tid + s]; __syncthreads(); }
    float r = sh[0]; __syncthreads();
    return r;
}
__device__ __forceinline__ float blk_max256(float v, float* sh) {
    int tid = threadIdx.x;
    sh[tid] = v; __syncthreads();
    #pragma unroll
    for (int s = 128; s > 0; s >>= 1) { if (tid < s) sh[tid] = fmaxf(sh[tid], sh[tid + s]); __syncthreads(); }
    float r = sh[0]; __syncthreads();
    return r;
}
__device__ __forceinline__ float gelu_exact(float x) {
    return 0.5f * x * (1.0f + erff(x * 0.7071067811865476f));
}
__device__ __forceinline__ void split_bf16(float v, bf16& h, bf16& l) {
    h = __float2bfloat16(v);
    l = __float2bfloat16(v - __bfloat162float(h));
}

// ---------------- PTX wrappers ----------------
__device__ __forceinline__ void mma_bf16(float* d, const uint32_t* a, const uint32_t* b) {
    asm volatile("mma.sync.aligned.m16n8k16.row.col.f32.bf16.bf16.f32 "
        "{%0,%1,%2,%3}, {%4,%5,%6,%7}, {%8,%9}, {%0,%1,%2,%3};"
        : "+f"(d[0]), "+f"(d[1]), "+f"(d[2]), "+f"(d[3])
        : "r"(a[0]), "r"(a[1]), "r"(a[2]), "r"(a[3]), "r"(b[0]), "r"(b[1]));
}
__device__ __forceinline__ void ldsm4(uint32_t* r, uint32_t addr) {
    asm volatile("ldmatrix.sync.aligned.m8n8.x4.shared.b16 {%0,%1,%2,%3}, [%4];"
        : "=r"(r[0]), "=r"(r[1]), "=r"(r[2]), "=r"(r[3]) : "r"(addr));
}
__device__ __forceinline__ void cp16(uint32_t s, const void* g) {
    asm volatile("cp.async.cg.shared.global [%0], [%1], 16;" :: "r"(s), "l"(g));
}
#define CP_COMMIT()  asm volatile("cp.async.commit_group;")
#define CP_WAIT(n)   asm volatile("cp.async.wait_group %0;" :: "n"(n))

// SW128 swizzle: 128B rows, 16B chunks, chunk ^= row&7  (conflict-free ldmatrix)
__device__ __forceinline__ uint32_t sw_off(int row, int chunk) {
    return (uint32_t)(row * 128 + ((chunk ^ (row & 7)) << 4));
}

// ---------------- split-bf16 HMMA GEMM (unchanged core) ----------------
template<int MODE, int TN, int NSTG>
__global__ __launch_bounds__(256, 1) void gemm_mma(
    const bf16* __restrict__ Ah, const bf16* __restrict__ Al,
    const bf16* __restrict__ Bh, const bf16* __restrict__ Bl,
    float* C, const float* Rs, bf16* Oh, bf16* Ol,
    int N, int K)
{
    constexpr int TSA = 128 * 128;
    constexpr int TSB = TN * 128;
    constexpr int SB  = 2 * TSA + 2 * TSB;
    constexpr int BCH = TN * 8;
    constexpr int TC  = 2048 + 2 * BCH;
    constexpr int NG  = TN / 64;
    constexpr int NF  = 2 * NG;

    extern __shared__ char dsm[];
    const int tid = threadIdx.x;
    const int lane = tid & 31, warp = tid >> 5;
    const int wm = warp & 1, wn = warp >> 1;
    const int row0 = blockIdx.x * 128, col0 = blockIdx.y * TN;
    const uint32_t sb = (uint32_t)__cvta_generic_to_shared(dsm);

    float acc[4][NF][4];
    #pragma unroll
    for (int i = 0; i < 4; i++)
        #pragma unroll
        for (int j = 0; j < NF; j++)
            #pragma unroll
            for (int r = 0; r < 4; r++) acc[i][j][r] = 0.f;

    auto load_stage = [&](int s) {
        int k0 = s * 64;
        uint32_t base = sb + (s % NSTG) * SB;
        #pragma unroll
        for (int ii = 0; ii < TC / 256; ii++) {
            int i = tid + ii * 256;
            const bf16* src;
            uint32_t toff;
            if (i < 2048) {
                int t = i >> 10, w = i & 1023;
                int r = w >> 3, c = w & 7;
                src = (t ? Al : Ah) + (size_t)(row0 + r) * K + k0 + c * 8;
                toff = t * TSA + sw_off(r, c);
            } else {
                int j = i - 2048;
                int t = j / BCH, w = j & (BCH - 1);
                int r = w >> 3, c = w & 7;
                src = (t ? Bl : Bh) + (size_t)(col0 + r) * K + k0 + c * 8;
                toff = 2 * TSA + t * TSB + sw_off(r, c);
            }
            cp16(base + toff, src);
        }
        CP_COMMIT();
    };

    const int Stot = K >> 6;
    const int SK = gridDim.z;
    const int Sc = (Stot + SK - 1) / SK;
    const int s0 = blockIdx.z * Sc;
    const int s1 = min(Stot, s0 + Sc);

    #pragma unroll
    for (int i = 0; i < NSTG; i++)
        if (s0 + i < s1) load_stage(s0 + i);

    const int lr = lane & 15, lcs = lane >> 4;

    for (int s = s0; s < s1; s++) {
        int ahead = s1 - 1 - s;
        int w = ahead < (NSTG - 1) ? ahead : (NSTG - 1);
        if (w == 2)      { CP_WAIT(2); }
        else if (w == 1) { CP_WAIT(1); }
        else             { CP_WAIT(0); }
        __syncthreads();
        uint32_t ab = sb + (s % NSTG) * SB;
        #pragma unroll
        for (int k16 = 0; k16 < 4; k16++) {
            const int cch = k16 * 2 + lcs;
            uint32_t ah[4][4], al[4][4];
            #pragma unroll
            for (int mf = 0; mf < 4; mf++) {
                int row = wm * 64 + mf * 16 + lr;
                uint32_t off = sw_off(row, cch);
                ldsm4(ah[mf], ab + off);
                ldsm4(al[mf], ab + TSA + off);
            }
            #pragma unroll
            for (int g = 0; g < NG; g++) {
                int row = wn * (TN / 4) + g * 16 + lr;
                uint32_t off = sw_off(row, cch);
                uint32_t rh[4], rl[4];
                ldsm4(rh, ab + 2 * TSA + off);
                ldsm4(rl, ab + 2 * TSA + TSB + off);
                uint32_t b0h[2] = {rh[0], rh[2]}, b1h[2] = {rh[1], rh[3]};
                uint32_t b0l[2] = {rl[0], rl[2]}, b1l[2] = {rl[1], rl[3]};
                #pragma unroll
                for (int mf = 0; mf < 4; mf++) {
                    mma_bf16(acc[mf][g*2], ah[mf], b0h);
                    mma_bf16(acc[mf][g*2], ah[mf], b0l);
                    mma_bf16(acc[mf][g*2], al[mf], b0h);
                    mma_bf16(acc[mf][g*2+1], ah[mf], b1h);
                    mma_bf16(acc[mf][g*2+1], ah[mf], b1l);
                    mma_bf16(acc[mf][g*2+1], al[mf], b1h);
                }
            }
        }
        __syncthreads();
        if (s + NSTG < s1) load_stage(s + NSTG);
    }

    const size_t pstride = (size_t)gridDim.x * 128 * N;
    float* Cp = C + (size_t)blockIdx.z * pstride;
    #pragma unroll
    for (int mf = 0; mf < 4; mf++)
        #pragma unroll
        for (int nf = 0; nf < NF; nf++) {
            int r = row0 + wm * 64 + mf * 16 + (lane >> 2);
            int c = col0 + wn * (TN / 4) + nf * 8 + (lane & 3) * 2;
            float* d = acc[mf][nf];
            if (gridDim.z > 1) {
                *(float2*)(Cp + (size_t)r * N + c)       = make_float2(d[0], d[1]);
                *(float2*)(Cp + (size_t)(r + 8) * N + c) = make_float2(d[2], d[3]);
            } else if (MODE == 0) {
                *(float2*)(C + (size_t)r * N + c)       = make_float2(d[0], d[1]);
                *(float2*)(C + (size_t)(r + 8) * N + c) = make_float2(d[2], d[3]);
            } else {
                float v0 = gelu_exact(d[0]), v1 = gelu_exact(d[1]);
                float v2 = gelu_exact(d[2]), v3 = gelu_exact(d[3]);
                bf16 h0, l0, h1, l1, h2, l2, h3, l3;
                split_bf16(v0, h0, l0); split_bf16(v1, h1, l1);
                split_bf16(v2, h2, l2); split_bf16(v3, h3, l3);
                *(__nv_bfloat162*)(Oh + (size_t)r * N + c)       = __halves2bfloat162(h0, h1);
                *(__nv_bfloat162*)(Ol + (size_t)r * N + c)       = __halves2bfloat162(l0, l1);
                *(__nv_bfloat162*)(Oh + (size_t)(r + 8) * N + c) = __halves2bfloat162(h2, h3);
                *(__nv_bfloat162*)(Ol + (size_t)(r + 8) * N + c) = __halves2bfloat162(l2, l3);
            }
        }
}

#define GSM128 (3 * (2*128*128 + 2*128*128))   // 196608
#define GSM256 (2 * (2*128*128 + 2*256*128))   // 196608

// ---------------- fused QKV reduce + RoPE + split (q & k heads) ----------------
__global__ void rope_split_qk(const float* __restrict__ part) {
    __shared__ float tile[64][64];
    int ttile = blockIdx.x, head = blockIdx.y;
    int tid = threadIdx.x;
    int cb = (head < NH) ? head * DHD : EE + (head - NH) * DHD;
    const int n = TT * QKVN;
    #pragma unroll
    for (int it = 0; it < 16; it++) {
        int i = tid + it * 256;
        int r = i >> 6, c = i & 63;
        size_t idx = (size_t)(ttile * 64 + r) * QKVN + cb + c;
        tile[r][c] = part[idx] + part[idx + n] + part[idx + 2 * (size_t)n];
    }
    __syncthreads();
    bf16 *dh, *dl; size_t off;
    if (head < NH) { dh = g_qh; dl = g_ql; off = (size_t)head * TT * DHD; }
    else           { dh = g_kh; dl = g_kl; off = (size_t)(head - NH) * TT * DHD; }
    #pragma unroll
    for (int it = 0; it < 16; it++) {
        int i = tid + it * 256;
        int r = i >> 6, d = i & 63;
        int t = ttile * 64 + r;
        float v;
        if (d < 32) {
            int j = d & 15;
            float theta = powf(10000.0f, -(float)j / 16.0f);
            float ang = (float)t * theta;
            float cs = cosf(ang), sn = sinf(ang);
            if (d < 16) v = tile[r][d] * cs - tile[r][d + 16] * sn;
            else        v = tile[r][d] * cs + tile[r][d - 16] * sn;
        } else v = tile[r][d];
        bf16 h, l; split_bf16(v, h, l);
        size_t o = off + (size_t)t * DHD + d;
        dh[o] = h; dl[o] = l;
    }
}

// ---------------- fused V reduce + transpose + split ----------------
__global__ void v_split_t(const float* __restrict__ part) {
    __shared__ float tile[64][65];
    int ttile = blockIdx.x, kh = blockIdx.y;
    int tid = threadIdx.x;
    int cb = EE + KVD + kh * DHD;
    const int n = TT * QKVN;
    #pragma unroll
    for (int it = 0; it < 16; it++) {
        int i = tid + it * 256;
        int r = i >> 6, c = i & 63;
        size_t idx = (size_t)(ttile * 64 + r) * QKVN + cb + c;
        tile[r][c] = part[idx] + part[idx + n] + part[idx + 2 * (size_t)n];
    }
    __syncthreads();
    #pragma unroll
    for (int it = 0; it < 16; it++) {
        int i = tid + it * 256;
        int d = i >> 6, tc = i & 63;
        float v = tile[tc][d];
        bf16 h, l; split_bf16(v, h, l);
        size_t o = ((size_t)kh * DHD + d) * TT + ttile * 64 + tc;
        g_vth[o] = h; g_vtl[o] = l;
    }
}

// ---------------- HMMA attention scores: 64(t) x 128(s), K=64 ----------------
#define SCSM 49152
__global__ __launch_bounds__(256) void scores_mma() {
    int st = blockIdx.x, tt = blockIdx.y, h = blockIdx.z;
    if (2 * st > tt) return;
    int khid = h >> 2;
    extern __shared__ char dsm[];
    const uint32_t sb = (uint32_t)__cvta_generic_to_shared(dsm);
    const int tid = threadIdx.x;
    const int lane = tid & 31, warp = tid >> 5;

    #pragma unroll
    for (int it = 0; it < 12; it++) {
        int i = tid + it * 256;
        const bf16* src; uint32_t dst;
        if (i < 1024) {
            int sub = i >> 9, w = i & 511, r = w >> 3, c = w & 7;
            src = (sub ? g_ql : g_qh) + ((size_t)h * TT + tt * 64 + r) * DHD + c * 8;
            dst = sub * 8192 + sw_off(r, c);
        } else {
            int j = i - 1024;
            int sub = j >> 10, w = j & 1023, r = w >> 3, c = w & 7;
            src = (sub ? g_kl : g_kh) + ((size_t)khid * TT + st * 128 + r) * DHD + c * 8;
            dst = 16384 + sub * 16384 + sw_off(r, c);
        }
        cp16(sb + dst, src);
    }
    CP_COMMIT(); CP_WAIT(0);
    __syncthreads();

    const int wm = warp & 1, wn = warp >> 1;
    const int lr = lane & 15, lcs = lane >> 4;
    float acc[2][4][4];
    #pragma unroll
    for (int a = 0; a < 2; a++)
        #pragma unroll
        for (int b = 0; b < 4; b++)
            #pragma unroll
            for (int c = 0; c < 4; c++) acc[a][b][c] = 0.f;

    #pragma unroll
    for (int k16 = 0; k16 < 4; k16++) {
        const int cch = k16 * 2 + lcs;
        uint32_t ah[2][4], al[2][4];
        #pragma unroll
        for (int mf = 0; mf < 2; mf++) {
            int row = wm * 32 + mf * 16 + lr;
            uint32_t off = sw_off(row, cch);
            ldsm4(ah[mf], sb + off);
            ldsm4(al[mf], sb + 8192 + off);
        }
        #pragma unroll
        for (int g = 0; g < 2; g++) {
            int row = wn * 32 + g * 16 + lr;
            uint32_t off = sw_off(row, cch);
            uint32_t rh[4], rl[4];
            ldsm4(rh, sb + 16384 + off);
            ldsm4(rl, sb + 32768 + off);
            uint32_t b0h[2] = {rh[0], rh[2]}, b1h[2] = {rh[1], rh[3]};
            uint32_t b0l[2] = {rl[0], rl[2]}, b1l[2] = {rl[1], rl[3]};
            #pragma unroll
            for (int mf = 0; mf < 2; mf++) {
                mma_bf16(acc[mf][g*2], ah[mf], b0h);
                mma_bf16(acc[mf][g*2], ah[mf], b0l);
                mma_bf16(acc[mf][g*2], al[mf], b0h);
                mma_bf16(acc[mf][g*2+1], ah[mf], b1h);
                mma_bf16(acc[mf][g*2+1], ah[mf], b1l);
                mma_bf16(acc[mf][g*2+1], al[mf], b1h);
            }
        }
    }
    float* o = g_att + (size_t)h * TT * TT;
    #pragma unroll
    for (int mf = 0; mf < 2; mf++)
        #pragma unroll
        for (int nf = 0; nf < 4; nf++) {
            int r = tt * 64 + wm * 32 + mf * 16 + (lane >> 2);
            int c = st * 128 + wn * 32 + nf * 8 + (lane & 3) * 2;
            float* d = acc[mf][nf];
            *(float2*)(o + (size_t)r * TT + c)       = make_float2(d[0]*0.125f, d[1]*0.125f);
            *(float2*)(o + (size_t)(r + 8) * TT + c) = make_float2(d[2]*0.125f, d[3]*0.125f);
        }
}

// ---------------- single-pass softmax + gate, writes split-bf16 att ----------------
__global__ void softmax_thresh_k(const float* __restrict__ gate_all, int l) {
    __shared__ float sh[256];
    int t = blockIdx.x, h = blockIdx.y;
    int tid = threadIdx.x;
    const float* p = g_att + (size_t)h * TT * TT + (size_t)t * TT;
    float thr = 1.0f / (1.0f + expf(-gate_all[l * NH + h]));
    float x[4];
    #pragma unroll
    for (int k = 0; k < 4; k++) {
        int i = k * 256 + tid;
        x[k] = (i <= t) ? p[i] : -1e30f;
    }
    float m = fmaxf(fmaxf(x[0], x[1]), fmaxf(x[2], x[3]));
    m = blk_max256(m, sh);
    float e[4], s = 0.f;
    #pragma unroll
    for (int k = 0; k < 4; k++) {
        int i = k * 256 + tid;
        e[k] = (i <= t) ? expf(x[k] - m) : 0.f;
        s += e[k];
    }
    s = blk_sum256(s, sh);
    float inv = 1.0f / s;
    int kend = ((t >> 6) + 1) << 6;
    size_t base = (size_t)h * TT * TT + (size_t)t * TT;
    #pragma unroll
    for (int k = 0; k < 4; k++) {
        int i = k * 256 + tid;
        if (i < kend) {
            float pv = e[k] * inv;
            pv = (pv >= thr) ? pv : 0.f;
            bf16 hh2, ll2; split_bf16(pv, hh2, ll2);
            g_atth[base + i] = hh2;
            g_attl[base + i] = ll2;
        }
    }
}

// ---------------- HMMA AV: 64(t) x 64(d), K-loop over s ----------------
#define AVSM 65536
__global__ __launch_bounds__(256) void av_mma() {
    int tt = blockIdx.x, h = blockIdx.y;
    int khid = h >> 2;
    int St = tt + 1;
    extern __shared__ char dsm[];
    const uint32_t sb = (uint32_t)__cvta_generic_to_shared(dsm);
    const int tid = threadIdx.x;
    const int lane = tid & 31, warp = tid >> 5;
    const int wm = warp & 1, wn = warp >> 1;
    const int lr = lane & 15, lcs = lane >> 4;

    auto load = [&](int s) {
        uint32_t base = sb + (s & 1) * 32768;
        #pragma unroll
        for (int it = 0; it < 8; it++) {
            int i = tid + it * 256;
            const bf16* src; uint32_t dst;
            if (i < 1024) {
                int sub = i >> 9, w = i & 511, r = w >> 3, c = w & 7;
                src = (sub ? g_attl : g_atth) + ((size_t)h * TT + tt * 64 + r) * TT + s * 64 + c * 8;
                dst = base + sub * 8192 + sw_off(r, c);
            } else {
                int j = i - 1024;
                int sub = j >> 9, w = j & 511, r = w >> 3, c = w & 7;
                src = (sub ? g_vtl : g_vth) + ((size_t)khid * DHD + r) * TT + s * 64 + c * 8;
                dst = base + 16384 + sub * 8192 + sw_off(r, c);
            }
            cp16(dst, src);
        }
        CP_COMMIT();
    };

    load(0);
    if (St > 1) load(1);

    float acc[2][2][4];
    #pragma unroll
    for (int a = 0; a < 2; a++)
        #pragma unroll
        for (int b = 0; b < 2; b++)
            #pragma unroll
            for (int c = 0; c < 4; c++) acc[a][b][c] = 0.f;

    for (int s = 0; s < St; s++) {
        if (s + 1 < St) { CP_WAIT(1); } else { CP_WAIT(0); }
        __syncthreads();
        uint32_t base = sb + (s & 1) * 32768;
        #pragma unroll
        for (int k16 = 0; k16 < 4; k16++) {
            const int cch = k16 * 2 + lcs;
            uint32_t ah[2][4], al[2][4];
            #pragma unroll
            for (int mf = 0; mf < 2; mf++) {
                int row = wm * 32 + mf * 16 + lr;
                uint32_t off = sw_off(row, cch);
                ldsm4(ah[mf], base + off);
                ldsm4(al[mf], base + 8192 + off);
            }
            int row = wn * 16 + lr;
            uint32_t off = sw_off(row, cch);
            uint32_t rh[4], rl[4];
            ldsm4(rh, base + 16384 + off);
            ldsm4(rl, base + 24576 + off);
            uint32_t b0h[2] = {rh[0], rh[2]}, b1h[2] = {rh[1], rh[3]};
            uint32_t b0l[2] = {rl[0], rl[2]}, b1l[2] = {rl[1], rl[3]};
            #pragma unroll
            for (int mf = 0; mf < 2; mf++) {
                mma_bf16(acc[mf][0], ah[mf], b0h);
                mma_bf16(acc[mf][0], ah[mf], b0l);
                mma_bf16(acc[mf][0], al[mf], b0h);
                mma_bf16(acc[mf][1], ah[mf], b1h);
                mma_bf16(acc[mf][1], ah[mf], b1l);
                mma_bf16(acc[mf][1], al[mf], b1h);
            }
        }
        __syncthreads();
        if (s + 2 < St) load(s + 2);
    }

    #pragma unroll
    for (int mf = 0; mf < 2; mf++)
        #pragma unroll
        for (int nf = 0; nf < 2; nf++) {
            int r = tt * 64 + wm * 32 + mf * 16 + (lane >> 2);
            int c = h * DHD + wn * 16 + nf * 8 + (lane & 3) * 2;
            float* d = acc[mf][nf];
            bf16 h0, l0, h1, l1, h2, l2, h3, l3;
            split_bf16(d[0], h0, l0); split_bf16(d[1], h1, l1);
            split_bf16(d[2], h2, l2); split_bf16(d[3], h3, l3);
            *(__nv_bfloat162*)(g_yh + (size_t)r * EE + c)       = __halves2bfloat162(h0, h1);
            *(__nv_bfloat162*)(g_yl + (size_t)r * EE + c)       = __halves2bfloat162(l0, l1);
            *(__nv_bfloat162*)(g_yh + (size_t)(r + 8) * EE + c) = __halves2bfloat162(h2, h3);
            *(__nv_bfloat162*)(g_yl + (size_t)(r + 8) * EE + c) = __halves2bfloat162(l2, l3);
        }
}

// ---------------- fused residual-add + layernorm + split ----------------
__global__ void add_ln_split_k(float* __restrict__ x, const float* __restrict__ p,
                               const float* __restrict__ g, const float* __restrict__ b,
                               bf16* __restrict__ oh, bf16* __restrict__ ol) {
    __shared__ float sh[256];
    int row = blockIdx.x, tid = threadIdx.x;
    const int n = TT * EE;
    float v[4];
    #pragma unroll
    for (int k = 0; k < 4; k++) {
        int i = row * EE + k * 256 + tid;
        v[k] = x[i] + p[i] + p[i + n];
        x[i] = v[k];
    }
    float mu = blk_sum256(v[0] + v[1] + v[2] + v[3], sh) * (1.0f / EE);
    float vs = 0.f;
    #pragma unroll
    for (int k = 0; k < 4; k++) { float d = v[k] - mu; vs += d * d; }
    float var = blk_sum256(vs, sh) * (1.0f / EE);
    float inv = rsqrtf(var + EPSV);
    #pragma unroll
    for (int k = 0; k < 4; k++) {
        int c = k * 256 + tid;
        float o = (v[k] - mu) * inv * g[c] + b[c];
        bf16 h, l; split_bf16(o, h, l);
        oh[row * EE + c] = h;
        ol[row * EE + c] = l;
    }
}

// ---------------- plain layernorm + split (first LN only) ----------------
__global__ void layernorm_split_k(const float* __restrict__ in, bf16* __restrict__ oh,
                                  bf16* __restrict__ ol,
                                  const float* __restrict__ g, const float* __restrict__ b) {
    __shared__ float sh[256];
    int row = blockIdx.x;
    const float* x = in + (size_t)row * EE;
    float s = 0.f;
    for (int i = threadIdx.x; i < EE; i += 256) s += x[i];
    float mu = blk_sum256(s, sh) * (1.0f / EE);
    float vs = 0.f;
    for (int i = threadIdx.x; i < EE; i += 256) { float d = x[i] - mu; vs += d * d; }
    float var = blk_sum256(vs, sh) * (1.0f / EE);
    float inv = rsqrtf(var + EPSV);
    for (int i = threadIdx.x; i < EE; i += 256) {
        float v = (x[i] - mu) * inv * g[i] + b[i];
        bf16 h, l; split_bf16(v, h, l);
        oh[(size_t)row * EE + i] = h;
        ol[(size_t)row * EE + i] = l;
    }
}

// ---------------- weight transpose + split ----------------
__global__ void wtsplit_k(const float* __restrict__ W, bf16* __restrict__ Th,
                          bf16* __restrict__ Tl, int K, int N, int ldt) {
    __shared__ float t[32][33];
    int n0 = blockIdx.x * 32, k0 = blockIdx.y * 32;
    int tx = threadIdx.x, ty = threadIdx.y;
    #pragma unroll
    for (int r = ty; r < 32; r += 8)
        t[r][tx] = W[(size_t)(k0 + r) * N + n0 + tx];
    __syncthreads();
    #pragma unroll
    for (int r = ty; r < 32; r += 8) {
        float v = t[tx][r];
        bf16 h, l; split_bf16(v, h, l);
        Th[(size_t)(n0 + r) * ldt + k0 + tx] = h;
        Tl[(size_t)(n0 + r) * ldt + k0 + tx] = l;
    }
}

// ---------------- embed split ----------------
__global__ void esplit_k(const float* __restrict__ E, bf16* __restrict__ Eh, bf16* __restrict__ El) {
    size_t i = ((size_t)blockIdx.x * 256 + threadIdx.x) * 4;
    float4 v = *(const float4*)(E + i);
    bf16 h0,l0,h1,l1,h2,l2,h3,l3;
    split_bf16(v.x,h0,l0); split_bf16(v.y,h1,l1); split_bf16(v.z,h2,l2); split_bf16(v.w,h3,l3);
    *(__nv_bfloat162*)(Eh + i)     = __halves2bfloat162(h0, h1);
    *(__nv_bfloat162*)(Eh + i + 2) = __halves2bfloat162(h2, h3);
    *(__nv_bfloat162*)(El + i)     = __halves2bfloat162(l0, l1);
    *(__nv_bfloat162*)(El + i + 2) = __halves2bfloat162(l2, l3);
}

// ---------------- embedding gather ----------------
__global__ void gather_embed_k(const float* __restrict__ embed, const int* __restrict__ idx) {
    int i = blockIdx.x * blockDim.x + threadIdx.x;
    int t = i >> 10, e = i & 1023;
    g_x[i] = embed[(size_t)idx[t] * EE + e];
}

// ---------------- loss ----------------
__global__ void zero_loss_k() { g_loss = 0.f; }

__global__ void loss_rows_k(const float* __restrict__ logits, const int* __restrict__ targets) {
    __shared__ float sh[256];
    int t = blockIdx.x;
    const float* row = logits + (size_t)t * VV;
    float m = -1e30f;
    for (int i = threadIdx.x; i < VV; i += 256) m = fmaxf(m, row[i]);
    m = blk_max256(m, sh);
    float s = 0.f;
    for (int i = threadIdx.x; i < VV; i += 256) s += expf(row[i] - m);
    s = blk_sum256(s, sh);
    if (threadIdx.x == 0) {
        float lp = row[targets[t]] - m - logf(s);
        atomicAdd(&g_loss, -lp);
    }
}

__global__ void loss_fin_k(float* dst) { *dst = g_loss * (1.0f / (float)TT); }

// ---------------- host orchestration ----------------
extern "C" void kernel_launch(void* const* d_in, const int* in_sizes, int n_in,
                              void* d_out, int out_size) {
    const float* embed = (const float*)d_in[0];
    const float* ln1_g = (const float*)d_in[1];
    const float* ln1_b = (const float*)d_in[2];
    const float* Wq    = (const float*)d_in[3];
    const float* Wk    = (const float*)d_in[4];
    const float* Wv    = (const float*)d_in[5];
    const float* Wo    = (const float*)d_in[6];
    const float* gate  = (const float*)d_in[7];
    const float* ln2_g = (const float*)d_in[8];
    const float* ln2_b = (const float*)d_in[9];
    const float* W1    = (const float*)d_in[10];
    const float* W2    = (const float*)d_in[11];
    const float* lnf_g = (const float*)d_in[12];
    const float* lnf_b = (const float*)d_in[13];
    const int*   idx   = (const int*)d_in[14];
    const int*   tgt   = (const int*)d_in[15];

    float *xp, *logp, *partp;
    bf16 *hh, *hl, *yh, *yl, *ffh, *ffl;
    bf16 *wqkvh, *wqkvl, *woh, *wol, *w1h, *w1l, *w2h, *w2l, *eh, *el;
    cudaGetSymbolAddress((void**)&xp,    g_x);
    cudaGetSymbolAddress((void**)&logp,  g_logits);
    cudaGetSymbolAddress((void**)&partp, g_part);
    cudaGetSymbolAddress((void**)&hh,    g_hh);
    cudaGetSymbolAddress((void**)&hl,    g_hl);
    cudaGetSymbolAddress((void**)&yh,    g_yh);
    cudaGetSymbolAddress((void**)&yl,    g_yl);
    cudaGetSymbolAddress((void**)&ffh,   g_ffh);
    cudaGetSymbolAddress((void**)&ffl,   g_ffl);
    cudaGetSymbolAddress((void**)&wqkvh, g_wqkv_h);
    cudaGetSymbolAddress((void**)&wqkvl, g_wqkv_l);
    cudaGetSymbolAddress((void**)&woh,   g_wo_h);
    cudaGetSymbolAddress((void**)&wol,   g_wo_l);
    cudaGetSymbolAddress((void**)&w1h,   g_w1_h);
    cudaGetSymbolAddress((void**)&w1l,   g_w1_l);
    cudaGetSymbolAddress((void**)&w2h,   g_w2_h);
    cudaGetSymbolAddress((void**)&w2l,   g_w2_l);
    cudaGetSymbolAddress((void**)&eh,    g_eh);
    cudaGetSymbolAddress((void**)&el,    g_el);

    cudaFuncSetAttribute(gemm_mma<0,128,3>, cudaFuncAttributeMaxDynamicSharedMemorySize, GSM128);
    cudaFuncSetAttribute(gemm_mma<0,256,2>, cudaFuncAttributeMaxDynamicSharedMemorySize, GSM256);
    cudaFuncSetAttribute(gemm_mma<2,256,2>, cudaFuncAttributeMaxDynamicSharedMemorySize, GSM256);
    cudaFuncSetAttribute(scores_mma, cudaFuncAttributeMaxDynamicSharedMemorySize, SCSM);
    cudaFuncSetAttribute(av_mma, cudaFuncAttributeMaxDynamicSharedMemorySize, AVSM);

    const size_t BTV = (size_t)TT * VV;
    float* logits_dst = ((size_t)out_size >= BTV) ? (float*)d_out : logp;
    float* loss_dst = nullptr;
    if ((size_t)out_size > BTV)      loss_dst = (float*)d_out + BTV;
    else if ((size_t)out_size < BTV) loss_dst = (float*)d_out;

    dim3 tb(32, 8);
    for (int l = 0; l < LNUM; l++) {
        wtsplit_k<<<dim3(EE/32, EE/32), tb>>>(Wq + (size_t)l*EE*EE,
            wqkvh + (size_t)l*QKVN*EE, wqkvl + (size_t)l*QKVN*EE, EE, EE, EE);
        wtsplit_k<<<dim3(KVD/32, EE/32), tb>>>(Wk + (size_t)l*EE*KVD,
            wqkvh + (size_t)l*QKVN*EE + (size_t)EE*EE, wqkvl + (size_t)l*QKVN*EE + (size_t)EE*EE, EE, KVD, EE);
        wtsplit_k<<<dim3(KVD/32, EE/32), tb>>>(Wv + (size_t)l*EE*KVD,
            wqkvh + (size_t)l*QKVN*EE + (size_t)(EE+KVD)*EE, wqkvl + (size_t)l*QKVN*EE + (size_t)(EE+KVD)*EE, EE, KVD, EE);
        wtsplit_k<<<dim3(EE/32, EE/32), tb>>>(Wo + (size_t)l*EE*EE,
            woh + (size_t)l*EE*EE, wol + (size_t)l*EE*EE, EE, EE, EE);
        wtsplit_k<<<dim3(FF/32, EE/32), tb>>>(W1 + (size_t)l*EE*FF,
            w1h + (size_t)l*FF*EE, w1l + (size_t)l*FF*EE, EE, FF, EE);
        wtsplit_k<<<dim3(EE/32, FF/32), tb>>>(W2 + (size_t)l*FF*EE,
            w2h + (size_t)l*EE*FF, w2l + (size_t)l*EE*FF, FF, EE, FF);
    }
    esplit_k<<<(int)(((size_t)VV*EE)/1024), 256>>>(embed, eh, el);

    gather_embed_k<<<(TT * EE) / 256, 256>>>(embed, idx);
    // first LN1
    layernorm_split_k<<<TT, 256>>>(xp, hh, hl, ln1_g, ln1_b);

    for (int it = 0; it < RNUM * LNUM; it++) {
        int l = it % LNUM;
        // QKV: split-K=3 -> partials
        gemm_mma<0,128,3><<<dim3(TT/128, QKVN/128, 3), 256, GSM128>>>(hh, hl,
            wqkvh + (size_t)l*QKVN*EE, wqkvl + (size_t)l*QKVN*EE,
            partp, nullptr, nullptr, nullptr, QKVN, EE);
        rope_split_qk<<<dim3(TT/64, NH + NKV), 256>>>(partp);
        v_split_t<<<dim3(TT/64, NKV), 256>>>(partp);
        scores_mma<<<dim3(TT/128, TT/64, NH), 256, SCSM>>>();
        softmax_thresh_k<<<dim3(TT, NH), 256>>>(gate, l);
        av_mma<<<dim3(TT/64, NH), 256, AVSM>>>();
        // Wo: split-K=2 -> partials; fused x+= & LN2
        gemm_mma<0,128,3><<<dim3(TT/128, EE/128, 2), 256, GSM128>>>(yh, yl,
            woh + (size_t)l*EE*EE, wol + (size_t)l*EE*EE,
            partp, nullptr, nullptr, nullptr, EE, EE);
        add_ln_split_k<<<TT, 256>>>(xp, partp, ln2_g + l * EE, ln2_b + l * EE, hh, hl);
        // FFN
        gemm_mma<2,256,2><<<dim3(TT/128, FF/256, 1), 256, GSM256>>>(hh, hl,
            w1h + (size_t)l*FF*EE, w1l + (size_t)l*FF*EE,
            nullptr, nullptr, ffh, ffl, FF, EE);
        gemm_mma<0,128,3><<<dim3(TT/128, EE/128, 2), 256, GSM128>>>(ffh, ffl,
            w2h + (size_t)l*EE*FF, w2l + (size_t)l*EE*FF,
            partp, nullptr, nullptr, nullptr, EE, FF);
        // fused x+= & next LN (ln1 of next layer, or lnf at the end)
        const float *ng, *nb;
        if (it == RNUM * LNUM - 1) { ng = lnf_g; nb = lnf_b; }
        else { int ln = (l + 1) % LNUM; ng = ln1_g + ln * EE; nb = ln1_b + ln * EE; }
        add_ln_split_k<<<TT, 256>>>(xp, partp, ng, nb, hh, hl);
    }

    // logits
    gemm_mma<0,256,2><<<dim3(TT/128, VV/256, 1), 256, GSM256>>>(hh, hl, eh, el,
        logits_dst, nullptr, nullptr, nullptr, VV, EE);

    zero_loss_k<<<1, 1>>>();
    loss_rows_k<<<TT, 256>>>(logits_dst, tgt);
    if (loss_dst) loss_fin_k<<<1, 1>>>(loss_dst);
}

// round 8
// speedup vs baseline: 4.1228x; 1.0077x over previous
#include <cuda_runtime.h>
#include <cuda_bf16.h>
#include <math.h>
#include <stdint.h>

// ---------------- problem constants ----------------
#define TT 1024
#define EE 1024
#define VV 32000
#define NH 16
#define NKV 4
#define DHD 64
#define KVD (NKV*DHD)     // 256
#define QKVN 1536
#define LNUM 2
#define RNUM 2
#define FF 4096
#define EPSV 1e-5f

typedef __nv_bfloat16 bf16;

// ---------------- device scratch ----------------
__device__ float g_x[TT*EE];
__device__ bf16  g_hh[TT*EE], g_hl[TT*EE];
__device__ float g_att[(size_t)NH*TT*TT];
__device__ bf16  g_atth[(size_t)NH*TT*TT], g_attl[(size_t)NH*TT*TT];
__device__ float g_part[3*TT*QKVN];          // split-K partials (reused)
__device__ bf16  g_qh[NH*TT*DHD],  g_ql[NH*TT*DHD];
__device__ bf16  g_kh[NKV*TT*DHD], g_kl[NKV*TT*DHD];
__device__ bf16  g_vth[NKV*DHD*TT], g_vtl[NKV*DHD*TT];   // transposed V
__device__ bf16  g_yh[TT*EE], g_yl[TT*EE];
__device__ bf16  g_ffh[TT*FF], g_ffl[TT*FF];
__device__ bf16  g_wqkv_h[LNUM*QKVN*EE], g_wqkv_l[LNUM*QKVN*EE];
__device__ bf16  g_wo_h[LNUM*EE*EE],     g_wo_l[LNUM*EE*EE];
__device__ bf16  g_w1_h[LNUM*FF*EE],     g_w1_l[LNUM*FF*EE];
__device__ bf16  g_w2_h[LNUM*EE*FF],     g_w2_l[LNUM*EE*FF];
__device__ bf16  g_eh[(size_t)VV*EE],    g_el[(size_t)VV*EE];
__device__ float g_logits[(size_t)TT*VV];
__device__ float g_loss;

// ---------------- generic helpers ----------------
__device__ __forceinline__ float blk_sum256(float v, float* sh) {
    int tid = threadIdx.x;
    sh[tid] = v; __syncthreads();
    #pragma unroll
    for (int s = 128; s > 0; s >>= 1) { if (tid < s) sh[tid] += sh[tid + s]; __syncthreads(); }
    float r = sh[0]; __syncthreads();
    return r;
}
__device__ __forceinline__ float blk_max256(float v, float* sh) {
    int tid = threadIdx.x;
    sh[tid] = v; __syncthreads();
    #pragma unroll
    for (int s = 128; s > 0; s >>= 1) { if (tid < s) sh[tid] = fmaxf(sh[tid], sh[tid + s]); __syncthreads(); }
    float r = sh[0]; __syncthreads();
    return r;
}
__device__ __forceinline__ float gelu_exact(float x) {
    return 0.5f * x * (1.0f + erff(x * 0.7071067811865476f));
}
__device__ __forceinline__ void split_bf16(float v, bf16& h, bf16& l) {
    h = __float2bfloat16(v);
    l = __float2bfloat16(v - __bfloat162float(h));
}

// ---------------- PTX wrappers ----------------
__device__ __forceinline__ void mma_bf16(float* d, const uint32_t* a, const uint32_t* b) {
    asm volatile("mma.sync.aligned.m16n8k16.row.col.f32.bf16.bf16.f32 "
        "{%0,%1,%2,%3}, {%4,%5,%6,%7}, {%8,%9}, {%0,%1,%2,%3};"
        : "+f"(d[0]), "+f"(d[1]), "+f"(d[2]), "+f"(d[3])
        : "r"(a[0]), "r"(a[1]), "r"(a[2]), "r"(a[3]), "r"(b[0]), "r"(b[1]));
}
__device__ __forceinline__ void ldsm4(uint32_t* r, uint32_t addr) {
    asm volatile("ldmatrix.sync.aligned.m8n8.x4.shared.b16 {%0,%1,%2,%3}, [%4];"
        : "=r"(r[0]), "=r"(r[1]), "=r"(r[2]), "=r"(r[3]) : "r"(addr));
}
__device__ __forceinline__ void cp16(uint32_t s, const void* g) {
    asm volatile("cp.async.cg.shared.global [%0], [%1], 16;" :: "r"(s), "l"(g));
}
#define CP_COMMIT()  asm volatile("cp.async.commit_group;")
#define CP_WAIT(n)   asm volatile("cp.async.wait_group %0;" :: "n"(n))

// SW128 swizzle: 128B rows, 16B chunks, chunk ^= row&7  (conflict-free ldmatrix)
__device__ __forceinline__ uint32_t sw_off(int row, int chunk) {
    return (uint32_t)(row * 128 + ((chunk ^ (row & 7)) << 4));
}

// ---------------- split-bf16 HMMA GEMM ----------------
template<int MODE, int TN, int NSTG>
__global__ __launch_bounds__(256, 1) void gemm_mma(
    const bf16* __restrict__ Ah, const bf16* __restrict__ Al,
    const bf16* __restrict__ Bh, const bf16* __restrict__ Bl,
    float* C, const float* Rs, bf16* Oh, bf16* Ol,
    int N, int K)
{
    constexpr int TSA = 128 * 128;
    constexpr int TSB = TN * 128;
    constexpr int SB  = 2 * TSA + 2 * TSB;
    constexpr int BCH = TN * 8;
    constexpr int TC  = 2048 + 2 * BCH;
    constexpr int NG  = TN / 64;
    constexpr int NF  = 2 * NG;

    extern __shared__ char dsm[];
    const int tid = threadIdx.x;
    const int lane = tid & 31, warp = tid >> 5;
    const int wm = warp & 1, wn = warp >> 1;
    const int row0 = blockIdx.x * 128, col0 = blockIdx.y * TN;
    const uint32_t sb = (uint32_t)__cvta_generic_to_shared(dsm);

    float acc[4][NF][4];
    #pragma unroll
    for (int i = 0; i < 4; i++)
        #pragma unroll
        for (int j = 0; j < NF; j++)
            #pragma unroll
            for (int r = 0; r < 4; r++) acc[i][j][r] = 0.f;

    auto load_stage = [&](int s) {
        int k0 = s * 64;
        uint32_t base = sb + (s % NSTG) * SB;
        #pragma unroll
        for (int ii = 0; ii < TC / 256; ii++) {
            int i = tid + ii * 256;
            const bf16* src;
            uint32_t toff;
            if (i < 2048) {
                int t = i >> 10, w = i & 1023;
                int r = w >> 3, c = w & 7;
                src = (t ? Al : Ah) + (size_t)(row0 + r) * K + k0 + c * 8;
                toff = t * TSA + sw_off(r, c);
            } else {
                int j = i - 2048;
                int t = j / BCH, w = j & (BCH - 1);
                int r = w >> 3, c = w & 7;
                src = (t ? Bl : Bh) + (size_t)(col0 + r) * K + k0 + c * 8;
                toff = 2 * TSA + t * TSB + sw_off(r, c);
            }
            cp16(base + toff, src);
        }
        CP_COMMIT();
    };

    const int Stot = K >> 6;
    const int SK = gridDim.z;
    const int Sc = (Stot + SK - 1) / SK;
    const int s0 = blockIdx.z * Sc;
    const int s1 = min(Stot, s0 + Sc);

    #pragma unroll
    for (int i = 0; i < NSTG; i++)
        if (s0 + i < s1) load_stage(s0 + i);

    const int lr = lane & 15, lcs = lane >> 4;

    for (int s = s0; s < s1; s++) {
        int ahead = s1 - 1 - s;
        int w = ahead < (NSTG - 1) ? ahead : (NSTG - 1);
        if (w == 2)      { CP_WAIT(2); }
        else if (w == 1) { CP_WAIT(1); }
        else             { CP_WAIT(0); }
        __syncthreads();
        uint32_t ab = sb + (s % NSTG) * SB;
        #pragma unroll
        for (int k16 = 0; k16 < 4; k16++) {
            const int cch = k16 * 2 + lcs;
            uint32_t ah[4][4], al[4][4];
            #pragma unroll
            for (int mf = 0; mf < 4; mf++) {
                int row = wm * 64 + mf * 16 + lr;
                uint32_t off = sw_off(row, cch);
                ldsm4(ah[mf], ab + off);
                ldsm4(al[mf], ab + TSA + off);
            }
            #pragma unroll
            for (int g = 0; g < NG; g++) {
                int row = wn * (TN / 4) + g * 16 + lr;
                uint32_t off = sw_off(row, cch);
                uint32_t rh[4], rl[4];
                ldsm4(rh, ab + 2 * TSA + off);
                ldsm4(rl, ab + 2 * TSA + TSB + off);
                uint32_t b0h[2] = {rh[0], rh[2]}, b1h[2] = {rh[1], rh[3]};
                uint32_t b0l[2] = {rl[0], rl[2]}, b1l[2] = {rl[1], rl[3]};
                #pragma unroll
                for (int mf = 0; mf < 4; mf++) {
                    mma_bf16(acc[mf][g*2], ah[mf], b0h);
                    mma_bf16(acc[mf][g*2], ah[mf], b0l);
                    mma_bf16(acc[mf][g*2], al[mf], b0h);
                    mma_bf16(acc[mf][g*2+1], ah[mf], b1h);
                    mma_bf16(acc[mf][g*2+1], ah[mf], b1l);
                    mma_bf16(acc[mf][g*2+1], al[mf], b1h);
                }
            }
        }
        __syncthreads();
        if (s + NSTG < s1) load_stage(s + NSTG);
    }

    const size_t pstride = (size_t)gridDim.x * 128 * N;
    float* Cp = C + (size_t)blockIdx.z * pstride;
    #pragma unroll
    for (int mf = 0; mf < 4; mf++)
        #pragma unroll
        for (int nf = 0; nf < NF; nf++) {
            int r = row0 + wm * 64 + mf * 16 + (lane >> 2);
            int c = col0 + wn * (TN / 4) + nf * 8 + (lane & 3) * 2;
            float* d = acc[mf][nf];
            if (gridDim.z > 1) {
                *(float2*)(Cp + (size_t)r * N + c)       = make_float2(d[0], d[1]);
                *(float2*)(Cp + (size_t)(r + 8) * N + c) = make_float2(d[2], d[3]);
            } else if (MODE == 0) {
                *(float2*)(C + (size_t)r * N + c)       = make_float2(d[0], d[1]);
                *(float2*)(C + (size_t)(r + 8) * N + c) = make_float2(d[2], d[3]);
            } else {
                float v0 = gelu_exact(d[0]), v1 = gelu_exact(d[1]);
                float v2 = gelu_exact(d[2]), v3 = gelu_exact(d[3]);
                bf16 h0, l0, h1, l1, h2, l2, h3, l3;
                split_bf16(v0, h0, l0); split_bf16(v1, h1, l1);
                split_bf16(v2, h2, l2); split_bf16(v3, h3, l3);
                *(__nv_bfloat162*)(Oh + (size_t)r * N + c)       = __halves2bfloat162(h0, h1);
                *(__nv_bfloat162*)(Ol + (size_t)r * N + c)       = __halves2bfloat162(l0, l1);
                *(__nv_bfloat162*)(Oh + (size_t)(r + 8) * N + c) = __halves2bfloat162(h2, h3);
                *(__nv_bfloat162*)(Ol + (size_t)(r + 8) * N + c) = __halves2bfloat162(l2, l3);
            }
        }
}

#define GSM128 (3 * (2*128*128 + 2*128*128))   // 196608
#define GSM256 (2 * (2*128*128 + 2*256*128))   // 196608

// ---------------- fused QKV reduce + RoPE/transpose + split ----------------
// blockIdx.y: 0..15 q heads (rope), 16..19 k heads (rope), 20..23 v heads (transpose)
__global__ void qkv_post_k(const float* __restrict__ part) {
    __shared__ float tile[64][65];
    int ttile = blockIdx.x, head = blockIdx.y;
    int tid = threadIdx.x;
    int cb;
    if (head < NH)            cb = head * DHD;
    else if (head < NH + NKV) cb = EE + (head - NH) * DHD;
    else                      cb = EE + KVD + (head - NH - NKV) * DHD;
    const int n = TT * QKVN;
    #pragma unroll
    for (int it = 0; it < 16; it++) {
        int i = tid + it * 256;
        int r = i >> 6, c = i & 63;
        size_t idx = (size_t)(ttile * 64 + r) * QKVN + cb + c;
        tile[r][c] = part[idx] + part[idx + n] + part[idx + 2 * (size_t)n];
    }
    __syncthreads();
    if (head < NH + NKV) {
        bf16 *dh, *dl; size_t off;
        if (head < NH) { dh = g_qh; dl = g_ql; off = (size_t)head * TT * DHD; }
        else           { dh = g_kh; dl = g_kl; off = (size_t)(head - NH) * TT * DHD; }
        #pragma unroll
        for (int it = 0; it < 16; it++) {
            int i = tid + it * 256;
            int r = i >> 6, d = i & 63;
            int t = ttile * 64 + r;
            float v;
            if (d < 32) {
                int j = d & 15;
                float theta = powf(10000.0f, -(float)j / 16.0f);
                float ang = (float)t * theta;
                float cs = cosf(ang), sn = sinf(ang);
                if (d < 16) v = tile[r][d] * cs - tile[r][d + 16] * sn;
                else        v = tile[r][d] * cs + tile[r][d - 16] * sn;
            } else v = tile[r][d];
            bf16 h, l; split_bf16(v, h, l);
            size_t o = off + (size_t)t * DHD + d;
            dh[o] = h; dl[o] = l;
        }
    } else {
        int kh = head - NH - NKV;
        #pragma unroll
        for (int it = 0; it < 16; it++) {
            int i = tid + it * 256;
            int d = i >> 6, tc = i & 63;
            float v = tile[tc][d];
            bf16 h, l; split_bf16(v, h, l);
            size_t o = ((size_t)kh * DHD + d) * TT + ttile * 64 + tc;
            g_vth[o] = h; g_vtl[o] = l;
        }
    }
}

// ---------------- HMMA attention scores: 64(t) x 128(s), K=64 ----------------
#define SCSM 49152
__global__ __launch_bounds__(256) void scores_mma() {
    int st = blockIdx.x, tt = blockIdx.y, h = blockIdx.z;
    if (2 * st > tt) return;
    int khid = h >> 2;
    extern __shared__ char dsm[];
    const uint32_t sb = (uint32_t)__cvta_generic_to_shared(dsm);
    const int tid = threadIdx.x;
    const int lane = tid & 31, warp = tid >> 5;

    #pragma unroll
    for (int it = 0; it < 12; it++) {
        int i = tid + it * 256;
        const bf16* src; uint32_t dst;
        if (i < 1024) {
            int sub = i >> 9, w = i & 511, r = w >> 3, c = w & 7;
            src = (sub ? g_ql : g_qh) + ((size_t)h * TT + tt * 64 + r) * DHD + c * 8;
            dst = sub * 8192 + sw_off(r, c);
        } else {
            int j = i - 1024;
            int sub = j >> 10, w = j & 1023, r = w >> 3, c = w & 7;
            src = (sub ? g_kl : g_kh) + ((size_t)khid * TT + st * 128 + r) * DHD + c * 8;
            dst = 16384 + sub * 16384 + sw_off(r, c);
        }
        cp16(sb + dst, src);
    }
    CP_COMMIT(); CP_WAIT(0);
    __syncthreads();

    const int wm = warp & 1, wn = warp >> 1;
    const int lr = lane & 15, lcs = lane >> 4;
    float acc[2][4][4];
    #pragma unroll
    for (int a = 0; a < 2; a++)
        #pragma unroll
        for (int b = 0; b < 4; b++)
            #pragma unroll
            for (int c = 0; c < 4; c++) acc[a][b][c] = 0.f;

    #pragma unroll
    for (int k16 = 0; k16 < 4; k16++) {
        const int cch = k16 * 2 + lcs;
        uint32_t ah[2][4], al[2][4];
        #pragma unroll
        for (int mf = 0; mf < 2; mf++) {
            int row = wm * 32 + mf * 16 + lr;
            uint32_t off = sw_off(row, cch);
            ldsm4(ah[mf], sb + off);
            ldsm4(al[mf], sb + 8192 + off);
        }
        #pragma unroll
        for (int g = 0; g < 2; g++) {
            int row = wn * 32 + g * 16 + lr;
            uint32_t off = sw_off(row, cch);
            uint32_t rh[4], rl[4];
            ldsm4(rh, sb + 16384 + off);
            ldsm4(rl, sb + 32768 + off);
            uint32_t b0h[2] = {rh[0], rh[2]}, b1h[2] = {rh[1], rh[3]};
            uint32_t b0l[2] = {rl[0], rl[2]}, b1l[2] = {rl[1], rl[3]};
            #pragma unroll
            for (int mf = 0; mf < 2; mf++) {
                mma_bf16(acc[mf][g*2], ah[mf], b0h);
                mma_bf16(acc[mf][g*2], ah[mf], b0l);
                mma_bf16(acc[mf][g*2], al[mf], b0h);
                mma_bf16(acc[mf][g*2+1], ah[mf], b1h);
                mma_bf16(acc[mf][g*2+1], ah[mf], b1l);
                mma_bf16(acc[mf][g*2+1], al[mf], b1h);
            }
        }
    }
    float* o = g_att + (size_t)h * TT * TT;
    #pragma unroll
    for (int mf = 0; mf < 2; mf++)
        #pragma unroll
        for (int nf = 0; nf < 4; nf++) {
            int r = tt * 64 + wm * 32 + mf * 16 + (lane >> 2);
            int c = st * 128 + wn * 32 + nf * 8 + (lane & 3) * 2;
            float* d = acc[mf][nf];
            *(float2*)(o + (size_t)r * TT + c)       = make_float2(d[0]*0.125f, d[1]*0.125f);
            *(float2*)(o + (size_t)(r + 8) * TT + c) = make_float2(d[2]*0.125f, d[3]*0.125f);
        }
}

// ---------------- single-pass softmax + gate, writes split-bf16 att ----------------
__global__ void softmax_thresh_k(const float* __restrict__ gate_all, int l) {
    __shared__ float sh[256];
    int t = blockIdx.x, h = blockIdx.y;
    int tid = threadIdx.x;
    const float* p = g_att + (size_t)h * TT * TT + (size_t)t * TT;
    float thr = 1.0f / (1.0f + expf(-gate_all[l * NH + h]));
    float x[4];
    #pragma unroll
    for (int k = 0; k < 4; k++) {
        int i = k * 256 + tid;
        x[k] = (i <= t) ? p[i] : -1e30f;
    }
    float m = fmaxf(fmaxf(x[0], x[1]), fmaxf(x[2], x[3]));
    m = blk_max256(m, sh);
    float e[4], s = 0.f;
    #pragma unroll
    for (int k = 0; k < 4; k++) {
        int i = k * 256 + tid;
        e[k] = (i <= t) ? expf(x[k] - m) : 0.f;
        s += e[k];
    }
    s = blk_sum256(s, sh);
    float inv = 1.0f / s;
    int kend = ((t >> 6) + 1) << 6;
    size_t base = (size_t)h * TT * TT + (size_t)t * TT;
    #pragma unroll
    for (int k = 0; k < 4; k++) {
        int i = k * 256 + tid;
        if (i < kend) {
            float pv = e[k] * inv;
            pv = (pv >= thr) ? pv : 0.f;
            bf16 hh2, ll2; split_bf16(pv, hh2, ll2);
            g_atth[base + i] = hh2;
            g_attl[base + i] = ll2;
        }
    }
}

// ---------------- HMMA AV: 64(t) x 64(d), K-loop over s ----------------
#define AVSM 65536
__global__ __launch_bounds__(256) void av_mma() {
    int tt = blockIdx.x, h = blockIdx.y;
    int khid = h >> 2;
    int St = tt + 1;
    extern __shared__ char dsm[];
    const uint32_t sb = (uint32_t)__cvta_generic_to_shared(dsm);
    const int tid = threadIdx.x;
    const int lane = tid & 31, warp = tid >> 5;
    const int wm = warp & 1, wn = warp >> 1;
    const int lr = lane & 15, lcs = lane >> 4;

    auto load = [&](int s) {
        uint32_t base = sb + (s & 1) * 32768;
        #pragma unroll
        for (int it = 0; it < 8; it++) {
            int i = tid + it * 256;
            const bf16* src; uint32_t dst;
            if (i < 1024) {
                int sub = i >> 9, w = i & 511, r = w >> 3, c = w & 7;
                src = (sub ? g_attl : g_atth) + ((size_t)h * TT + tt * 64 + r) * TT + s * 64 + c * 8;
                dst = base + sub * 8192 + sw_off(r, c);
            } else {
                int j = i - 1024;
                int sub = j >> 9, w = j & 511, r = w >> 3, c = w & 7;
                src = (sub ? g_vtl : g_vth) + ((size_t)khid * DHD + r) * TT + s * 64 + c * 8;
                dst = base + 16384 + sub * 8192 + sw_off(r, c);
            }
            cp16(dst, src);
        }
        CP_COMMIT();
    };

    load(0);
    if (St > 1) load(1);

    float acc[2][2][4];
    #pragma unroll
    for (int a = 0; a < 2; a++)
        #pragma unroll
        for (int b = 0; b < 2; b++)
            #pragma unroll
            for (int c = 0; c < 4; c++) acc[a][b][c] = 0.f;

    for (int s = 0; s < St; s++) {
        if (s + 1 < St) { CP_WAIT(1); } else { CP_WAIT(0); }
        __syncthreads();
        uint32_t base = sb + (s & 1) * 32768;
        #pragma unroll
        for (int k16 = 0; k16 < 4; k16++) {
            const int cch = k16 * 2 + lcs;
            uint32_t ah[2][4], al[2][4];
            #pragma unroll
            for (int mf = 0; mf < 2; mf++) {
                int row = wm * 32 + mf * 16 + lr;
                uint32_t off = sw_off(row, cch);
                ldsm4(ah[mf], base + off);
                ldsm4(al[mf], base + 8192 + off);
            }
            int row = wn * 16 + lr;
            uint32_t off = sw_off(row, cch);
            uint32_t rh[4], rl[4];
            ldsm4(rh, base + 16384 + off);
            ldsm4(rl, base + 24576 + off);
            uint32_t b0h[2] = {rh[0], rh[2]}, b1h[2] = {rh[1], rh[3]};
            uint32_t b0l[2] = {rl[0], rl[2]}, b1l[2] = {rl[1], rl[3]};
            #pragma unroll
            for (int mf = 0; mf < 2; mf++) {
                mma_bf16(acc[mf][0], ah[mf], b0h);
                mma_bf16(acc[mf][0], ah[mf], b0l);
                mma_bf16(acc[mf][0], al[mf], b0h);
                mma_bf16(acc[mf][1], ah[mf], b1h);
                mma_bf16(acc[mf][1], ah[mf], b1l);
                mma_bf16(acc[mf][1], al[mf], b1h);
            }
        }
        __syncthreads();
        if (s + 2 < St) load(s + 2);
    }

    #pragma unroll
    for (int mf = 0; mf < 2; mf++)
        #pragma unroll
        for (int nf = 0; nf < 2; nf++) {
            int r = tt * 64 + wm * 32 + mf * 16 + (lane >> 2);
            int c = h * DHD + wn * 16 + nf * 8 + (lane & 3) * 2;
            float* d = acc[mf][nf];
            bf16 h0, l0, h1, l1, h2, l2, h3, l3;
            split_bf16(d[0], h0, l0); split_bf16(d[1], h1, l1);
            split_bf16(d[2], h2, l2); split_bf16(d[3], h3, l3);
            *(__nv_bfloat162*)(g_yh + (size_t)r * EE + c)       = __halves2bfloat162(h0, h1);
            *(__nv_bfloat162*)(g_yl + (size_t)r * EE + c)       = __halves2bfloat162(l0, l1);
            *(__nv_bfloat162*)(g_yh + (size_t)(r + 8) * EE + c) = __halves2bfloat162(h2, h3);
            *(__nv_bfloat162*)(g_yl + (size_t)(r + 8) * EE + c) = __halves2bfloat162(l2, l3);
        }
}

// ---------------- fused residual-add + layernorm + split ----------------
__global__ void add_ln_split_k(float* __restrict__ x, const float* __restrict__ p,
                               const float* __restrict__ g, const float* __restrict__ b,
                               bf16* __restrict__ oh, bf16* __restrict__ ol) {
    __shared__ float sh[256];
    int row = blockIdx.x, tid = threadIdx.x;
    const int n = TT * EE;
    float v[4];
    #pragma unroll
    for (int k = 0; k < 4; k++) {
        int i = row * EE + k * 256 + tid;
        v[k] = x[i] + p[i] + p[i + n];
        x[i] = v[k];
    }
    float mu = blk_sum256(v[0] + v[1] + v[2] + v[3], sh) * (1.0f / EE);
    float vs = 0.f;
    #pragma unroll
    for (int k = 0; k < 4; k++) { float d = v[k] - mu; vs += d * d; }
    float var = blk_sum256(vs, sh) * (1.0f / EE);
    float inv = rsqrtf(var + EPSV);
    #pragma unroll
    for (int k = 0; k < 4; k++) {
        int c = k * 256 + tid;
        float o = (v[k] - mu) * inv * g[c] + b[c];
        bf16 h, l; split_bf16(o, h, l);
        oh[row * EE + c] = h;
        ol[row * EE + c] = l;
    }
}

// ---------------- plain layernorm + split (first LN only) ----------------
__global__ void layernorm_split_k(const float* __restrict__ in, bf16* __restrict__ oh,
                                  bf16* __restrict__ ol,
                                  const float* __restrict__ g, const float* __restrict__ b) {
    __shared__ float sh[256];
    int row = blockIdx.x;
    const float* x = in + (size_t)row * EE;
    float s = 0.f;
    for (int i = threadIdx.x; i < EE; i += 256) s += x[i];
    float mu = blk_sum256(s, sh) * (1.0f / EE);
    float vs = 0.f;
    for (int i = threadIdx.x; i < EE; i += 256) { float d = x[i] - mu; vs += d * d; }
    float var = blk_sum256(vs, sh) * (1.0f / EE);
    float inv = rsqrtf(var + EPSV);
    for (int i = threadIdx.x; i < EE; i += 256) {
        float v = (x[i] - mu) * inv * g[i] + b[i];
        bf16 h, l; split_bf16(v, h, l);
        oh[(size_t)row * EE + i] = h;
        ol[(size_t)row * EE + i] = l;
    }
}

// ---------------- weight transpose + split ----------------
__global__ void wtsplit_k(const float* __restrict__ W, bf16* __restrict__ Th,
                          bf16* __restrict__ Tl, int K, int N, int ldt) {
    __shared__ float t[32][33];
    int n0 = blockIdx.x * 32, k0 = blockIdx.y * 32;
    int tx = threadIdx.x, ty = threadIdx.y;
    #pragma unroll
    for (int r = ty; r < 32; r += 8)
        t[r][tx] = W[(size_t)(k0 + r) * N + n0 + tx];
    __syncthreads();
    #pragma unroll
    for (int r = ty; r < 32; r += 8) {
        float v = t[tx][r];
        bf16 h, l; split_bf16(v, h, l);
        Th[(size_t)(n0 + r) * ldt + k0 + tx] = h;
        Tl[(size_t)(n0 + r) * ldt + k0 + tx] = l;
    }
}

// ---------------- embed split ----------------
__global__ void esplit_k(const float* __restrict__ E, bf16* __restrict__ Eh, bf16* __restrict__ El) {
    size_t i = ((size_t)blockIdx.x * 256 + threadIdx.x) * 4;
    float4 v = *(const float4*)(E + i);
    bf16 h0,l0,h1,l1,h2,l2,h3,l3;
    split_bf16(v.x,h0,l0); split_bf16(v.y,h1,l1); split_bf16(v.z,h2,l2); split_bf16(v.w,h3,l3);
    *(__nv_bfloat162*)(Eh + i)     = __halves2bfloat162(h0, h1);
    *(__nv_bfloat162*)(Eh + i + 2) = __halves2bfloat162(h2, h3);
    *(__nv_bfloat162*)(El + i)     = __halves2bfloat162(l0, l1);
    *(__nv_bfloat162*)(El + i + 2) = __halves2bfloat162(l2, l3);
}

// ---------------- embedding gather ----------------
__global__ void gather_embed_k(const float* __restrict__ embed, const int* __restrict__ idx) {
    int i = blockIdx.x * blockDim.x + threadIdx.x;
    int t = i >> 10, e = i & 1023;
    g_x[i] = embed[(size_t)idx[t] * EE + e];
}

// ---------------- loss: single-pass online softmax ----------------
__global__ void zero_loss_k() { g_loss = 0.f; }

__global__ void loss_rows_k(const float* __restrict__ logits, const int* __restrict__ targets) {
    __shared__ float shm[256], shs[256];
    int t = blockIdx.x, tid = threadIdx.x;
    const float* row = logits + (size_t)t * VV;
    float m = -1e30f, s = 0.f;
    for (int i = tid; i < VV; i += 256) {
        float v = row[i];
        if (v > m) { s = s * expf(m - v) + 1.f; m = v; }
        else       { s += expf(v - m); }
    }
    shm[tid] = m; shs[tid] = s; __syncthreads();
    #pragma unroll
    for (int st = 128; st > 0; st >>= 1) {
        if (tid < st) {
            float m2 = shm[tid + st], s2 = shs[tid + st];
            float M = fmaxf(shm[tid], m2);
            shs[tid] = shs[tid] * expf(shm[tid] - M) + s2 * expf(m2 - M);
            shm[tid] = M;
        }
        __syncthreads();
    }
    if (tid == 0) {
        float lp = row[targets[t]] - shm[0] - logf(shs[0]);
        atomicAdd(&g_loss, -lp);
    }
}

__global__ void loss_fin_k(float* dst) { *dst = g_loss * (1.0f / (float)TT); }

// ---------------- host orchestration ----------------
extern "C" void kernel_launch(void* const* d_in, const int* in_sizes, int n_in,
                              void* d_out, int out_size) {
    const float* embed = (const float*)d_in[0];
    const float* ln1_g = (const float*)d_in[1];
    const float* ln1_b = (const float*)d_in[2];
    const float* Wq    = (const float*)d_in[3];
    const float* Wk    = (const float*)d_in[4];
    const float* Wv    = (const float*)d_in[5];
    const float* Wo    = (const float*)d_in[6];
    const float* gate  = (const float*)d_in[7];
    const float* ln2_g = (const float*)d_in[8];
    const float* ln2_b = (const float*)d_in[9];
    const float* W1    = (const float*)d_in[10];
    const float* W2    = (const float*)d_in[11];
    const float* lnf_g = (const float*)d_in[12];
    const float* lnf_b = (const float*)d_in[13];
    const int*   idx   = (const int*)d_in[14];
    const int*   tgt   = (const int*)d_in[15];

    float *xp, *logp, *partp;
    bf16 *hh, *hl, *yh, *yl, *ffh, *ffl;
    bf16 *wqkvh, *wqkvl, *woh, *wol, *w1h, *w1l, *w2h, *w2l, *eh, *el;
    cudaGetSymbolAddress((void**)&xp,    g_x);
    cudaGetSymbolAddress((void**)&logp,  g_logits);
    cudaGetSymbolAddress((void**)&partp, g_part);
    cudaGetSymbolAddress((void**)&hh,    g_hh);
    cudaGetSymbolAddress((void**)&hl,    g_hl);
    cudaGetSymbolAddress((void**)&yh,    g_yh);
    cudaGetSymbolAddress((void**)&yl,    g_yl);
    cudaGetSymbolAddress((void**)&ffh,   g_ffh);
    cudaGetSymbolAddress((void**)&ffl,   g_ffl);
    cudaGetSymbolAddress((void**)&wqkvh, g_wqkv_h);
    cudaGetSymbolAddress((void**)&wqkvl, g_wqkv_l);
    cudaGetSymbolAddress((void**)&woh,   g_wo_h);
    cudaGetSymbolAddress((void**)&wol,   g_wo_l);
    cudaGetSymbolAddress((void**)&w1h,   g_w1_h);
    cudaGetSymbolAddress((void**)&w1l,   g_w1_l);
    cudaGetSymbolAddress((void**)&w2h,   g_w2_h);
    cudaGetSymbolAddress((void**)&w2l,   g_w2_l);
    cudaGetSymbolAddress((void**)&eh,    g_eh);
    cudaGetSymbolAddress((void**)&el,    g_el);

    cudaFuncSetAttribute(gemm_mma<0,128,3>, cudaFuncAttributeMaxDynamicSharedMemorySize, GSM128);
    cudaFuncSetAttribute(gemm_mma<0,256,2>, cudaFuncAttributeMaxDynamicSharedMemorySize, GSM256);
    cudaFuncSetAttribute(gemm_mma<2,256,2>, cudaFuncAttributeMaxDynamicSharedMemorySize, GSM256);
    cudaFuncSetAttribute(scores_mma, cudaFuncAttributeMaxDynamicSharedMemorySize, SCSM);
    cudaFuncSetAttribute(av_mma, cudaFuncAttributeMaxDynamicSharedMemorySize, AVSM);

    // side stream + events (created once; host-side objects only)
    static cudaStream_t s2 = nullptr;
    static cudaEvent_t ev_fork = nullptr, ev_w0 = nullptr, ev_w1 = nullptr, ev_e = nullptr;
    if (!s2) {
        cudaStreamCreateWithFlags(&s2, cudaStreamNonBlocking);
        cudaEventCreateWithFlags(&ev_fork, cudaEventDisableTiming);
        cudaEventCreateWithFlags(&ev_w0, cudaEventDisableTiming);
        cudaEventCreateWithFlags(&ev_w1, cudaEventDisableTiming);
        cudaEventCreateWithFlags(&ev_e, cudaEventDisableTiming);
    }

    const size_t BTV = (size_t)TT * VV;
    float* logits_dst = ((size_t)out_size >= BTV) ? (float*)d_out : logp;
    float* loss_dst = nullptr;
    if ((size_t)out_size > BTV)      loss_dst = (float*)d_out + BTV;
    else if ((size_t)out_size < BTV) loss_dst = (float*)d_out;

    dim3 tb(32, 8);

    // ---- fork: preprocessing that is not needed immediately goes to s2 ----
    cudaEventRecord(ev_fork, 0);
    cudaStreamWaitEvent(s2, ev_fork, 0);

    // s2: layer-0 Wo/W1/W2 splits (needed ~150us into iter 0)
    wtsplit_k<<<dim3(EE/32, EE/32), tb, 0, s2>>>(Wo, woh, wol, EE, EE, EE);
    wtsplit_k<<<dim3(FF/32, EE/32), tb, 0, s2>>>(W1, w1h, w1l, EE, FF, EE);
    wtsplit_k<<<dim3(EE/32, FF/32), tb, 0, s2>>>(W2, w2h, w2l, FF, EE, FF);
    cudaEventRecord(ev_w0, s2);
    // s2: all layer-1 splits (needed at iter 1)
    {
        const int l = 1;
        wtsplit_k<<<dim3(EE/32, EE/32), tb, 0, s2>>>(Wq + (size_t)l*EE*EE,
            wqkvh + (size_t)l*QKVN*EE, wqkvl + (size_t)l*QKVN*EE, EE, EE, EE);
        wtsplit_k<<<dim3(KVD/32, EE/32), tb, 0, s2>>>(Wk + (size_t)l*EE*KVD,
            wqkvh + (size_t)l*QKVN*EE + (size_t)EE*EE, wqkvl + (size_t)l*QKVN*EE + (size_t)EE*EE, EE, KVD, EE);
        wtsplit_k<<<dim3(KVD/32, EE/32), tb, 0, s2>>>(Wv + (size_t)l*EE*KVD,
            wqkvh + (size_t)l*QKVN*EE + (size_t)(EE+KVD)*EE, wqkvl + (size_t)l*QKVN*EE + (size_t)(EE+KVD)*EE, EE, KVD, EE);
        wtsplit_k<<<dim3(EE/32, EE/32), tb, 0, s2>>>(Wo + (size_t)l*EE*EE,
            woh + (size_t)l*EE*EE, wol + (size_t)l*EE*EE, EE, EE, EE);
        wtsplit_k<<<dim3(FF/32, EE/32), tb, 0, s2>>>(W1 + (size_t)l*EE*FF,
            w1h + (size_t)l*FF*EE, w1l + (size_t)l*FF*EE, EE, FF, EE);
        wtsplit_k<<<dim3(EE/32, FF/32), tb, 0, s2>>>(W2 + (size_t)l*FF*EE,
            w2h + (size_t)l*EE*FF, w2l + (size_t)l*EE*FF, FF, EE, FF);
    }
    cudaEventRecord(ev_w1, s2);
    // s2: embed split (needed at logits)
    esplit_k<<<(int)(((size_t)VV*EE)/1024), 256, 0, s2>>>(embed, eh, el);
    cudaEventRecord(ev_e, s2);

    // ---- main stream: critical path ----
    wtsplit_k<<<dim3(EE/32, EE/32), tb>>>(Wq, wqkvh, wqkvl, EE, EE, EE);
    wtsplit_k<<<dim3(KVD/32, EE/32), tb>>>(Wk, wqkvh + (size_t)EE*EE, wqkvl + (size_t)EE*EE, EE, KVD, EE);
    wtsplit_k<<<dim3(KVD/32, EE/32), tb>>>(Wv, wqkvh + (size_t)(EE+KVD)*EE, wqkvl + (size_t)(EE+KVD)*EE, EE, KVD, EE);
    gather_embed_k<<<(TT * EE) / 256, 256>>>(embed, idx);
    layernorm_split_k<<<TT, 256>>>(xp, hh, hl, ln1_g, ln1_b);

    for (int it = 0; it < RNUM * LNUM; it++) {
        int l = it % LNUM;
        if (it == 1) cudaStreamWaitEvent(0, ev_w1, 0);
        // QKV: split-K=3 -> partials
        gemm_mma<0,128,3><<<dim3(TT/128, QKVN/128, 3), 256, GSM128>>>(hh, hl,
            wqkvh + (size_t)l*QKVN*EE, wqkvl + (size_t)l*QKVN*EE,
            partp, nullptr, nullptr, nullptr, QKVN, EE);
        qkv_post_k<<<dim3(TT/64, NH + 2*NKV), 256>>>(partp);
        scores_mma<<<dim3(TT/128, TT/64, NH), 256, SCSM>>>();
        softmax_thresh_k<<<dim3(TT, NH), 256>>>(gate, l);
        av_mma<<<dim3(TT/64, NH), 256, AVSM>>>();
        if (it == 0) cudaStreamWaitEvent(0, ev_w0, 0);
        // Wo: split-K=2 -> partials; fused x+= & LN2
        gemm_mma<0,128,3><<<dim3(TT/128, EE/128, 2), 256, GSM128>>>(yh, yl,
            woh + (size_t)l*EE*EE, wol + (size_t)l*EE*EE,
            partp, nullptr, nullptr, nullptr, EE, EE);
        add_ln_split_k<<<TT, 256>>>(xp, partp, ln2_g + l * EE, ln2_b + l * EE, hh, hl);
        // FFN
        gemm_mma<2,256,2><<<dim3(TT/128, FF/256, 1), 256, GSM256>>>(hh, hl,
            w1h + (size_t)l*FF*EE, w1l + (size_t)l*FF*EE,
            nullptr, nullptr, ffh, ffl, FF, EE);
        gemm_mma<0,128,3><<<dim3(TT/128, EE/128, 2), 256, GSM128>>>(ffh, ffl,
            w2h + (size_t)l*EE*FF, w2l + (size_t)l*EE*FF,
            partp, nullptr, nullptr, nullptr, EE, FF);
        const float *ng, *nb;
        if (it == RNUM * LNUM - 1) { ng = lnf_g; nb = lnf_b; }
        else { int ln = (l + 1) % LNUM; ng = ln1_g + ln * EE; nb = ln1_b + ln * EE; }
        add_ln_split_k<<<TT, 256>>>(xp, partp, ng, nb, hh, hl);
    }

    // logits (needs embed split)
    cudaStreamWaitEvent(0, ev_e, 0);
    gemm_mma<0,256,2><<<dim3(TT/128, VV/256, 1), 256, GSM256>>>(hh, hl, eh, el,
        logits_dst, nullptr, nullptr, nullptr, VV, EE);

    zero_loss_k<<<1, 1>>>();
    loss_rows_k<<<TT, 256>>>(logits_dst, tgt);
    if (loss_dst) loss_fin_k<<<1, 1>>>(loss_dst);
}

// round 9
// speedup vs baseline: 4.6009x; 1.1160x over previous
#include <cuda_runtime.h>
#include <cuda_bf16.h>
#include <cuda_fp16.h>
#include <math.h>
#include <stdint.h>

// ---------------- problem constants ----------------
#define TT 1024
#define EE 1024
#define VV 32000
#define NH 16
#define NKV 4
#define DHD 64
#define KVD (NKV*DHD)     // 256
#define QKVN 1536
#define LNUM 2
#define RNUM 2
#define FF 4096
#define EPSV 1e-5f

typedef __nv_bfloat16 bf16;

// ---------------- device scratch ----------------
__device__ float g_x[TT*EE];
__device__ bf16  g_hh[TT*EE], g_hl[TT*EE];
__device__ __half g_hf[TT*EE];                         // fp16 final-LN output for logits
__device__ float g_att[(size_t)NH*TT*TT];
__device__ bf16  g_atth[(size_t)NH*TT*TT], g_attl[(size_t)NH*TT*TT];
__device__ float g_part[3*TT*QKVN];          // split-K partials (reused)
__device__ bf16  g_qh[NH*TT*DHD],  g_ql[NH*TT*DHD];
__device__ bf16  g_kh[NKV*TT*DHD], g_kl[NKV*TT*DHD];
__device__ bf16  g_vth[NKV*DHD*TT], g_vtl[NKV*DHD*TT];   // transposed V
__device__ bf16  g_yh[TT*EE], g_yl[TT*EE];
__device__ bf16  g_ffh[TT*FF], g_ffl[TT*FF];
__device__ bf16  g_wqkv_h[LNUM*QKVN*EE], g_wqkv_l[LNUM*QKVN*EE];
__device__ bf16  g_wo_h[LNUM*EE*EE],     g_wo_l[LNUM*EE*EE];
__device__ bf16  g_w1_h[LNUM*FF*EE],     g_w1_l[LNUM*FF*EE];
__device__ bf16  g_w2_h[LNUM*EE*FF],     g_w2_l[LNUM*EE*FF];
__device__ __half g_efh[(size_t)VV*EE], g_efl[(size_t)VV*EE];  // fp16 hi/lo embed
__device__ float g_logits[(size_t)TT*VV];
__device__ float g_loss;

// ---------------- generic helpers ----------------
__device__ __forceinline__ float blk_sum256(float v, float* sh) {
    int tid = threadIdx.x;
    sh[tid] = v; __syncthreads();
    #pragma unroll
    for (int s = 128; s > 0; s >>= 1) { if (tid < s) sh[tid] += sh[tid + s]; __syncthreads(); }
    float r = sh[0]; __syncthreads();
    return r;
}
__device__ __forceinline__ float blk_max256(float v, float* sh) {
    int tid = threadIdx.x;
    sh[tid] = v; __syncthreads();
    #pragma unroll
    for (int s = 128; s > 0; s >>= 1) { if (tid < s) sh[tid] = fmaxf(sh[tid], sh[tid + s]); __syncthreads(); }
    float r = sh[0]; __syncthreads();
    return r;
}
__device__ __forceinline__ float gelu_exact(float x) {
    return 0.5f * x * (1.0f + erff(x * 0.7071067811865476f));
}
__device__ __forceinline__ void split_bf16(float v, bf16& h, bf16& l) {
    h = __float2bfloat16(v);
    l = __float2bfloat16(v - __bfloat162float(h));
}
__device__ __forceinline__ void split_fp16(float v, __half& h, __half& l) {
    h = __float2half_rn(v);
    l = __float2half_rn(v - __half2float(h));
}

// ---------------- PTX wrappers ----------------
__device__ __forceinline__ void mma_bf16(float* d, const uint32_t* a, const uint32_t* b) {
    asm volatile("mma.sync.aligned.m16n8k16.row.col.f32.bf16.bf16.f32 "
        "{%0,%1,%2,%3}, {%4,%5,%6,%7}, {%8,%9}, {%0,%1,%2,%3};"
        : "+f"(d[0]), "+f"(d[1]), "+f"(d[2]), "+f"(d[3])
        : "r"(a[0]), "r"(a[1]), "r"(a[2]), "r"(a[3]), "r"(b[0]), "r"(b[1]));
}
__device__ __forceinline__ void mma_fp16(float* d, const uint32_t* a, const uint32_t* b) {
    asm volatile("mma.sync.aligned.m16n8k16.row.col.f32.f16.f16.f32 "
        "{%0,%1,%2,%3}, {%4,%5,%6,%7}, {%8,%9}, {%0,%1,%2,%3};"
        : "+f"(d[0]), "+f"(d[1]), "+f"(d[2]), "+f"(d[3])
        : "r"(a[0]), "r"(a[1]), "r"(a[2]), "r"(a[3]), "r"(b[0]), "r"(b[1]));
}
__device__ __forceinline__ void ldsm4(uint32_t* r, uint32_t addr) {
    asm volatile("ldmatrix.sync.aligned.m8n8.x4.shared.b16 {%0,%1,%2,%3}, [%4];"
        : "=r"(r[0]), "=r"(r[1]), "=r"(r[2]), "=r"(r[3]) : "r"(addr));
}
__device__ __forceinline__ void cp16(uint32_t s, const void* g) {
    asm volatile("cp.async.cg.shared.global [%0], [%1], 16;" :: "r"(s), "l"(g));
}
#define CP_COMMIT()  asm volatile("cp.async.commit_group;")
#define CP_WAIT(n)   asm volatile("cp.async.wait_group %0;" :: "n"(n))

// SW128 swizzle: 128B rows, 16B chunks, chunk ^= row&7  (conflict-free ldmatrix)
__device__ __forceinline__ uint32_t sw_off(int row, int chunk) {
    return (uint32_t)(row * 128 + ((chunk ^ (row & 7)) << 4));
}

// ---------------- split-bf16 HMMA GEMM ----------------
template<int MODE, int TN, int NSTG>
__global__ __launch_bounds__(256, 1) void gemm_mma(
    const bf16* __restrict__ Ah, const bf16* __restrict__ Al,
    const bf16* __restrict__ Bh, const bf16* __restrict__ Bl,
    float* C, const float* Rs, bf16* Oh, bf16* Ol,
    int N, int K)
{
    constexpr int TSA = 128 * 128;
    constexpr int TSB = TN * 128;
    constexpr int SB  = 2 * TSA + 2 * TSB;
    constexpr int BCH = TN * 8;
    constexpr int TC  = 2048 + 2 * BCH;
    constexpr int NG  = TN / 64;
    constexpr int NF  = 2 * NG;

    extern __shared__ char dsm[];
    const int tid = threadIdx.x;
    const int lane = tid & 31, warp = tid >> 5;
    const int wm = warp & 1, wn = warp >> 1;
    const int row0 = blockIdx.x * 128, col0 = blockIdx.y * TN;
    const uint32_t sb = (uint32_t)__cvta_generic_to_shared(dsm);

    float acc[4][NF][4];
    #pragma unroll
    for (int i = 0; i < 4; i++)
        #pragma unroll
        for (int j = 0; j < NF; j++)
            #pragma unroll
            for (int r = 0; r < 4; r++) acc[i][j][r] = 0.f;

    auto load_stage = [&](int s) {
        int k0 = s * 64;
        uint32_t base = sb + (s % NSTG) * SB;
        #pragma unroll
        for (int ii = 0; ii < TC / 256; ii++) {
            int i = tid + ii * 256;
            const bf16* src;
            uint32_t toff;
            if (i < 2048) {
                int t = i >> 10, w = i & 1023;
                int r = w >> 3, c = w & 7;
                src = (t ? Al : Ah) + (size_t)(row0 + r) * K + k0 + c * 8;
                toff = t * TSA + sw_off(r, c);
            } else {
                int j = i - 2048;
                int t = j / BCH, w = j & (BCH - 1);
                int r = w >> 3, c = w & 7;
                src = (t ? Bl : Bh) + (size_t)(col0 + r) * K + k0 + c * 8;
                toff = 2 * TSA + t * TSB + sw_off(r, c);
            }
            cp16(base + toff, src);
        }
        CP_COMMIT();
    };

    const int Stot = K >> 6;
    const int SK = gridDim.z;
    const int Sc = (Stot + SK - 1) / SK;
    const int s0 = blockIdx.z * Sc;
    const int s1 = min(Stot, s0 + Sc);

    #pragma unroll
    for (int i = 0; i < NSTG; i++)
        if (s0 + i < s1) load_stage(s0 + i);

    const int lr = lane & 15, lcs = lane >> 4;

    for (int s = s0; s < s1; s++) {
        int ahead = s1 - 1 - s;
        int w = ahead < (NSTG - 1) ? ahead : (NSTG - 1);
        if (w == 2)      { CP_WAIT(2); }
        else if (w == 1) { CP_WAIT(1); }
        else             { CP_WAIT(0); }
        __syncthreads();
        uint32_t ab = sb + (s % NSTG) * SB;
        #pragma unroll
        for (int k16 = 0; k16 < 4; k16++) {
            const int cch = k16 * 2 + lcs;
            uint32_t ah[4][4], al[4][4];
            #pragma unroll
            for (int mf = 0; mf < 4; mf++) {
                int row = wm * 64 + mf * 16 + lr;
                uint32_t off = sw_off(row, cch);
                ldsm4(ah[mf], ab + off);
                ldsm4(al[mf], ab + TSA + off);
            }
            #pragma unroll
            for (int g = 0; g < NG; g++) {
                int row = wn * (TN / 4) + g * 16 + lr;
                uint32_t off = sw_off(row, cch);
                uint32_t rh[4], rl[4];
                ldsm4(rh, ab + 2 * TSA + off);
                ldsm4(rl, ab + 2 * TSA + TSB + off);
                uint32_t b0h[2] = {rh[0], rh[2]}, b1h[2] = {rh[1], rh[3]};
                uint32_t b0l[2] = {rl[0], rl[2]}, b1l[2] = {rl[1], rl[3]};
                #pragma unroll
                for (int mf = 0; mf < 4; mf++) {
                    mma_bf16(acc[mf][g*2], ah[mf], b0h);
                    mma_bf16(acc[mf][g*2], ah[mf], b0l);
                    mma_bf16(acc[mf][g*2], al[mf], b0h);
                    mma_bf16(acc[mf][g*2+1], ah[mf], b1h);
                    mma_bf16(acc[mf][g*2+1], ah[mf], b1l);
                    mma_bf16(acc[mf][g*2+1], al[mf], b1h);
                }
            }
        }
        __syncthreads();
        if (s + NSTG < s1) load_stage(s + NSTG);
    }

    const size_t pstride = (size_t)gridDim.x * 128 * N;
    float* Cp = C + (size_t)blockIdx.z * pstride;
    #pragma unroll
    for (int mf = 0; mf < 4; mf++)
        #pragma unroll
        for (int nf = 0; nf < NF; nf++) {
            int r = row0 + wm * 64 + mf * 16 + (lane >> 2);
            int c = col0 + wn * (TN / 4) + nf * 8 + (lane & 3) * 2;
            float* d = acc[mf][nf];
            if (gridDim.z > 1) {
                *(float2*)(Cp + (size_t)r * N + c)       = make_float2(d[0], d[1]);
                *(float2*)(Cp + (size_t)(r + 8) * N + c) = make_float2(d[2], d[3]);
            } else if (MODE == 0) {
                *(float2*)(C + (size_t)r * N + c)       = make_float2(d[0], d[1]);
                *(float2*)(C + (size_t)(r + 8) * N + c) = make_float2(d[2], d[3]);
            } else {
                float v0 = gelu_exact(d[0]), v1 = gelu_exact(d[1]);
                float v2 = gelu_exact(d[2]), v3 = gelu_exact(d[3]);
                bf16 h0, l0, h1, l1, h2, l2, h3, l3;
                split_bf16(v0, h0, l0); split_bf16(v1, h1, l1);
                split_bf16(v2, h2, l2); split_bf16(v3, h3, l3);
                *(__nv_bfloat162*)(Oh + (size_t)r * N + c)       = __halves2bfloat162(h0, h1);
                *(__nv_bfloat162*)(Ol + (size_t)r * N + c)       = __halves2bfloat162(l0, l1);
                *(__nv_bfloat162*)(Oh + (size_t)(r + 8) * N + c) = __halves2bfloat162(h2, h3);
                *(__nv_bfloat162*)(Ol + (size_t)(r + 8) * N + c) = __halves2bfloat162(l2, l3);
            }
        }
}

#define GSM128 (3 * (2*128*128 + 2*128*128))   // 196608
#define GSM256 (2 * (2*128*128 + 2*256*128))   // 196608

// ---------------- fp16 2-term logits GEMM: C = A * (Bh+Bl)^T ----------------
// A fp16 single (hi bits of final LN), B fp16 hi/lo. 2 MMAs per logical op.
#define LGSM (2 * (128*128 + 2*256*128))       // 163840
__global__ __launch_bounds__(256, 1) void logits_mma(
    const __half* __restrict__ A, const __half* __restrict__ Bh,
    const __half* __restrict__ Bl, float* __restrict__ C)
{
    constexpr int TSA = 128 * 128;    // 16KB
    constexpr int TSB = 256 * 128;    // 32KB
    constexpr int SB  = TSA + 2 * TSB;
    const int N = VV, K = EE;

    extern __shared__ char dsm[];
    const int tid = threadIdx.x;
    const int lane = tid & 31, warp = tid >> 5;
    const int wm = warp & 1, wn = warp >> 1;
    const int row0 = blockIdx.x * 128, col0 = blockIdx.y * 256;
    const uint32_t sb = (uint32_t)__cvta_generic_to_shared(dsm);

    float acc[4][8][4];
    #pragma unroll
    for (int i = 0; i < 4; i++)
        #pragma unroll
        for (int j = 0; j < 8; j++)
            #pragma unroll
            for (int r = 0; r < 4; r++) acc[i][j][r] = 0.f;

    auto load_stage = [&](int s) {
        int k0 = s * 64;
        uint32_t base = sb + (s & 1) * SB;
        #pragma unroll
        for (int ii = 0; ii < 20; ii++) {
            int i = tid + ii * 256;
            const __half* src; uint32_t toff;
            if (i < 1024) {
                int r = i >> 3, c = i & 7;
                src = A + (size_t)(row0 + r) * K + k0 + c * 8;
                toff = sw_off(r, c);
            } else {
                int j = i - 1024;
                int t = j >> 11, w = j & 2047;
                int r = w >> 3, c = w & 7;
                src = (t ? Bl : Bh) + (size_t)(col0 + r) * K + k0 + c * 8;
                toff = TSA + t * TSB + sw_off(r, c);
            }
            cp16(base + toff, src);
        }
        CP_COMMIT();
    };

    const int S = K >> 6;   // 16
    load_stage(0);
    load_stage(1);
    const int lr = lane & 15, lcs = lane >> 4;

    for (int s = 0; s < S; s++) {
        if (s + 1 < S) { CP_WAIT(1); } else { CP_WAIT(0); }
        __syncthreads();
        uint32_t ab = sb + (s & 1) * SB;
        #pragma unroll
        for (int k16 = 0; k16 < 4; k16++) {
            const int cch = k16 * 2 + lcs;
            uint32_t ah[4][4];
            #pragma unroll
            for (int mf = 0; mf < 4; mf++)
                ldsm4(ah[mf], ab + sw_off(wm * 64 + mf * 16 + lr, cch));
            #pragma unroll
            for (int g = 0; g < 4; g++) {
                uint32_t off = sw_off(wn * 64 + g * 16 + lr, cch);
                uint32_t rh[4], rl[4];
                ldsm4(rh, ab + TSA + off);
                ldsm4(rl, ab + TSA + TSB + off);
                uint32_t b0h[2] = {rh[0], rh[2]}, b1h[2] = {rh[1], rh[3]};
                uint32_t b0l[2] = {rl[0], rl[2]}, b1l[2] = {rl[1], rl[3]};
                #pragma unroll
                for (int mf = 0; mf < 4; mf++) {
                    mma_fp16(acc[mf][g*2], ah[mf], b0h);
                    mma_fp16(acc[mf][g*2], ah[mf], b0l);
                    mma_fp16(acc[mf][g*2+1], ah[mf], b1h);
                    mma_fp16(acc[mf][g*2+1], ah[mf], b1l);
                }
            }
        }
        __syncthreads();
        if (s + 2 < S) load_stage(s + 2);
    }

    #pragma unroll
    for (int mf = 0; mf < 4; mf++)
        #pragma unroll
        for (int nf = 0; nf < 8; nf++) {
            int r = row0 + wm * 64 + mf * 16 + (lane >> 2);
            int c = col0 + wn * 64 + nf * 8 + (lane & 3) * 2;
            float* d = acc[mf][nf];
            *(float2*)(C + (size_t)r * N + c)       = make_float2(d[0], d[1]);
            *(float2*)(C + (size_t)(r + 8) * N + c) = make_float2(d[2], d[3]);
        }
}

// ---------------- fused QKV reduce + RoPE/transpose + split ----------------
__global__ void qkv_post_k(const float* __restrict__ part) {
    __shared__ float tile[64][65];
    int ttile = blockIdx.x, head = blockIdx.y;
    int tid = threadIdx.x;
    int cb;
    if (head < NH)            cb = head * DHD;
    else if (head < NH + NKV) cb = EE + (head - NH) * DHD;
    else                      cb = EE + KVD + (head - NH - NKV) * DHD;
    const int n = TT * QKVN;
    #pragma unroll
    for (int it = 0; it < 16; it++) {
        int i = tid + it * 256;
        int r = i >> 6, c = i & 63;
        size_t idx = (size_t)(ttile * 64 + r) * QKVN + cb + c;
        tile[r][c] = part[idx] + part[idx + n] + part[idx + 2 * (size_t)n];
    }
    __syncthreads();
    if (head < NH + NKV) {
        bf16 *dh, *dl; size_t off;
        if (head < NH) { dh = g_qh; dl = g_ql; off = (size_t)head * TT * DHD; }
        else           { dh = g_kh; dl = g_kl; off = (size_t)(head - NH) * TT * DHD; }
        #pragma unroll
        for (int it = 0; it < 16; it++) {
            int i = tid + it * 256;
            int r = i >> 6, d = i & 63;
            int t = ttile * 64 + r;
            float v;
            if (d < 32) {
                int j = d & 15;
                float theta = powf(10000.0f, -(float)j / 16.0f);
                float ang = (float)t * theta;
                float cs = cosf(ang), sn = sinf(ang);
                if (d < 16) v = tile[r][d] * cs - tile[r][d + 16] * sn;
                else        v = tile[r][d] * cs + tile[r][d - 16] * sn;
            } else v = tile[r][d];
            bf16 h, l; split_bf16(v, h, l);
            size_t o = off + (size_t)t * DHD + d;
            dh[o] = h; dl[o] = l;
        }
    } else {
        int kh = head - NH - NKV;
        #pragma unroll
        for (int it = 0; it < 16; it++) {
            int i = tid + it * 256;
            int d = i >> 6, tc = i & 63;
            float v = tile[tc][d];
            bf16 h, l; split_bf16(v, h, l);
            size_t o = ((size_t)kh * DHD + d) * TT + ttile * 64 + tc;
            g_vth[o] = h; g_vtl[o] = l;
        }
    }
}

// ---------------- HMMA attention scores: 64(t) x 128(s), K=64 ----------------
#define SCSM 49152
__global__ __launch_bounds__(256) void scores_mma() {
    int st = blockIdx.x, tt = blockIdx.y, h = blockIdx.z;
    if (2 * st > tt) return;
    int khid = h >> 2;
    extern __shared__ char dsm[];
    const uint32_t sb = (uint32_t)__cvta_generic_to_shared(dsm);
    const int tid = threadIdx.x;
    const int lane = tid & 31, warp = tid >> 5;

    #pragma unroll
    for (int it = 0; it < 12; it++) {
        int i = tid + it * 256;
        const bf16* src; uint32_t dst;
        if (i < 1024) {
            int sub = i >> 9, w = i & 511, r = w >> 3, c = w & 7;
            src = (sub ? g_ql : g_qh) + ((size_t)h * TT + tt * 64 + r) * DHD + c * 8;
            dst = sub * 8192 + sw_off(r, c);
        } else {
            int j = i - 1024;
            int sub = j >> 10, w = j & 1023, r = w >> 3, c = w & 7;
            src = (sub ? g_kl : g_kh) + ((size_t)khid * TT + st * 128 + r) * DHD + c * 8;
            dst = 16384 + sub * 16384 + sw_off(r, c);
        }
        cp16(sb + dst, src);
    }
    CP_COMMIT(); CP_WAIT(0);
    __syncthreads();

    const int wm = warp & 1, wn = warp >> 1;
    const int lr = lane & 15, lcs = lane >> 4;
    float acc[2][4][4];
    #pragma unroll
    for (int a = 0; a < 2; a++)
        #pragma unroll
        for (int b = 0; b < 4; b++)
            #pragma unroll
            for (int c = 0; c < 4; c++) acc[a][b][c] = 0.f;

    #pragma unroll
    for (int k16 = 0; k16 < 4; k16++) {
        const int cch = k16 * 2 + lcs;
        uint32_t ah[2][4], al[2][4];
        #pragma unroll
        for (int mf = 0; mf < 2; mf++) {
            int row = wm * 32 + mf * 16 + lr;
            uint32_t off = sw_off(row, cch);
            ldsm4(ah[mf], sb + off);
            ldsm4(al[mf], sb + 8192 + off);
        }
        #pragma unroll
        for (int g = 0; g < 2; g++) {
            int row = wn * 32 + g * 16 + lr;
            uint32_t off = sw_off(row, cch);
            uint32_t rh[4], rl[4];
            ldsm4(rh, sb + 16384 + off);
            ldsm4(rl, sb + 32768 + off);
            uint32_t b0h[2] = {rh[0], rh[2]}, b1h[2] = {rh[1], rh[3]};
            uint32_t b0l[2] = {rl[0], rl[2]}, b1l[2] = {rl[1], rl[3]};
            #pragma unroll
            for (int mf = 0; mf < 2; mf++) {
                mma_bf16(acc[mf][g*2], ah[mf], b0h);
                mma_bf16(acc[mf][g*2], ah[mf], b0l);
                mma_bf16(acc[mf][g*2], al[mf], b0h);
                mma_bf16(acc[mf][g*2+1], ah[mf], b1h);
                mma_bf16(acc[mf][g*2+1], ah[mf], b1l);
                mma_bf16(acc[mf][g*2+1], al[mf], b1h);
            }
        }
    }
    float* o = g_att + (size_t)h * TT * TT;
    #pragma unroll
    for (int mf = 0; mf < 2; mf++)
        #pragma unroll
        for (int nf = 0; nf < 4; nf++) {
            int r = tt * 64 + wm * 32 + mf * 16 + (lane >> 2);
            int c = st * 128 + wn * 32 + nf * 8 + (lane & 3) * 2;
            float* d = acc[mf][nf];
            *(float2*)(o + (size_t)r * TT + c)       = make_float2(d[0]*0.125f, d[1]*0.125f);
            *(float2*)(o + (size_t)(r + 8) * TT + c) = make_float2(d[2]*0.125f, d[3]*0.125f);
        }
}

// ---------------- single-pass softmax + gate, writes split-bf16 att ----------------
__global__ void softmax_thresh_k(const float* __restrict__ gate_all, int l) {
    __shared__ float sh[256];
    int t = blockIdx.x, h = blockIdx.y;
    int tid = threadIdx.x;
    const float* p = g_att + (size_t)h * TT * TT + (size_t)t * TT;
    float thr = 1.0f / (1.0f + expf(-gate_all[l * NH + h]));
    float x[4];
    #pragma unroll
    for (int k = 0; k < 4; k++) {
        int i = k * 256 + tid;
        x[k] = (i <= t) ? p[i] : -1e30f;
    }
    float m = fmaxf(fmaxf(x[0], x[1]), fmaxf(x[2], x[3]));
    m = blk_max256(m, sh);
    float e[4], s = 0.f;
    #pragma unroll
    for (int k = 0; k < 4; k++) {
        int i = k * 256 + tid;
        e[k] = (i <= t) ? expf(x[k] - m) : 0.f;
        s += e[k];
    }
    s = blk_sum256(s, sh);
    float inv = 1.0f / s;
    int kend = ((t >> 6) + 1) << 6;
    size_t base = (size_t)h * TT * TT + (size_t)t * TT;
    #pragma unroll
    for (int k = 0; k < 4; k++) {
        int i = k * 256 + tid;
        if (i < kend) {
            float pv = e[k] * inv;
            pv = (pv >= thr) ? pv : 0.f;
            bf16 hh2, ll2; split_bf16(pv, hh2, ll2);
            g_atth[base + i] = hh2;
            g_attl[base + i] = ll2;
        }
    }
}

// ---------------- HMMA AV: 64(t) x 64(d), K-loop over s (largest-K first) ----------------
#define AVSM 65536
__global__ __launch_bounds__(256) void av_mma() {
    int tt = gridDim.x - 1 - blockIdx.x;    // largest-K blocks launch first
    int h = blockIdx.y;
    int khid = h >> 2;
    int St = tt + 1;
    extern __shared__ char dsm[];
    const uint32_t sb = (uint32_t)__cvta_generic_to_shared(dsm);
    const int tid = threadIdx.x;
    const int lane = tid & 31, warp = tid >> 5;
    const int wm = warp & 1, wn = warp >> 1;
    const int lr = lane & 15, lcs = lane >> 4;

    auto load = [&](int s) {
        uint32_t base = sb + (s & 1) * 32768;
        #pragma unroll
        for (int it = 0; it < 8; it++) {
            int i = tid + it * 256;
            const bf16* src; uint32_t dst;
            if (i < 1024) {
                int sub = i >> 9, w = i & 511, r = w >> 3, c = w & 7;
                src = (sub ? g_attl : g_atth) + ((size_t)h * TT + tt * 64 + r) * TT + s * 64 + c * 8;
                dst = base + sub * 8192 + sw_off(r, c);
            } else {
                int j = i - 1024;
                int sub = j >> 9, w = j & 511, r = w >> 3, c = w & 7;
                src = (sub ? g_vtl : g_vth) + ((size_t)khid * DHD + r) * TT + s * 64 + c * 8;
                dst = base + 16384 + sub * 8192 + sw_off(r, c);
            }
            cp16(dst, src);
        }
        CP_COMMIT();
    };

    load(0);
    if (St > 1) load(1);

    float acc[2][2][4];
    #pragma unroll
    for (int a = 0; a < 2; a++)
        #pragma unroll
        for (int b = 0; b < 2; b++)
            #pragma unroll
            for (int c = 0; c < 4; c++) acc[a][b][c] = 0.f;

    for (int s = 0; s < St; s++) {
        if (s + 1 < St) { CP_WAIT(1); } else { CP_WAIT(0); }
        __syncthreads();
        uint32_t base = sb + (s & 1) * 32768;
        #pragma unroll
        for (int k16 = 0; k16 < 4; k16++) {
            const int cch = k16 * 2 + lcs;
            uint32_t ah[2][4], al[2][4];
            #pragma unroll
            for (int mf = 0; mf < 2; mf++) {
                int row = wm * 32 + mf * 16 + lr;
                uint32_t off = sw_off(row, cch);
                ldsm4(ah[mf], base + off);
                ldsm4(al[mf], base + 8192 + off);
            }
            int row = wn * 16 + lr;
            uint32_t off = sw_off(row, cch);
            uint32_t rh[4], rl[4];
            ldsm4(rh, base + 16384 + off);
            ldsm4(rl, base + 24576 + off);
            uint32_t b0h[2] = {rh[0], rh[2]}, b1h[2] = {rh[1], rh[3]};
            uint32_t b0l[2] = {rl[0], rl[2]}, b1l[2] = {rl[1], rl[3]};
            #pragma unroll
            for (int mf = 0; mf < 2; mf++) {
                mma_bf16(acc[mf][0], ah[mf], b0h);
                mma_bf16(acc[mf][0], ah[mf], b0l);
                mma_bf16(acc[mf][0], al[mf], b0h);
                mma_bf16(acc[mf][1], ah[mf], b1h);
                mma_bf16(acc[mf][1], ah[mf], b1l);
                mma_bf16(acc[mf][1], al[mf], b1h);
            }
        }
        __syncthreads();
        if (s + 2 < St) load(s + 2);
    }

    #pragma unroll
    for (int mf = 0; mf < 2; mf++)
        #pragma unroll
        for (int nf = 0; nf < 2; nf++) {
            int r = tt * 64 + wm * 32 + mf * 16 + (lane >> 2);
            int c = h * DHD + wn * 16 + nf * 8 + (lane & 3) * 2;
            float* d = acc[mf][nf];
            bf16 h0, l0, h1, l1, h2, l2, h3, l3;
            split_bf16(d[0], h0, l0); split_bf16(d[1], h1, l1);
            split_bf16(d[2], h2, l2); split_bf16(d[3], h3, l3);
            *(__nv_bfloat162*)(g_yh + (size_t)r * EE + c)       = __halves2bfloat162(h0, h1);
            *(__nv_bfloat162*)(g_yl + (size_t)r * EE + c)       = __halves2bfloat162(l0, l1);
            *(__nv_bfloat162*)(g_yh + (size_t)(r + 8) * EE + c) = __halves2bfloat162(h2, h3);
            *(__nv_bfloat162*)(g_yl + (size_t)(r + 8) * EE + c) = __halves2bfloat162(l2, l3);
        }
}

// ---------------- fused residual-add + layernorm + split (bf16 pair or fp16) ----------------
__global__ void add_ln_split_k(float* __restrict__ x, const float* __restrict__ p,
                               const float* __restrict__ g, const float* __restrict__ b,
                               bf16* __restrict__ oh, bf16* __restrict__ ol,
                               __half* __restrict__ of) {
    __shared__ float sh[256];
    int row = blockIdx.x, tid = threadIdx.x;
    const int n = TT * EE;
    float v[4];
    #pragma unroll
    for (int k = 0; k < 4; k++) {
        int i = row * EE + k * 256 + tid;
        v[k] = x[i] + p[i] + p[i + n];
        x[i] = v[k];
    }
    float mu = blk_sum256(v[0] + v[1] + v[2] + v[3], sh) * (1.0f / EE);
    float vs = 0.f;
    #pragma unroll
    for (int k = 0; k < 4; k++) { float d = v[k] - mu; vs += d * d; }
    float var = blk_sum256(vs, sh) * (1.0f / EE);
    float inv = rsqrtf(var + EPSV);
    #pragma unroll
    for (int k = 0; k < 4; k++) {
        int c = k * 256 + tid;
        float o = (v[k] - mu) * inv * g[c] + b[c];
        if (of) {
            of[row * EE + c] = __float2half_rn(o);
        } else {
            bf16 h, l; split_bf16(o, h, l);
            oh[row * EE + c] = h;
            ol[row * EE + c] = l;
        }
    }
}

// ---------------- plain layernorm + split (first LN only) ----------------
__global__ void layernorm_split_k(const float* __restrict__ in, bf16* __restrict__ oh,
                                  bf16* __restrict__ ol,
                                  const float* __restrict__ g, const float* __restrict__ b) {
    __shared__ float sh[256];
    int row = blockIdx.x;
    const float* x = in + (size_t)row * EE;
    float s = 0.f;
    for (int i = threadIdx.x; i < EE; i += 256) s += x[i];
    float mu = blk_sum256(s, sh) * (1.0f / EE);
    float vs = 0.f;
    for (int i = threadIdx.x; i < EE; i += 256) { float d = x[i] - mu; vs += d * d; }
    float var = blk_sum256(vs, sh) * (1.0f / EE);
    float inv = rsqrtf(var + EPSV);
    for (int i = threadIdx.x; i < EE; i += 256) {
        float v = (x[i] - mu) * inv * g[i] + b[i];
        bf16 h, l; split_bf16(v, h, l);
        oh[(size_t)row * EE + i] = h;
        ol[(size_t)row * EE + i] = l;
    }
}

// ---------------- weight transpose + split ----------------
__global__ void wtsplit_k(const float* __restrict__ W, bf16* __restrict__ Th,
                          bf16* __restrict__ Tl, int K, int N, int ldt) {
    __shared__ float t[32][33];
    int n0 = blockIdx.x * 32, k0 = blockIdx.y * 32;
    int tx = threadIdx.x, ty = threadIdx.y;
    #pragma unroll
    for (int r = ty; r < 32; r += 8)
        t[r][tx] = W[(size_t)(k0 + r) * N + n0 + tx];
    __syncthreads();
    #pragma unroll
    for (int r = ty; r < 32; r += 8) {
        float v = t[tx][r];
        bf16 h, l; split_bf16(v, h, l);
        Th[(size_t)(n0 + r) * ldt + k0 + tx] = h;
        Tl[(size_t)(n0 + r) * ldt + k0 + tx] = l;
    }
}

// ---------------- embed split (fp16 hi/lo) ----------------
__global__ void esplit_f16_k(const float* __restrict__ E, __half* __restrict__ Eh,
                             __half* __restrict__ El) {
    size_t i = ((size_t)blockIdx.x * 256 + threadIdx.x) * 4;
    float4 v = *(const float4*)(E + i);
    __half h0,l0,h1,l1,h2,l2,h3,l3;
    split_fp16(v.x,h0,l0); split_fp16(v.y,h1,l1); split_fp16(v.z,h2,l2); split_fp16(v.w,h3,l3);
    *(__half2*)(Eh + i)     = __halves2half2(h0, h1);
    *(__half2*)(Eh + i + 2) = __halves2half2(h2, h3);
    *(__half2*)(El + i)     = __halves2half2(l0, l1);
    *(__half2*)(El + i + 2) = __halves2half2(l2, l3);
}

// ---------------- embedding gather ----------------
__global__ void gather_embed_k(const float* __restrict__ embed, const int* __restrict__ idx) {
    int i = blockIdx.x * blockDim.x + threadIdx.x;
    int t = i >> 10, e = i & 1023;
    g_x[i] = embed[(size_t)idx[t] * EE + e];
}

// ---------------- loss: single-pass online softmax ----------------
__global__ void zero_loss_k() { g_loss = 0.f; }

__global__ void loss_rows_k(const float* __restrict__ logits, const int* __restrict__ targets) {
    __shared__ float shm[256], shs[256];
    int t = blockIdx.x, tid = threadIdx.x;
    const float* row = logits + (size_t)t * VV;
    float m = -1e30f, s = 0.f;
    for (int i = tid; i < VV; i += 256) {
        float v = row[i];
        if (v > m) { s = s * expf(m - v) + 1.f; m = v; }
        else       { s += expf(v - m); }
    }
    shm[tid] = m; shs[tid] = s; __syncthreads();
    #pragma unroll
    for (int st = 128; st > 0; st >>= 1) {
        if (tid < st) {
            float m2 = shm[tid + st], s2 = shs[tid + st];
            float M = fmaxf(shm[tid], m2);
            shs[tid] = shs[tid] * expf(shm[tid] - M) + s2 * expf(m2 - M);
            shm[tid] = M;
        }
        __syncthreads();
    }
    if (tid == 0) {
        float lp = row[targets[t]] - shm[0] - logf(shs[0]);
        atomicAdd(&g_loss, -lp);
    }
}

__global__ void loss_fin_k(float* dst) { *dst = g_loss * (1.0f / (float)TT); }

// ---------------- host orchestration ----------------
extern "C" void kernel_launch(void* const* d_in, const int* in_sizes, int n_in,
                              void* d_out, int out_size) {
    const float* embed = (const float*)d_in[0];
    const float* ln1_g = (const float*)d_in[1];
    const float* ln1_b = (const float*)d_in[2];
    const float* Wq    = (const float*)d_in[3];
    const float* Wk    = (const float*)d_in[4];
    const float* Wv    = (const float*)d_in[5];
    const float* Wo    = (const float*)d_in[6];
    const float* gate  = (const float*)d_in[7];
    const float* ln2_g = (const float*)d_in[8];
    const float* ln2_b = (const float*)d_in[9];
    const float* W1    = (const float*)d_in[10];
    const float* W2    = (const float*)d_in[11];
    const float* lnf_g = (const float*)d_in[12];
    const float* lnf_b = (const float*)d_in[13];
    const int*   idx   = (const int*)d_in[14];
    const int*   tgt   = (const int*)d_in[15];

    float *xp, *logp, *partp;
    bf16 *hh, *hl, *yh, *yl, *ffh, *ffl;
    bf16 *wqkvh, *wqkvl, *woh, *wol, *w1h, *w1l, *w2h, *w2l;
    __half *hf, *efh, *efl;
    cudaGetSymbolAddress((void**)&xp,    g_x);
    cudaGetSymbolAddress((void**)&logp,  g_logits);
    cudaGetSymbolAddress((void**)&partp, g_part);
    cudaGetSymbolAddress((void**)&hh,    g_hh);
    cudaGetSymbolAddress((void**)&hl,    g_hl);
    cudaGetSymbolAddress((void**)&hf,    g_hf);
    cudaGetSymbolAddress((void**)&yh,    g_yh);
    cudaGetSymbolAddress((void**)&yl,    g_yl);
    cudaGetSymbolAddress((void**)&ffh,   g_ffh);
    cudaGetSymbolAddress((void**)&ffl,   g_ffl);
    cudaGetSymbolAddress((void**)&wqkvh, g_wqkv_h);
    cudaGetSymbolAddress((void**)&wqkvl, g_wqkv_l);
    cudaGetSymbolAddress((void**)&woh,   g_wo_h);
    cudaGetSymbolAddress((void**)&wol,   g_wo_l);
    cudaGetSymbolAddress((void**)&w1h,   g_w1_h);
    cudaGetSymbolAddress((void**)&w1l,   g_w1_l);
    cudaGetSymbolAddress((void**)&w2h,   g_w2_h);
    cudaGetSymbolAddress((void**)&w2l,   g_w2_l);
    cudaGetSymbolAddress((void**)&efh,   g_efh);
    cudaGetSymbolAddress((void**)&efl,   g_efl);

    cudaFuncSetAttribute(gemm_mma<0,128,3>, cudaFuncAttributeMaxDynamicSharedMemorySize, GSM128);
    cudaFuncSetAttribute(gemm_mma<2,256,2>, cudaFuncAttributeMaxDynamicSharedMemorySize, GSM256);
    cudaFuncSetAttribute(logits_mma, cudaFuncAttributeMaxDynamicSharedMemorySize, LGSM);
    cudaFuncSetAttribute(scores_mma, cudaFuncAttributeMaxDynamicSharedMemorySize, SCSM);
    cudaFuncSetAttribute(av_mma, cudaFuncAttributeMaxDynamicSharedMemorySize, AVSM);

    // side stream + events (created once; host-side objects only)
    static cudaStream_t s2 = nullptr;
    static cudaEvent_t ev_fork = nullptr, ev_w0 = nullptr, ev_w1 = nullptr, ev_e = nullptr;
    if (!s2) {
        cudaStreamCreateWithFlags(&s2, cudaStreamNonBlocking);
        cudaEventCreateWithFlags(&ev_fork, cudaEventDisableTiming);
        cudaEventCreateWithFlags(&ev_w0, cudaEventDisableTiming);
        cudaEventCreateWithFlags(&ev_w1, cudaEventDisableTiming);
        cudaEventCreateWithFlags(&ev_e, cudaEventDisableTiming);
    }

    const size_t BTV = (size_t)TT * VV;
    float* logits_dst = ((size_t)out_size >= BTV) ? (float*)d_out : logp;
    float* loss_dst = nullptr;
    if ((size_t)out_size > BTV)      loss_dst = (float*)d_out + BTV;
    else if ((size_t)out_size < BTV) loss_dst = (float*)d_out;

    dim3 tb(32, 8);

    // ---- fork: non-immediate preprocessing on s2 ----
    cudaEventRecord(ev_fork, 0);
    cudaStreamWaitEvent(s2, ev_fork, 0);

    wtsplit_k<<<dim3(EE/32, EE/32), tb, 0, s2>>>(Wo, woh, wol, EE, EE, EE);
    wtsplit_k<<<dim3(FF/32, EE/32), tb, 0, s2>>>(W1, w1h, w1l, EE, FF, EE);
    wtsplit_k<<<dim3(EE/32, FF/32), tb, 0, s2>>>(W2, w2h, w2l, FF, EE, FF);
    cudaEventRecord(ev_w0, s2);
    {
        const int l = 1;
        wtsplit_k<<<dim3(EE/32, EE/32), tb, 0, s2>>>(Wq + (size_t)l*EE*EE,
            wqkvh + (size_t)l*QKVN*EE, wqkvl + (size_t)l*QKVN*EE, EE, EE, EE);
        wtsplit_k<<<dim3(KVD/32, EE/32), tb, 0, s2>>>(Wk + (size_t)l*EE*KVD,
            wqkvh + (size_t)l*QKVN*EE + (size_t)EE*EE, wqkvl + (size_t)l*QKVN*EE + (size_t)EE*EE, EE, KVD, EE);
        wtsplit_k<<<dim3(KVD/32, EE/32), tb, 0, s2>>>(Wv + (size_t)l*EE*KVD,
            wqkvh + (size_t)l*QKVN*EE + (size_t)(EE+KVD)*EE, wqkvl + (size_t)l*QKVN*EE + (size_t)(EE+KVD)*EE, EE, KVD, EE);
        wtsplit_k<<<dim3(EE/32, EE/32), tb, 0, s2>>>(Wo + (size_t)l*EE*EE,
            woh + (size_t)l*EE*EE, wol + (size_t)l*EE*EE, EE, EE, EE);
        wtsplit_k<<<dim3(FF/32, EE/32), tb, 0, s2>>>(W1 + (size_t)l*EE*FF,
            w1h + (size_t)l*FF*EE, w1l + (size_t)l*FF*EE, EE, FF, EE);
        wtsplit_k<<<dim3(EE/32, FF/32), tb, 0, s2>>>(W2 + (size_t)l*FF*EE,
            w2h + (size_t)l*EE*FF, w2l + (size_t)l*EE*FF, FF, EE, FF);
    }
    cudaEventRecord(ev_w1, s2);
    esplit_f16_k<<<(int)(((size_t)VV*EE)/1024), 256, 0, s2>>>(embed, efh, efl);
    cudaEventRecord(ev_e, s2);

    // ---- main stream: critical path ----
    wtsplit_k<<<dim3(EE/32, EE/32), tb>>>(Wq, wqkvh, wqkvl, EE, EE, EE);
    wtsplit_k<<<dim3(KVD/32, EE/32), tb>>>(Wk, wqkvh + (size_t)EE*EE, wqkvl + (size_t)EE*EE, EE, KVD, EE);
    wtsplit_k<<<dim3(KVD/32, EE/32), tb>>>(Wv, wqkvh + (size_t)(EE+KVD)*EE, wqkvl + (size_t)(EE+KVD)*EE, EE, KVD, EE);
    gather_embed_k<<<(TT * EE) / 256, 256>>>(embed, idx);
    layernorm_split_k<<<TT, 256>>>(xp, hh, hl, ln1_g, ln1_b);

    for (int it = 0; it < RNUM * LNUM; it++) {
        int l = it % LNUM;
        if (it == 1) cudaStreamWaitEvent(0, ev_w1, 0);
        gemm_mma<0,128,3><<<dim3(TT/128, QKVN/128, 3), 256, GSM128>>>(hh, hl,
            wqkvh + (size_t)l*QKVN*EE, wqkvl + (size_t)l*QKVN*EE,
            partp, nullptr, nullptr, nullptr, QKVN, EE);
        qkv_post_k<<<dim3(TT/64, NH + 2*NKV), 256>>>(partp);
        scores_mma<<<dim3(TT/128, TT/64, NH), 256, SCSM>>>();
        softmax_thresh_k<<<dim3(TT, NH), 256>>>(gate, l);
        av_mma<<<dim3(TT/64, NH), 256, AVSM>>>();
        if (it == 0) cudaStreamWaitEvent(0, ev_w0, 0);
        gemm_mma<0,128,3><<<dim3(TT/128, EE/128, 2), 256, GSM128>>>(yh, yl,
            woh + (size_t)l*EE*EE, wol + (size_t)l*EE*EE,
            partp, nullptr, nullptr, nullptr, EE, EE);
        add_ln_split_k<<<TT, 256>>>(xp, partp, ln2_g + l * EE, ln2_b + l * EE, hh, hl, nullptr);
        gemm_mma<2,256,2><<<dim3(TT/128, FF/256, 1), 256, GSM256>>>(hh, hl,
            w1h + (size_t)l*FF*EE, w1l + (size_t)l*FF*EE,
            nullptr, nullptr, ffh, ffl, FF, EE);
        gemm_mma<0,128,3><<<dim3(TT/128, EE/128, 2), 256, GSM128>>>(ffh, ffl,
            w2h + (size_t)l*EE*FF, w2l + (size_t)l*EE*FF,
            partp, nullptr, nullptr, nullptr, EE, FF);
        if (it == RNUM * LNUM - 1) {
            // final: fused x+= & LNf, fp16 single output for logits GEMM
            add_ln_split_k<<<TT, 256>>>(xp, partp, lnf_g, lnf_b, nullptr, nullptr, hf);
        } else {
            int ln = (l + 1) % LNUM;
            add_ln_split_k<<<TT, 256>>>(xp, partp, ln1_g + ln * EE, ln1_b + ln * EE, hh, hl, nullptr);
        }
    }

    // logits: fp16 2-term GEMM (needs fp16 embed split)
    cudaStreamWaitEvent(0, ev_e, 0);
    logits_mma<<<dim3(TT/128, VV/256), 256, LGSM>>>(hf, efh, efl, logits_dst);

    zero_loss_k<<<1, 1>>>();
    loss_rows_k<<<TT, 256>>>(logits_dst, tgt);
    if (loss_dst) loss_fin_k<<<1, 1>>>(loss_dst);
}

// round 10
// speedup vs baseline: 5.2843x; 1.1485x over previous
#include <cuda_runtime.h>
#include <cuda_bf16.h>
#include <cuda_fp16.h>
#include <math.h>
#include <stdint.h>

// ---------------- problem constants ----------------
#define TT 1024
#define EE 1024
#define VV 32000
#define NH 16
#define NKV 4
#define DHD 64
#define KVD (NKV*DHD)     // 256
#define QKVN 1536
#define LNUM 2
#define RNUM 2
#define FF 4096
#define EPSV 1e-5f

typedef __nv_bfloat16 bf16;

// ---------------- device scratch ----------------
__device__ float g_x[TT*EE];
__device__ bf16  g_hh[TT*EE], g_hl[TT*EE];
__device__ __half g_hf[TT*EE];                         // fp16 LN output (LN2 / final)
__device__ __half g_fff[TT*FF];                        // fp16 gelu(FFN1) output
__device__ float g_att[(size_t)NH*TT*TT];
__device__ bf16  g_atth[(size_t)NH*TT*TT], g_attl[(size_t)NH*TT*TT];
__device__ float g_part[3*TT*QKVN];          // split-K partials (reused)
__device__ bf16  g_qh[NH*TT*DHD],  g_ql[NH*TT*DHD];
__device__ bf16  g_kh[NKV*TT*DHD], g_kl[NKV*TT*DHD];
__device__ bf16  g_vth[NKV*DHD*TT], g_vtl[NKV*DHD*TT];   // transposed V
__device__ bf16  g_yh[TT*EE], g_yl[TT*EE];
__device__ bf16  g_wqkv_h[LNUM*QKVN*EE], g_wqkv_l[LNUM*QKVN*EE];
__device__ bf16  g_wo_h[LNUM*EE*EE],     g_wo_l[LNUM*EE*EE];
__device__ __half g_w1fh[LNUM*FF*EE],    g_w1fl[LNUM*FF*EE];   // fp16 hi/lo W1
__device__ __half g_w2fh[LNUM*EE*FF],    g_w2fl[LNUM*EE*FF];   // fp16 hi/lo W2
__device__ __half g_efh[(size_t)VV*EE],  g_efl[(size_t)VV*EE]; // fp16 hi/lo embed
__device__ float g_logits[(size_t)TT*VV];
__device__ float g_loss;

// ---------------- generic helpers ----------------
__device__ __forceinline__ float blk_sum256(float v, float* sh) {
    int tid = threadIdx.x;
    sh[tid] = v; __syncthreads();
    #pragma unroll
    for (int s = 128; s > 0; s >>= 1) { if (tid < s) sh[tid] += sh[tid + s]; __syncthreads(); }
    float r = sh[0]; __syncthreads();
    return r;
}
__device__ __forceinline__ float blk_max256(float v, float* sh) {
    int tid = threadIdx.x;
    sh[tid] = v; __syncthreads();
    #pragma unroll
    for (int s = 128; s > 0; s >>= 1) { if (tid < s) sh[tid] = fmaxf(sh[tid], sh[tid + s]); __syncthreads(); }
    float r = sh[0]; __syncthreads();
    return r;
}
__device__ __forceinline__ float gelu_exact(float x) {
    return 0.5f * x * (1.0f + erff(x * 0.7071067811865476f));
}
__device__ __forceinline__ void split_bf16(float v, bf16& h, bf16& l) {
    h = __float2bfloat16(v);
    l = __float2bfloat16(v - __bfloat162float(h));
}
__device__ __forceinline__ void split_fp16(float v, __half& h, __half& l) {
    h = __float2half_rn(v);
    l = __float2half_rn(v - __half2float(h));
}

// ---------------- PTX wrappers ----------------
__device__ __forceinline__ void mma_bf16(float* d, const uint32_t* a, const uint32_t* b) {
    asm volatile("mma.sync.aligned.m16n8k16.row.col.f32.bf16.bf16.f32 "
        "{%0,%1,%2,%3}, {%4,%5,%6,%7}, {%8,%9}, {%0,%1,%2,%3};"
        : "+f"(d[0]), "+f"(d[1]), "+f"(d[2]), "+f"(d[3])
        : "r"(a[0]), "r"(a[1]), "r"(a[2]), "r"(a[3]), "r"(b[0]), "r"(b[1]));
}
__device__ __forceinline__ void mma_fp16(float* d, const uint32_t* a, const uint32_t* b) {
    asm volatile("mma.sync.aligned.m16n8k16.row.col.f32.f16.f16.f32 "
        "{%0,%1,%2,%3}, {%4,%5,%6,%7}, {%8,%9}, {%0,%1,%2,%3};"
        : "+f"(d[0]), "+f"(d[1]), "+f"(d[2]), "+f"(d[3])
        : "r"(a[0]), "r"(a[1]), "r"(a[2]), "r"(a[3]), "r"(b[0]), "r"(b[1]));
}
__device__ __forceinline__ void ldsm4(uint32_t* r, uint32_t addr) {
    asm volatile("ldmatrix.sync.aligned.m8n8.x4.shared.b16 {%0,%1,%2,%3}, [%4];"
        : "=r"(r[0]), "=r"(r[1]), "=r"(r[2]), "=r"(r[3]) : "r"(addr));
}
__device__ __forceinline__ void cp16(uint32_t s, const void* g) {
    asm volatile("cp.async.cg.shared.global [%0], [%1], 16;" :: "r"(s), "l"(g));
}
#define CP_COMMIT()  asm volatile("cp.async.commit_group;")
#define CP_WAIT(n)   asm volatile("cp.async.wait_group %0;" :: "n"(n))

// SW128 swizzle: 128B rows, 16B chunks, chunk ^= row&7  (conflict-free ldmatrix)
__device__ __forceinline__ uint32_t sw_off(int row, int chunk) {
    return (uint32_t)(row * 128 + ((chunk ^ (row & 7)) << 4));
}

// ---------------- split-bf16 3-term HMMA GEMM (QKV / Wo) ----------------
template<int MODE, int TN, int NSTG>
__global__ __launch_bounds__(256, 1) void gemm_mma(
    const bf16* __restrict__ Ah, const bf16* __restrict__ Al,
    const bf16* __restrict__ Bh, const bf16* __restrict__ Bl,
    float* C, const float* Rs, bf16* Oh, bf16* Ol,
    int N, int K)
{
    constexpr int TSA = 128 * 128;
    constexpr int TSB = TN * 128;
    constexpr int SB  = 2 * TSA + 2 * TSB;
    constexpr int BCH = TN * 8;
    constexpr int TC  = 2048 + 2 * BCH;
    constexpr int NG  = TN / 64;
    constexpr int NF  = 2 * NG;

    extern __shared__ char dsm[];
    const int tid = threadIdx.x;
    const int lane = tid & 31, warp = tid >> 5;
    const int wm = warp & 1, wn = warp >> 1;
    const int row0 = blockIdx.x * 128, col0 = blockIdx.y * TN;
    const uint32_t sb = (uint32_t)__cvta_generic_to_shared(dsm);

    float acc[4][NF][4];
    #pragma unroll
    for (int i = 0; i < 4; i++)
        #pragma unroll
        for (int j = 0; j < NF; j++)
            #pragma unroll
            for (int r = 0; r < 4; r++) acc[i][j][r] = 0.f;

    auto load_stage = [&](int s) {
        int k0 = s * 64;
        uint32_t base = sb + (s % NSTG) * SB;
        #pragma unroll
        for (int ii = 0; ii < TC / 256; ii++) {
            int i = tid + ii * 256;
            const bf16* src;
            uint32_t toff;
            if (i < 2048) {
                int t = i >> 10, w = i & 1023;
                int r = w >> 3, c = w & 7;
                src = (t ? Al : Ah) + (size_t)(row0 + r) * K + k0 + c * 8;
                toff = t * TSA + sw_off(r, c);
            } else {
                int j = i - 2048;
                int t = j / BCH, w = j & (BCH - 1);
                int r = w >> 3, c = w & 7;
                src = (t ? Bl : Bh) + (size_t)(col0 + r) * K + k0 + c * 8;
                toff = 2 * TSA + t * TSB + sw_off(r, c);
            }
            cp16(base + toff, src);
        }
        CP_COMMIT();
    };

    const int Stot = K >> 6;
    const int SK = gridDim.z;
    const int Sc = (Stot + SK - 1) / SK;
    const int s0 = blockIdx.z * Sc;
    const int s1 = min(Stot, s0 + Sc);

    #pragma unroll
    for (int i = 0; i < NSTG; i++)
        if (s0 + i < s1) load_stage(s0 + i);

    const int lr = lane & 15, lcs = lane >> 4;

    for (int s = s0; s < s1; s++) {
        int ahead = s1 - 1 - s;
        int w = ahead < (NSTG - 1) ? ahead : (NSTG - 1);
        if (w == 2)      { CP_WAIT(2); }
        else if (w == 1) { CP_WAIT(1); }
        else             { CP_WAIT(0); }
        __syncthreads();
        uint32_t ab = sb + (s % NSTG) * SB;
        #pragma unroll
        for (int k16 = 0; k16 < 4; k16++) {
            const int cch = k16 * 2 + lcs;
            uint32_t ah[4][4], al[4][4];
            #pragma unroll
            for (int mf = 0; mf < 4; mf++) {
                int row = wm * 64 + mf * 16 + lr;
                uint32_t off = sw_off(row, cch);
                ldsm4(ah[mf], ab + off);
                ldsm4(al[mf], ab + TSA + off);
            }
            #pragma unroll
            for (int g = 0; g < NG; g++) {
                int row = wn * (TN / 4) + g * 16 + lr;
                uint32_t off = sw_off(row, cch);
                uint32_t rh[4], rl[4];
                ldsm4(rh, ab + 2 * TSA + off);
                ldsm4(rl, ab + 2 * TSA + TSB + off);
                uint32_t b0h[2] = {rh[0], rh[2]}, b1h[2] = {rh[1], rh[3]};
                uint32_t b0l[2] = {rl[0], rl[2]}, b1l[2] = {rl[1], rl[3]};
                #pragma unroll
                for (int mf = 0; mf < 4; mf++) {
                    mma_bf16(acc[mf][g*2], ah[mf], b0h);
                    mma_bf16(acc[mf][g*2], ah[mf], b0l);
                    mma_bf16(acc[mf][g*2], al[mf], b0h);
                    mma_bf16(acc[mf][g*2+1], ah[mf], b1h);
                    mma_bf16(acc[mf][g*2+1], ah[mf], b1l);
                    mma_bf16(acc[mf][g*2+1], al[mf], b1h);
                }
            }
        }
        __syncthreads();
        if (s + NSTG < s1) load_stage(s + NSTG);
    }

    const size_t pstride = (size_t)gridDim.x * 128 * N;
    float* Cp = C + (size_t)blockIdx.z * pstride;
    #pragma unroll
    for (int mf = 0; mf < 4; mf++)
        #pragma unroll
        for (int nf = 0; nf < NF; nf++) {
            int r = row0 + wm * 64 + mf * 16 + (lane >> 2);
            int c = col0 + wn * (TN / 4) + nf * 8 + (lane & 3) * 2;
            float* d = acc[mf][nf];
            *(float2*)(Cp + (size_t)r * N + c)       = make_float2(d[0], d[1]);
            *(float2*)(Cp + (size_t)(r + 8) * N + c) = make_float2(d[2], d[3]);
        }
}

#define GSM128 (3 * (2*128*128 + 2*128*128))   // 196608

// ---------------- fp16 2-term GEMM: C = A * (Bh+Bl)^T ----------------
// A fp16 single, B fp16 hi/lo. 2 MMAs per logical op.
// MODE 0: fp32 store (split-K slab if gridDim.z>1). MODE 2: gelu -> fp16 single Of.
template<int MODE, int TN, int NSTG>
__global__ __launch_bounds__(256, 1) void fp16_mma(
    const __half* __restrict__ A, const __half* __restrict__ Bh,
    const __half* __restrict__ Bl, float* __restrict__ C,
    __half* __restrict__ Of, int N, int K)
{
    constexpr int TSA = 128 * 128;
    constexpr int TSB = TN * 128;
    constexpr int SB  = TSA + 2 * TSB;
    constexpr int BCH = TN * 8;
    constexpr int TC  = 1024 + 2 * BCH;
    constexpr int NG  = TN / 64;
    constexpr int NF  = 2 * NG;

    extern __shared__ char dsm[];
    const int tid = threadIdx.x;
    const int lane = tid & 31, warp = tid >> 5;
    const int wm = warp & 1, wn = warp >> 1;
    const int row0 = blockIdx.x * 128, col0 = blockIdx.y * TN;
    const uint32_t sb = (uint32_t)__cvta_generic_to_shared(dsm);

    float acc[4][NF][4];
    #pragma unroll
    for (int i = 0; i < 4; i++)
        #pragma unroll
        for (int j = 0; j < NF; j++)
            #pragma unroll
            for (int r = 0; r < 4; r++) acc[i][j][r] = 0.f;

    auto load_stage = [&](int s) {
        int k0 = s * 64;
        uint32_t base = sb + (s % NSTG) * SB;
        #pragma unroll
        for (int ii = 0; ii < TC / 256; ii++) {
            int i = tid + ii * 256;
            const __half* src; uint32_t toff;
            if (i < 1024) {
                int r = i >> 3, c = i & 7;
                src = A + (size_t)(row0 + r) * K + k0 + c * 8;
                toff = sw_off(r, c);
            } else {
                int j = i - 1024;
                int t = j / BCH, w = j & (BCH - 1);
                int r = w >> 3, c = w & 7;
                src = (t ? Bl : Bh) + (size_t)(col0 + r) * K + k0 + c * 8;
                toff = TSA + t * TSB + sw_off(r, c);
            }
            cp16(base + toff, src);
        }
        CP_COMMIT();
    };

    const int Stot = K >> 6;
    const int SK = gridDim.z;
    const int Sc = (Stot + SK - 1) / SK;
    const int s0 = blockIdx.z * Sc;
    const int s1 = min(Stot, s0 + Sc);

    #pragma unroll
    for (int i = 0; i < NSTG; i++)
        if (s0 + i < s1) load_stage(s0 + i);

    const int lr = lane & 15, lcs = lane >> 4;

    for (int s = s0; s < s1; s++) {
        int ahead = s1 - 1 - s;
        int w = ahead < (NSTG - 1) ? ahead : (NSTG - 1);
        if (w == 2)      { CP_WAIT(2); }
        else if (w == 1) { CP_WAIT(1); }
        else             { CP_WAIT(0); }
        __syncthreads();
        uint32_t ab = sb + (s % NSTG) * SB;
        #pragma unroll
        for (int k16 = 0; k16 < 4; k16++) {
            const int cch = k16 * 2 + lcs;
            uint32_t ah[4][4];
            #pragma unroll
            for (int mf = 0; mf < 4; mf++)
                ldsm4(ah[mf], ab + sw_off(wm * 64 + mf * 16 + lr, cch));
            #pragma unroll
            for (int g = 0; g < NG; g++) {
                uint32_t off = sw_off(wn * (TN / 4) + g * 16 + lr, cch);
                uint32_t rh[4], rl[4];
                ldsm4(rh, ab + TSA + off);
                ldsm4(rl, ab + TSA + TSB + off);
                uint32_t b0h[2] = {rh[0], rh[2]}, b1h[2] = {rh[1], rh[3]};
                uint32_t b0l[2] = {rl[0], rl[2]}, b1l[2] = {rl[1], rl[3]};
                #pragma unroll
                for (int mf = 0; mf < 4; mf++) {
                    mma_fp16(acc[mf][g*2], ah[mf], b0h);
                    mma_fp16(acc[mf][g*2], ah[mf], b0l);
                    mma_fp16(acc[mf][g*2+1], ah[mf], b1h);
                    mma_fp16(acc[mf][g*2+1], ah[mf], b1l);
                }
            }
        }
        __syncthreads();
        if (s + NSTG < s1) load_stage(s + NSTG);
    }

    const size_t pstride = (size_t)gridDim.x * 128 * N;
    float* Cp = C + (size_t)blockIdx.z * pstride;
    #pragma unroll
    for (int mf = 0; mf < 4; mf++)
        #pragma unroll
        for (int nf = 0; nf < NF; nf++) {
            int r = row0 + wm * 64 + mf * 16 + (lane >> 2);
            int c = col0 + wn * (TN / 4) + nf * 8 + (lane & 3) * 2;
            float* d = acc[mf][nf];
            if (MODE == 0) {
                *(float2*)(Cp + (size_t)r * N + c)       = make_float2(d[0], d[1]);
                *(float2*)(Cp + (size_t)(r + 8) * N + c) = make_float2(d[2], d[3]);
            } else {
                __half o0 = __float2half_rn(gelu_exact(d[0]));
                __half o1 = __float2half_rn(gelu_exact(d[1]));
                __half o2 = __float2half_rn(gelu_exact(d[2]));
                __half o3 = __float2half_rn(gelu_exact(d[3]));
                *(__half2*)(Of + (size_t)r * N + c)       = __halves2half2(o0, o1);
                *(__half2*)(Of + (size_t)(r + 8) * N + c) = __halves2half2(o2, o3);
            }
        }
}

#define F16SM128 (3 * (128*128 + 2*128*128))   // 147456
#define F16SM256 (2 * (128*128 + 2*256*128))   // 163840

// ---------------- fused QKV reduce + RoPE/transpose + split ----------------
__global__ void qkv_post_k(const float* __restrict__ part) {
    __shared__ float tile[64][65];
    int ttile = blockIdx.x, head = blockIdx.y;
    int tid = threadIdx.x;
    int cb;
    if (head < NH)            cb = head * DHD;
    else if (head < NH + NKV) cb = EE + (head - NH) * DHD;
    else                      cb = EE + KVD + (head - NH - NKV) * DHD;
    const int n = TT * QKVN;
    #pragma unroll
    for (int it = 0; it < 16; it++) {
        int i = tid + it * 256;
        int r = i >> 6, c = i & 63;
        size_t idx = (size_t)(ttile * 64 + r) * QKVN + cb + c;
        tile[r][c] = part[idx] + part[idx + n] + part[idx + 2 * (size_t)n];
    }
    __syncthreads();
    if (head < NH + NKV) {
        bf16 *dh, *dl; size_t off;
        if (head < NH) { dh = g_qh; dl = g_ql; off = (size_t)head * TT * DHD; }
        else           { dh = g_kh; dl = g_kl; off = (size_t)(head - NH) * TT * DHD; }
        #pragma unroll
        for (int it = 0; it < 16; it++) {
            int i = tid + it * 256;
            int r = i >> 6, d = i & 63;
            int t = ttile * 64 + r;
            float v;
            if (d < 32) {
                int j = d & 15;
                float theta = powf(10000.0f, -(float)j / 16.0f);
                float ang = (float)t * theta;
                float cs = cosf(ang), sn = sinf(ang);
                if (d < 16) v = tile[r][d] * cs - tile[r][d + 16] * sn;
                else        v = tile[r][d] * cs + tile[r][d - 16] * sn;
            } else v = tile[r][d];
            bf16 h, l; split_bf16(v, h, l);
            size_t o = off + (size_t)t * DHD + d;
            dh[o] = h; dl[o] = l;
        }
    } else {
        int kh = head - NH - NKV;
        #pragma unroll
        for (int it = 0; it < 16; it++) {
            int i = tid + it * 256;
            int d = i >> 6, tc = i & 63;
            float v = tile[tc][d];
            bf16 h, l; split_bf16(v, h, l);
            size_t o = ((size_t)kh * DHD + d) * TT + ttile * 64 + tc;
            g_vth[o] = h; g_vtl[o] = l;
        }
    }
}

// ---------------- HMMA attention scores: 64(t) x 128(s), K=64 ----------------
#define SCSM 49152
__global__ __launch_bounds__(256) void scores_mma() {
    int st = blockIdx.x, tt = blockIdx.y, h = blockIdx.z;
    if (2 * st > tt) return;
    int khid = h >> 2;
    extern __shared__ char dsm[];
    const uint32_t sb = (uint32_t)__cvta_generic_to_shared(dsm);
    const int tid = threadIdx.x;
    const int lane = tid & 31, warp = tid >> 5;

    #pragma unroll
    for (int it = 0; it < 12; it++) {
        int i = tid + it * 256;
        const bf16* src; uint32_t dst;
        if (i < 1024) {
            int sub = i >> 9, w = i & 511, r = w >> 3, c = w & 7;
            src = (sub ? g_ql : g_qh) + ((size_t)h * TT + tt * 64 + r) * DHD + c * 8;
            dst = sub * 8192 + sw_off(r, c);
        } else {
            int j = i - 1024;
            int sub = j >> 10, w = j & 1023, r = w >> 3, c = w & 7;
            src = (sub ? g_kl : g_kh) + ((size_t)khid * TT + st * 128 + r) * DHD + c * 8;
            dst = 16384 + sub * 16384 + sw_off(r, c);
        }
        cp16(sb + dst, src);
    }
    CP_COMMIT(); CP_WAIT(0);
    __syncthreads();

    const int wm = warp & 1, wn = warp >> 1;
    const int lr = lane & 15, lcs = lane >> 4;
    float acc[2][4][4];
    #pragma unroll
    for (int a = 0; a < 2; a++)
        #pragma unroll
        for (int b = 0; b < 4; b++)
            #pragma unroll
            for (int c = 0; c < 4; c++) acc[a][b][c] = 0.f;

    #pragma unroll
    for (int k16 = 0; k16 < 4; k16++) {
        const int cch = k16 * 2 + lcs;
        uint32_t ah[2][4], al[2][4];
        #pragma unroll
        for (int mf = 0; mf < 2; mf++) {
            int row = wm * 32 + mf * 16 + lr;
            uint32_t off = sw_off(row, cch);
            ldsm4(ah[mf], sb + off);
            ldsm4(al[mf], sb + 8192 + off);
        }
        #pragma unroll
        for (int g = 0; g < 2; g++) {
            int row = wn * 32 + g * 16 + lr;
            uint32_t off = sw_off(row, cch);
            uint32_t rh[4], rl[4];
            ldsm4(rh, sb + 16384 + off);
            ldsm4(rl, sb + 32768 + off);
            uint32_t b0h[2] = {rh[0], rh[2]}, b1h[2] = {rh[1], rh[3]};
            uint32_t b0l[2] = {rl[0], rl[2]}, b1l[2] = {rl[1], rl[3]};
            #pragma unroll
            for (int mf = 0; mf < 2; mf++) {
                mma_bf16(acc[mf][g*2], ah[mf], b0h);
                mma_bf16(acc[mf][g*2], ah[mf], b0l);
                mma_bf16(acc[mf][g*2], al[mf], b0h);
                mma_bf16(acc[mf][g*2+1], ah[mf], b1h);
                mma_bf16(acc[mf][g*2+1], ah[mf], b1l);
                mma_bf16(acc[mf][g*2+1], al[mf], b1h);
            }
        }
    }
    float* o = g_att + (size_t)h * TT * TT;
    #pragma unroll
    for (int mf = 0; mf < 2; mf++)
        #pragma unroll
        for (int nf = 0; nf < 4; nf++) {
            int r = tt * 64 + wm * 32 + mf * 16 + (lane >> 2);
            int c = st * 128 + wn * 32 + nf * 8 + (lane & 3) * 2;
            float* d = acc[mf][nf];
            *(float2*)(o + (size_t)r * TT + c)       = make_float2(d[0]*0.125f, d[1]*0.125f);
            *(float2*)(o + (size_t)(r + 8) * TT + c) = make_float2(d[2]*0.125f, d[3]*0.125f);
        }
}

// ---------------- single-pass softmax + gate, writes split-bf16 att ----------------
__global__ void softmax_thresh_k(const float* __restrict__ gate_all, int l) {
    __shared__ float sh[256];
    int t = blockIdx.x, h = blockIdx.y;
    int tid = threadIdx.x;
    const float* p = g_att + (size_t)h * TT * TT + (size_t)t * TT;
    float thr = 1.0f / (1.0f + expf(-gate_all[l * NH + h]));
    float x[4];
    #pragma unroll
    for (int k = 0; k < 4; k++) {
        int i = k * 256 + tid;
        x[k] = (i <= t) ? p[i] : -1e30f;
    }
    float m = fmaxf(fmaxf(x[0], x[1]), fmaxf(x[2], x[3]));
    m = blk_max256(m, sh);
    float e[4], s = 0.f;
    #pragma unroll
    for (int k = 0; k < 4; k++) {
        int i = k * 256 + tid;
        e[k] = (i <= t) ? expf(x[k] - m) : 0.f;
        s += e[k];
    }
    s = blk_sum256(s, sh);
    float inv = 1.0f / s;
    int kend = ((t >> 6) + 1) << 6;
    size_t base = (size_t)h * TT * TT + (size_t)t * TT;
    #pragma unroll
    for (int k = 0; k < 4; k++) {
        int i = k * 256 + tid;
        if (i < kend) {
            float pv = e[k] * inv;
            pv = (pv >= thr) ? pv : 0.f;
            bf16 hh2, ll2; split_bf16(pv, hh2, ll2);
            g_atth[base + i] = hh2;
            g_attl[base + i] = ll2;
        }
    }
}

// ---------------- HMMA AV: 64(t) x 64(d), K-loop over s (largest-K first) ----------------
#define AVSM 65536
__global__ __launch_bounds__(256) void av_mma() {
    int tt = gridDim.x - 1 - blockIdx.x;    // largest-K blocks launch first
    int h = blockIdx.y;
    int khid = h >> 2;
    int St = tt + 1;
    extern __shared__ char dsm[];
    const uint32_t sb = (uint32_t)__cvta_generic_to_shared(dsm);
    const int tid = threadIdx.x;
    const int lane = tid & 31, warp = tid >> 5;
    const int wm = warp & 1, wn = warp >> 1;
    const int lr = lane & 15, lcs = lane >> 4;

    auto load = [&](int s) {
        uint32_t base = sb + (s & 1) * 32768;
        #pragma unroll
        for (int it = 0; it < 8; it++) {
            int i = tid + it * 256;
            const bf16* src; uint32_t dst;
            if (i < 1024) {
                int sub = i >> 9, w = i & 511, r = w >> 3, c = w & 7;
                src = (sub ? g_attl : g_atth) + ((size_t)h * TT + tt * 64 + r) * TT + s * 64 + c * 8;
                dst = base + sub * 8192 + sw_off(r, c);
            } else {
                int j = i - 1024;
                int sub = j >> 9, w = j & 511, r = w >> 3, c = w & 7;
                src = (sub ? g_vtl : g_vth) + ((size_t)khid * DHD + r) * TT + s * 64 + c * 8;
                dst = base + 16384 + sub * 8192 + sw_off(r, c);
            }
            cp16(dst, src);
        }
        CP_COMMIT();
    };

    load(0);
    if (St > 1) load(1);

    float acc[2][2][4];
    #pragma unroll
    for (int a = 0; a < 2; a++)
        #pragma unroll
        for (int b = 0; b < 2; b++)
            #pragma unroll
            for (int c = 0; c < 4; c++) acc[a][b][c] = 0.f;

    for (int s = 0; s < St; s++) {
        if (s + 1 < St) { CP_WAIT(1); } else { CP_WAIT(0); }
        __syncthreads();
        uint32_t base = sb + (s & 1) * 32768;
        #pragma unroll
        for (int k16 = 0; k16 < 4; k16++) {
            const int cch = k16 * 2 + lcs;
            uint32_t ah[2][4], al[2][4];
            #pragma unroll
            for (int mf = 0; mf < 2; mf++) {
                int row = wm * 32 + mf * 16 + lr;
                uint32_t off = sw_off(row, cch);
                ldsm4(ah[mf], base + off);
                ldsm4(al[mf], base + 8192 + off);
            }
            int row = wn * 16 + lr;
            uint32_t off = sw_off(row, cch);
            uint32_t rh[4], rl[4];
            ldsm4(rh, base + 16384 + off);
            ldsm4(rl, base + 24576 + off);
            uint32_t b0h[2] = {rh[0], rh[2]}, b1h[2] = {rh[1], rh[3]};
            uint32_t b0l[2] = {rl[0], rl[2]}, b1l[2] = {rl[1], rl[3]};
            #pragma unroll
            for (int mf = 0; mf < 2; mf++) {
                mma_bf16(acc[mf][0], ah[mf], b0h);
                mma_bf16(acc[mf][0], ah[mf], b0l);
                mma_bf16(acc[mf][0], al[mf], b0h);
                mma_bf16(acc[mf][1], ah[mf], b1h);
                mma_bf16(acc[mf][1], ah[mf], b1l);
                mma_bf16(acc[mf][1], al[mf], b1h);
            }
        }
        __syncthreads();
        if (s + 2 < St) load(s + 2);
    }

    #pragma unroll
    for (int mf = 0; mf < 2; mf++)
        #pragma unroll
        for (int nf = 0; nf < 2; nf++) {
            int r = tt * 64 + wm * 32 + mf * 16 + (lane >> 2);
            int c = h * DHD + wn * 16 + nf * 8 + (lane & 3) * 2;
            float* d = acc[mf][nf];
            bf16 h0, l0, h1, l1, h2, l2, h3, l3;
            split_bf16(d[0], h0, l0); split_bf16(d[1], h1, l1);
            split_bf16(d[2], h2, l2); split_bf16(d[3], h3, l3);
            *(__nv_bfloat162*)(g_yh + (size_t)r * EE + c)       = __halves2bfloat162(h0, h1);
            *(__nv_bfloat162*)(g_yl + (size_t)r * EE + c)       = __halves2bfloat162(l0, l1);
            *(__nv_bfloat162*)(g_yh + (size_t)(r + 8) * EE + c) = __halves2bfloat162(h2, h3);
            *(__nv_bfloat162*)(g_yl + (size_t)(r + 8) * EE + c) = __halves2bfloat162(l2, l3);
        }
}

// ---------------- fused residual-add + layernorm + split (bf16 pair or fp16) ----------------
__global__ void add_ln_split_k(float* __restrict__ x, const float* __restrict__ p,
                               const float* __restrict__ g, const float* __restrict__ b,
                               bf16* __restrict__ oh, bf16* __restrict__ ol,
                               __half* __restrict__ of) {
    __shared__ float sh[256];
    int row = blockIdx.x, tid = threadIdx.x;
    const int n = TT * EE;
    float v[4];
    #pragma unroll
    for (int k = 0; k < 4; k++) {
        int i = row * EE + k * 256 + tid;
        v[k] = x[i] + p[i] + p[i + n];
        x[i] = v[k];
    }
    float mu = blk_sum256(v[0] + v[1] + v[2] + v[3], sh) * (1.0f / EE);
    float vs = 0.f;
    #pragma unroll
    for (int k = 0; k < 4; k++) { float d = v[k] - mu; vs += d * d; }
    float var = blk_sum256(vs, sh) * (1.0f / EE);
    float inv = rsqrtf(var + EPSV);
    #pragma unroll
    for (int k = 0; k < 4; k++) {
        int c = k * 256 + tid;
        float o = (v[k] - mu) * inv * g[c] + b[c];
        if (of) {
            of[row * EE + c] = __float2half_rn(o);
        } else {
            bf16 h, l; split_bf16(o, h, l);
            oh[row * EE + c] = h;
            ol[row * EE + c] = l;
        }
    }
}

// ---------------- plain layernorm + split (first LN only) ----------------
__global__ void layernorm_split_k(const float* __restrict__ in, bf16* __restrict__ oh,
                                  bf16* __restrict__ ol,
                                  const float* __restrict__ g, const float* __restrict__ b) {
    __shared__ float sh[256];
    int row = blockIdx.x;
    const float* x = in + (size_t)row * EE;
    float s = 0.f;
    for (int i = threadIdx.x; i < EE; i += 256) s += x[i];
    float mu = blk_sum256(s, sh) * (1.0f / EE);
    float vs = 0.f;
    for (int i = threadIdx.x; i < EE; i += 256) { float d = x[i] - mu; vs += d * d; }
    float var = blk_sum256(vs, sh) * (1.0f / EE);
    float inv = rsqrtf(var + EPSV);
    for (int i = threadIdx.x; i < EE; i += 256) {
        float v = (x[i] - mu) * inv * g[i] + b[i];
        bf16 h, l; split_bf16(v, h, l);
        oh[(size_t)row * EE + i] = h;
        ol[(size_t)row * EE + i] = l;
    }
}

// ---------------- weight transpose + split (bf16) ----------------
__global__ void wtsplit_k(const float* __restrict__ W, bf16* __restrict__ Th,
                          bf16* __restrict__ Tl, int K, int N, int ldt) {
    __shared__ float t[32][33];
    int n0 = blockIdx.x * 32, k0 = blockIdx.y * 32;
    int tx = threadIdx.x, ty = threadIdx.y;
    #pragma unroll
    for (int r = ty; r < 32; r += 8)
        t[r][tx] = W[(size_t)(k0 + r) * N + n0 + tx];
    __syncthreads();
    #pragma unroll
    for (int r = ty; r < 32; r += 8) {
        float v = t[tx][r];
        bf16 h, l; split_bf16(v, h, l);
        Th[(size_t)(n0 + r) * ldt + k0 + tx] = h;
        Tl[(size_t)(n0 + r) * ldt + k0 + tx] = l;
    }
}

// ---------------- weight transpose + split (fp16) ----------------
__global__ void wtsplit_f16_k(const float* __restrict__ W, __half* __restrict__ Th,
                              __half* __restrict__ Tl, int K, int N, int ldt) {
    __shared__ float t[32][33];
    int n0 = blockIdx.x * 32, k0 = blockIdx.y * 32;
    int tx = threadIdx.x, ty = threadIdx.y;
    #pragma unroll
    for (int r = ty; r < 32; r += 8)
        t[r][tx] = W[(size_t)(k0 + r) * N + n0 + tx];
    __syncthreads();
    #pragma unroll
    for (int r = ty; r < 32; r += 8) {
        float v = t[tx][r];
        __half h, l; split_fp16(v, h, l);
        Th[(size_t)(n0 + r) * ldt + k0 + tx] = h;
        Tl[(size_t)(n0 + r) * ldt + k0 + tx] = l;
    }
}

// ---------------- embed split (fp16 hi/lo) ----------------
__global__ void esplit_f16_k(const float* __restrict__ E, __half* __restrict__ Eh,
                             __half* __restrict__ El) {
    size_t i = ((size_t)blockIdx.x * 256 + threadIdx.x) * 4;
    float4 v = *(const float4*)(E + i);
    __half h0,l0,h1,l1,h2,l2,h3,l3;
    split_fp16(v.x,h0,l0); split_fp16(v.y,h1,l1); split_fp16(v.z,h2,l2); split_fp16(v.w,h3,l3);
    *(__half2*)(Eh + i)     = __halves2half2(h0, h1);
    *(__half2*)(Eh + i + 2) = __halves2half2(h2, h3);
    *(__half2*)(El + i)     = __halves2half2(l0, l1);
    *(__half2*)(El + i + 2) = __halves2half2(l2, l3);
}

// ---------------- embedding gather ----------------
__global__ void gather_embed_k(const float* __restrict__ embed, const int* __restrict__ idx) {
    int i = blockIdx.x * blockDim.x + threadIdx.x;
    int t = i >> 10, e = i & 1023;
    g_x[i] = embed[(size_t)idx[t] * EE + e];
}

// ---------------- loss: single-pass online softmax ----------------
__global__ void zero_loss_k() { g_loss = 0.f; }

__global__ void loss_rows_k(const float* __restrict__ logits, const int* __restrict__ targets) {
    __shared__ float shm[256], shs[256];
    int t = blockIdx.x, tid = threadIdx.x;
    const float* row = logits + (size_t)t * VV;
    float m = -1e30f, s = 0.f;
    for (int i = tid; i < VV; i += 256) {
        float v = row[i];
        if (v > m) { s = s * expf(m - v) + 1.f; m = v; }
        else       { s += expf(v - m); }
    }
    shm[tid] = m; shs[tid] = s; __syncthreads();
    #pragma unroll
    for (int st = 128; st > 0; st >>= 1) {
        if (tid < st) {
            float m2 = shm[tid + st], s2 = shs[tid + st];
            float M = fmaxf(shm[tid], m2);
            shs[tid] = shs[tid] * expf(shm[tid] - M) + s2 * expf(m2 - M);
            shm[tid] = M;
        }
        __syncthreads();
    }
    if (tid == 0) {
        float lp = row[targets[t]] - shm[0] - logf(shs[0]);
        atomicAdd(&g_loss, -lp);
    }
}

__global__ void loss_fin_k(float* dst) { *dst = g_loss * (1.0f / (float)TT); }

// ---------------- host orchestration ----------------
extern "C" void kernel_launch(void* const* d_in, const int* in_sizes, int n_in,
                              void* d_out, int out_size) {
    const float* embed = (const float*)d_in[0];
    const float* ln1_g = (const float*)d_in[1];
    const float* ln1_b = (const float*)d_in[2];
    const float* Wq    = (const float*)d_in[3];
    const float* Wk    = (const float*)d_in[4];
    const float* Wv    = (const float*)d_in[5];
    const float* Wo    = (const float*)d_in[6];
    const float* gate  = (const float*)d_in[7];
    const float* ln2_g = (const float*)d_in[8];
    const float* ln2_b = (const float*)d_in[9];
    const float* W1    = (const float*)d_in[10];
    const float* W2    = (const float*)d_in[11];
    const float* lnf_g = (const float*)d_in[12];
    const float* lnf_b = (const float*)d_in[13];
    const int*   idx   = (const int*)d_in[14];
    const int*   tgt   = (const int*)d_in[15];

    float *xp, *logp, *partp;
    bf16 *hh, *hl, *yh, *yl;
    bf16 *wqkvh, *wqkvl, *woh, *wol;
    __half *hf, *fff, *w1fh, *w1fl, *w2fh, *w2fl, *efh, *efl;
    cudaGetSymbolAddress((void**)&xp,    g_x);
    cudaGetSymbolAddress((void**)&logp,  g_logits);
    cudaGetSymbolAddress((void**)&partp, g_part);
    cudaGetSymbolAddress((void**)&hh,    g_hh);
    cudaGetSymbolAddress((void**)&hl,    g_hl);
    cudaGetSymbolAddress((void**)&hf,    g_hf);
    cudaGetSymbolAddress((void**)&fff,   g_fff);
    cudaGetSymbolAddress((void**)&yh,    g_yh);
    cudaGetSymbolAddress((void**)&yl,    g_yl);
    cudaGetSymbolAddress((void**)&wqkvh, g_wqkv_h);
    cudaGetSymbolAddress((void**)&wqkvl, g_wqkv_l);
    cudaGetSymbolAddress((void**)&woh,   g_wo_h);
    cudaGetSymbolAddress((void**)&wol,   g_wo_l);
    cudaGetSymbolAddress((void**)&w1fh,  g_w1fh);
    cudaGetSymbolAddress((void**)&w1fl,  g_w1fl);
    cudaGetSymbolAddress((void**)&w2fh,  g_w2fh);
    cudaGetSymbolAddress((void**)&w2fl,  g_w2fl);
    cudaGetSymbolAddress((void**)&efh,   g_efh);
    cudaGetSymbolAddress((void**)&efl,   g_efl);

    cudaFuncSetAttribute(gemm_mma<0,128,3>, cudaFuncAttributeMaxDynamicSharedMemorySize, GSM128);
    cudaFuncSetAttribute(fp16_mma<0,128,3>, cudaFuncAttributeMaxDynamicSharedMemorySize, F16SM128);
    cudaFuncSetAttribute(fp16_mma<0,256,2>, cudaFuncAttributeMaxDynamicSharedMemorySize, F16SM256);
    cudaFuncSetAttribute(fp16_mma<2,256,2>, cudaFuncAttributeMaxDynamicSharedMemorySize, F16SM256);
    cudaFuncSetAttribute(scores_mma, cudaFuncAttributeMaxDynamicSharedMemorySize, SCSM);
    cudaFuncSetAttribute(av_mma, cudaFuncAttributeMaxDynamicSharedMemorySize, AVSM);

    // side stream + events (created once; host-side objects only)
    static cudaStream_t s2 = nullptr;
    static cudaEvent_t ev_fork = nullptr, ev_w0 = nullptr, ev_w1 = nullptr, ev_e = nullptr;
    if (!s2) {
        cudaStreamCreateWithFlags(&s2, cudaStreamNonBlocking);
        cudaEventCreateWithFlags(&ev_fork, cudaEventDisableTiming);
        cudaEventCreateWithFlags(&ev_w0, cudaEventDisableTiming);
        cudaEventCreateWithFlags(&ev_w1, cudaEventDisableTiming);
        cudaEventCreateWithFlags(&ev_e, cudaEventDisableTiming);
    }

    const size_t BTV = (size_t)TT * VV;
    float* logits_dst = ((size_t)out_size >= BTV) ? (float*)d_out : logp;
    float* loss_dst = nullptr;
    if ((size_t)out_size > BTV)      loss_dst = (float*)d_out + BTV;
    else if ((size_t)out_size < BTV) loss_dst = (float*)d_out;

    dim3 tb(32, 8);

    // ---- fork: non-immediate preprocessing on s2 ----
    cudaEventRecord(ev_fork, 0);
    cudaStreamWaitEvent(s2, ev_fork, 0);

    wtsplit_k<<<dim3(EE/32, EE/32), tb, 0, s2>>>(Wo, woh, wol, EE, EE, EE);
    wtsplit_f16_k<<<dim3(FF/32, EE/32), tb, 0, s2>>>(W1, w1fh, w1fl, EE, FF, EE);
    wtsplit_f16_k<<<dim3(EE/32, FF/32), tb, 0, s2>>>(W2, w2fh, w2fl, FF, EE, FF);
    cudaEventRecord(ev_w0, s2);
    {
        const int l = 1;
        wtsplit_k<<<dim3(EE/32, EE/32), tb, 0, s2>>>(Wq + (size_t)l*EE*EE,
            wqkvh + (size_t)l*QKVN*EE, wqkvl + (size_t)l*QKVN*EE, EE, EE, EE);
        wtsplit_k<<<dim3(KVD/32, EE/32), tb, 0, s2>>>(Wk + (size_t)l*EE*KVD,
            wqkvh + (size_t)l*QKVN*EE + (size_t)EE*EE, wqkvl + (size_t)l*QKVN*EE + (size_t)EE*EE, EE, KVD, EE);
        wtsplit_k<<<dim3(KVD/32, EE/32), tb, 0, s2>>>(Wv + (size_t)l*EE*KVD,
            wqkvh + (size_t)l*QKVN*EE + (size_t)(EE+KVD)*EE, wqkvl + (size_t)l*QKVN*EE + (size_t)(EE+KVD)*EE, EE, KVD, EE);
        wtsplit_k<<<dim3(EE/32, EE/32), tb, 0, s2>>>(Wo + (size_t)l*EE*EE,
            woh + (size_t)l*EE*EE, wol + (size_t)l*EE*EE, EE, EE, EE);
        wtsplit_f16_k<<<dim3(FF/32, EE/32), tb, 0, s2>>>(W1 + (size_t)l*EE*FF,
            w1fh + (size_t)l*FF*EE, w1fl + (size_t)l*FF*EE, EE, FF, EE);
        wtsplit_f16_k<<<dim3(EE/32, FF/32), tb, 0, s2>>>(W2 + (size_t)l*FF*EE,
            w2fh + (size_t)l*EE*FF, w2fl + (size_t)l*EE*FF, FF, EE, FF);
    }
    cudaEventRecord(ev_w1, s2);
    esplit_f16_k<<<(int)(((size_t)VV*EE)/1024), 256, 0, s2>>>(embed, efh, efl);
    cudaEventRecord(ev_e, s2);

    // ---- main stream: critical path ----
    wtsplit_k<<<dim3(EE/32, EE/32), tb>>>(Wq, wqkvh, wqkvl, EE, EE, EE);
    wtsplit_k<<<dim3(KVD/32, EE/32), tb>>>(Wk, wqkvh + (size_t)EE*EE, wqkvl + (size_t)EE*EE, EE, KVD, EE);
    wtsplit_k<<<dim3(KVD/32, EE/32), tb>>>(Wv, wqkvh + (size_t)(EE+KVD)*EE, wqkvl + (size_t)(EE+KVD)*EE, EE, KVD, EE);
    gather_embed_k<<<(TT * EE) / 256, 256>>>(embed, idx);
    layernorm_split_k<<<TT, 256>>>(xp, hh, hl, ln1_g, ln1_b);

    for (int it = 0; it < RNUM * LNUM; it++) {
        int l = it % LNUM;
        if (it == 1) cudaStreamWaitEvent(0, ev_w1, 0);
        // QKV: 3-term bf16, split-K=3
        gemm_mma<0,128,3><<<dim3(TT/128, QKVN/128, 3), 256, GSM128>>>(hh, hl,
            wqkvh + (size_t)l*QKVN*EE, wqkvl + (size_t)l*QKVN*EE,
            partp, nullptr, nullptr, nullptr, QKVN, EE);
        qkv_post_k<<<dim3(TT/64, NH + 2*NKV), 256>>>(partp);
        scores_mma<<<dim3(TT/128, TT/64, NH), 256, SCSM>>>();
        softmax_thresh_k<<<dim3(TT, NH), 256>>>(gate, l);
        av_mma<<<dim3(TT/64, NH), 256, AVSM>>>();
        if (it == 0) cudaStreamWaitEvent(0, ev_w0, 0);
        // Wo: 3-term bf16, split-K=2; fused x+= & LN2 (fp16 single out for FFN1)
        gemm_mma<0,128,3><<<dim3(TT/128, EE/128, 2), 256, GSM128>>>(yh, yl,
            woh + (size_t)l*EE*EE, wol + (size_t)l*EE*EE,
            partp, nullptr, nullptr, nullptr, EE, EE);
        add_ln_split_k<<<TT, 256>>>(xp, partp, ln2_g + l * EE, ln2_b + l * EE,
                                    nullptr, nullptr, hf);
        // FFN1: fp16 2-term, gelu -> fp16 single
        fp16_mma<2,256,2><<<dim3(TT/128, FF/256, 1), 256, F16SM256>>>(hf,
            w1fh + (size_t)l*FF*EE, w1fl + (size_t)l*FF*EE,
            nullptr, fff, FF, EE);
        // FFN2: fp16 2-term, split-K=2 -> partials
        fp16_mma<0,128,3><<<dim3(TT/128, EE/128, 2), 256, F16SM128>>>(fff,
            w2fh + (size_t)l*EE*FF, w2fl + (size_t)l*EE*FF,
            partp, nullptr, EE, FF);
        if (it == RNUM * LNUM - 1) {
            add_ln_split_k<<<TT, 256>>>(xp, partp, lnf_g, lnf_b, nullptr, nullptr, hf);
        } else {
            int ln = (l + 1) % LNUM;
            add_ln_split_k<<<TT, 256>>>(xp, partp, ln1_g + ln * EE, ln1_b + ln * EE,
                                        hh, hl, nullptr);
        }
    }

    // logits: fp16 2-term GEMM
    cudaStreamWaitEvent(0, ev_e, 0);
    fp16_mma<0,256,2><<<dim3(TT/128, VV/256, 1), 256, F16SM256>>>(hf, efh, efl,
        logits_dst, nullptr, VV, EE);

    zero_loss_k<<<1, 1>>>();
    loss_rows_k<<<TT, 256>>>(logits_dst, tgt);
    if (loss_dst) loss_fin_k<<<1, 1>>>(loss_dst);
}